// round 5
// baseline (speedup 1.0000x reference)
#include <cuda_runtime.h>
#include <math.h>

#define NNODES 50000
#define NEDGES 800000
#define HID    128
#define FE     16

typedef unsigned long long u64;
typedef unsigned int u32;

// ---------------- scratch ----------------
__device__ float g_Ha[NNODES * HID];    // h @ eW1[0:128,:]
__device__ float g_Hb[NNODES * HID];    // h @ eW1[128:256,:]
__device__ float g_vec1[NNODES * 3];
__device__ float g_vec2[NNODES * 3];
__device__ int   g_rows[NEDGES];
__device__ int   g_cols[NEDGES];
__device__ int   g_is64;

// ---------------- f32x2 helpers ----------------
__device__ __forceinline__ u64 pack2(float lo, float hi) {
    u64 r; asm("mov.b64 %0, {%1, %2};" : "=l"(r) : "f"(lo), "f"(hi)); return r;
}
__device__ __forceinline__ float2 unpack2(u64 v) {
    float2 f; asm("mov.b64 {%0, %1}, %2;" : "=f"(f.x), "=f"(f.y) : "l"(v)); return f;
}
__device__ __forceinline__ void fma2(u64& c, u64 a, u64 b) {
    asm("fma.rn.f32x2 %0, %1, %2, %3;" : "=l"(c) : "l"(a), "l"(b), "l"(c));
}
__device__ __forceinline__ void add2(u64& c, u64 a) {
    asm("add.rn.f32x2 %0, %1, %2;" : "=l"(c) : "l"(a), "l"(c));
}
// store {v,v} pair to shared without any MOV
__device__ __forceinline__ void sts_dup(u32 addr, float v) {
    asm volatile("st.shared.v2.f32 [%0], {%1, %1};" :: "r"(addr), "f"(v));
}
__device__ __forceinline__ u32 smem_addr(const void* p) {
    return (u32)__cvta_generic_to_shared(p);
}

__device__ __forceinline__ float siluf(float v) {
    return __fdividef(v, 1.0f + __expf(-v));
}
__device__ __forceinline__ void cpf4(float* dst, const float* src, int nfloats,
                                     int tid, int nthreads) {
    const float4* s = reinterpret_cast<const float4*>(src);
    float4* d = reinterpret_cast<float4*>(dst);
    for (int i = tid; i < nfloats / 4; i += nthreads) d[i] = s[i];
}

// ---------------- dtype detection + index canonicalization ------------------
__global__ void ol_detect_kernel(const int* __restrict__ ei32) {
    if (threadIdx.x == 0 && blockIdx.x == 0) {
        int any = 0;
#pragma unroll
        for (int i = 0; i < 64; i++) any |= ei32[2 * i + 1];
        g_is64 = (any == 0) ? 1 : 0;
    }
}

__global__ void ol_convert_kernel(const void* __restrict__ eiv) {
    int i = blockIdx.x * blockDim.x + threadIdx.x;
    if (i >= NEDGES) return;
    if (g_is64) {
        const long long* e = (const long long*)eiv;
        g_rows[i] = (int)e[i];
        g_cols[i] = (int)e[NEDGES + i];
    } else {
        const int* e = (const int*)eiv;
        g_rows[i] = e[i];
        g_cols[i] = e[NEDGES + i];
    }
}

// ---------------- zero vec accumulators ----------------
__global__ void ol_zero_kernel() {
    int i = blockIdx.x * blockDim.x + threadIdx.x;
    if (i < NNODES * 3) { g_vec1[i] = 0.0f; g_vec2[i] = 0.0f; }
}

// ---------------- node precompute: Ha = h@W1a, Hb = h@W1b (f32x2, dup-smem) --
// 256 threads = 8 warps, 8 nodes/warp. act stored as duplicated pairs,
// permuted: value k=4*lane+j at pair-slot 32*j+lane.
#define PRE_SMEM ((256 * 128) * 4 + 8 * 8 * 128 * 8)
__global__ void __launch_bounds__(256, 1)
ol_precompute_kernel(const float* __restrict__ h, const float* __restrict__ eW1) {
    extern __shared__ float smem[];
    float* Wab = smem;                           // 256*128 floats
    float* actbase = smem + 256 * 128;           // 8 warps * 8 nodes * 128 pairs

    cpf4(Wab, eW1, 256 * 128, threadIdx.x, 256);
    __syncthreads();

    const int warp = threadIdx.x >> 5, lane = threadIdx.x & 31;
    float* act = actbase + warp * (8 * 256);     // floats (8 nodes * 128 pairs)
    const u32 act_a = smem_addr(act);
    const ulonglong2* actU = reinterpret_cast<const ulonglong2*>(act);
    const int n0 = (blockIdx.x * 8 + warp) * 8;

    // stage 8 node rows of h as duplicated pairs (permuted slots)
#pragma unroll
    for (int e = 0; e < 8; e++) {
        int n = n0 + e;
        float4 v = make_float4(0.f, 0.f, 0.f, 0.f);
        if (n < NNODES) v = reinterpret_cast<const float4*>(h)[n * 32 + lane];
        u32 base = act_a + e * 1024 + lane * 8;
        sts_dup(base + 0 * 256, v.x);
        sts_dup(base + 1 * 256, v.y);
        sts_dup(base + 2 * 256, v.z);
        sts_dup(base + 3 * 256, v.w);
    }
    __syncwarp();

    u64 accA0[8], accA1[8], accB0[8], accB1[8];
#pragma unroll
    for (int e = 0; e < 8; e++) {
        accA0[e] = 0ull; accA1[e] = 0ull; accB0[e] = 0ull; accB1[e] = 0ull;
    }
    const ulonglong2* Wab2 = reinterpret_cast<const ulonglong2*>(Wab);
#pragma unroll 4
    for (int t = 0; t < 32; t++) {
        int base = ((16 * t) & 127) + (t >> 3);   // k for slot 4t
        ulonglong2 wa0 = Wab2[(base + 0) * 32 + lane];
        ulonglong2 wa1 = Wab2[(base + 4) * 32 + lane];
        ulonglong2 wa2 = Wab2[(base + 8) * 32 + lane];
        ulonglong2 wa3 = Wab2[(base + 12) * 32 + lane];
        ulonglong2 wb0 = Wab2[(128 + base + 0) * 32 + lane];
        ulonglong2 wb1 = Wab2[(128 + base + 4) * 32 + lane];
        ulonglong2 wb2 = Wab2[(128 + base + 8) * 32 + lane];
        ulonglong2 wb3 = Wab2[(128 + base + 12) * 32 + lane];
#pragma unroll
        for (int e = 0; e < 8; e++) {
            ulonglong2 a0 = actU[e * 64 + 2 * t];      // dup pairs slots 4t,4t+1
            ulonglong2 a1 = actU[e * 64 + 2 * t + 1];  // slots 4t+2,4t+3
            fma2(accA0[e], a0.x, wa0.x); fma2(accA1[e], a0.x, wa0.y);
            fma2(accA0[e], a0.y, wa1.x); fma2(accA1[e], a0.y, wa1.y);
            fma2(accA0[e], a1.x, wa2.x); fma2(accA1[e], a1.x, wa2.y);
            fma2(accA0[e], a1.y, wa3.x); fma2(accA1[e], a1.y, wa3.y);
            fma2(accB0[e], a0.x, wb0.x); fma2(accB1[e], a0.x, wb0.y);
            fma2(accB0[e], a0.y, wb1.x); fma2(accB1[e], a0.y, wb1.y);
            fma2(accB0[e], a1.x, wb2.x); fma2(accB1[e], a1.x, wb2.y);
            fma2(accB0[e], a1.y, wb3.x); fma2(accB1[e], a1.y, wb3.y);
        }
    }
#pragma unroll
    for (int e = 0; e < 8; e++) {
        int n = n0 + e;
        if (n < NNODES) {
            reinterpret_cast<ulonglong2*>(g_Ha)[n * 32 + lane] =
                make_ulonglong2(accA0[e], accA1[e]);
            reinterpret_cast<ulonglong2*>(g_Hb)[n * 32 + lane] =
                make_ulonglong2(accB0[e], accB1[e]);
        }
    }
}

// ---------------- fused edge kernel (f32x2, dup-smem acts, 2 edges/warp) ----
// smem floats: W1c 2048 | eW2 16384 | v1W1 16384 | v2W1 16384 | 6*128 |
//              8 warps * (act_dup 512 + ea_dup 64 + wsc 8) = 584/warp
#define EDGE_SMEM ((2048 + 3 * 16384 + 6 * 128 + 8 * 584) * 4)

__global__ void __launch_bounds__(256, 1)
ol_edge_kernel(const float* __restrict__ x,
               const float* __restrict__ edge_attr,
               const float* __restrict__ eW1, const float* __restrict__ eb1,
               const float* __restrict__ eW2, const float* __restrict__ eb2,
               const float* __restrict__ v1W1, const float* __restrict__ v1b1,
               const float* __restrict__ v1W2, const float* __restrict__ v1b2,
               const float* __restrict__ v2W1, const float* __restrict__ v2b1,
               const float* __restrict__ v2W2, const float* __restrict__ v2b2) {
    extern __shared__ float smem[];
    float* sW1c  = smem;                    // 16 x 128
    float* sW2   = sW1c + 2048;             // 128 x 128
    float* sV1   = sW2 + 16384;             // 128 x 128
    float* sV2   = sV1 + 16384;             // 128 x 128
    float* sb1   = sV2 + 16384;
    float* sb2   = sb1 + 128;
    float* sv1b1 = sb2 + 128;
    float* sv2b1 = sv1b1 + 128;
    float* sv1w2 = sv2b1 + 128;
    float* sv2w2 = sv1w2 + 128;
    float* warpbuf = sv2w2 + 128;

    const int tid = threadIdx.x;
    cpf4(sW1c, eW1 + 256 * 128, 2048, tid, 256);
    cpf4(sW2, eW2, 16384, tid, 256);
    cpf4(sV1, v1W1, 16384, tid, 256);
    cpf4(sV2, v2W1, 16384, tid, 256);
    cpf4(sb1, eb1, 128, tid, 256);
    cpf4(sb2, eb2, 128, tid, 256);
    cpf4(sv1b1, v1b1, 128, tid, 256);
    cpf4(sv2b1, v2b1, 128, tid, 256);
    cpf4(sv1w2, v1W2, 128, tid, 256);
    cpf4(sv2w2, v2W2, 128, tid, 256);
    __syncthreads();

    const float c1 = __ldg(v1b2);
    const float c2 = __ldg(v2b2);

    const int warp = tid >> 5, lane = tid & 31;
    float* act = warpbuf + warp * 584;            // 2 edges * 128 dup-pairs
    float* ea  = act + 512;                       // 2 edges * 16 dup-pairs
    float* wsc = ea + 64;                         // 2 edges * 2 scalars
    const u32 act_a = smem_addr(act);
    const u32 ea_a  = smem_addr(ea);
    const ulonglong2* actU = reinterpret_cast<const ulonglong2*>(act);
    const ulonglong2* eaU  = reinterpret_cast<const ulonglong2*>(ea);
    const ulonglong2* sW2_u = reinterpret_cast<const ulonglong2*>(sW2);
    const ulonglong2* sV1_u = reinterpret_cast<const ulonglong2*>(sV1);
    const ulonglong2* sV2_u = reinterpret_cast<const ulonglong2*>(sV2);
    const ulonglong2* sW1c_u = reinterpret_cast<const ulonglong2*>(sW1c);

    const float4 b1v   = reinterpret_cast<const float4*>(sb1)[lane];
    const float4 b2v   = reinterpret_cast<const float4*>(sb2)[lane];
    const float4 v1b1v = reinterpret_cast<const float4*>(sv1b1)[lane];
    const float4 v2b1v = reinterpret_cast<const float4*>(sv2b1)[lane];
    const float4 w2a   = reinterpret_cast<const float4*>(sv1w2)[lane];
    const float4 w2b   = reinterpret_cast<const float4*>(sv2w2)[lane];

    const u64 b1lo = pack2(b1v.x, b1v.y),     b1hi = pack2(b1v.z, b1v.w);
    const u64 b2lo = pack2(b2v.x, b2v.y),     b2hi = pack2(b2v.z, b2v.w);
    const u64 h1lo = pack2(v1b1v.x, v1b1v.y), h1hi = pack2(v1b1v.z, v1b1v.w);
    const u64 h2lo = pack2(v2b1v.x, v2b1v.y), h2hi = pack2(v2b1v.z, v2b1v.w);

    const int ntiles = NEDGES / 16;   // 16 edges per CTA iteration (8 warps * 2)
    for (int tile = blockIdx.x; tile < ntiles; tile += gridDim.x) {
        const int e0 = tile * 16 + warp * 2;

        // ---- indices (lanes 0-1 rows, 2-3 cols), broadcast via shfl ----
        int my = 0;
        if (lane < 2)      my = g_rows[e0 + lane];
        else if (lane < 4) my = g_cols[e0 + (lane - 2)];
        const int idxv = my;
        int rows[2], cols[2];
#pragma unroll
        for (int e = 0; e < 2; e++) {
            rows[e] = __shfl_sync(0xffffffffu, idxv, e);
            cols[e] = __shfl_sync(0xffffffffu, idxv, 2 + e);
        }

        // ---- stage edge_attr as duplicated pairs (2*16 = 32 scalars) ----
        sts_dup(ea_a + lane * 8, edge_attr[e0 * 16 + lane]);
        __syncwarp();

        // ---- layer 1: z1 = Ha[row] + Hb[col] + ea@W1c + b1 ; y1 = silu ----
#pragma unroll
        for (int e = 0; e < 2; e++) {
            ulonglong2 a = reinterpret_cast<const ulonglong2*>(g_Ha)[rows[e] * 32 + lane];
            ulonglong2 b = reinterpret_cast<const ulonglong2*>(g_Hb)[cols[e] * 32 + lane];
            u64 acc0 = b1lo, acc1 = b1hi;
            add2(acc0, a.x); add2(acc0, b.x);
            add2(acc1, a.y); add2(acc1, b.y);
#pragma unroll
            for (int kk = 0; kk < 4; kk++) {
                ulonglong2 d0 = eaU[e * 8 + 2 * kk];       // dup(a_{4kk}), dup(a_{4kk+1})
                ulonglong2 d1 = eaU[e * 8 + 2 * kk + 1];   // dup(a_{4kk+2}), dup(a_{4kk+3})
                ulonglong2 w0 = sW1c_u[(4 * kk + 0) * 32 + lane];
                ulonglong2 w1 = sW1c_u[(4 * kk + 1) * 32 + lane];
                ulonglong2 w2 = sW1c_u[(4 * kk + 2) * 32 + lane];
                ulonglong2 w3 = sW1c_u[(4 * kk + 3) * 32 + lane];
                fma2(acc0, d0.x, w0.x); fma2(acc1, d0.x, w0.y);
                fma2(acc0, d0.y, w1.x); fma2(acc1, d0.y, w1.y);
                fma2(acc0, d1.x, w2.x); fma2(acc1, d1.x, w2.y);
                fma2(acc0, d1.y, w3.x); fma2(acc1, d1.y, w3.y);
            }
            float2 lo = unpack2(acc0), hi = unpack2(acc1);
            u32 basea = act_a + e * 1024 + lane * 8;
            sts_dup(basea + 0 * 256, siluf(lo.x));   // k=4*lane+0 -> slot 0*32+lane
            sts_dup(basea + 1 * 256, siluf(lo.y));
            sts_dup(basea + 2 * 256, siluf(hi.x));
            sts_dup(basea + 3 * 256, siluf(hi.y));
        }
        __syncwarp();

        // ---- layer 2: ef = silu(y1 @ eW2 + b2) ----
        {
            u64 acc0[2], acc1[2];
#pragma unroll
            for (int e = 0; e < 2; e++) { acc0[e] = b2lo; acc1[e] = b2hi; }
#pragma unroll 4
            for (int t = 0; t < 32; t++) {
                int base = ((16 * t) & 127) + (t >> 3);
                ulonglong2 w0 = sW2_u[(base + 0) * 32 + lane];
                ulonglong2 w1 = sW2_u[(base + 4) * 32 + lane];
                ulonglong2 w2 = sW2_u[(base + 8) * 32 + lane];
                ulonglong2 w3 = sW2_u[(base + 12) * 32 + lane];
#pragma unroll
                for (int e = 0; e < 2; e++) {
                    ulonglong2 a0 = actU[e * 64 + 2 * t];
                    ulonglong2 a1 = actU[e * 64 + 2 * t + 1];
                    fma2(acc0[e], a0.x, w0.x); fma2(acc1[e], a0.x, w0.y);
                    fma2(acc0[e], a0.y, w1.x); fma2(acc1[e], a0.y, w1.y);
                    fma2(acc0[e], a1.x, w2.x); fma2(acc1[e], a1.x, w2.y);
                    fma2(acc0[e], a1.y, w3.x); fma2(acc1[e], a1.y, w3.y);
                }
            }
            __syncwarp();   // everyone done reading y1
#pragma unroll
            for (int e = 0; e < 2; e++) {
                float2 lo = unpack2(acc0[e]), hi = unpack2(acc1[e]);
                u32 basea = act_a + e * 1024 + lane * 8;
                sts_dup(basea + 0 * 256, siluf(lo.x));
                sts_dup(basea + 1 * 256, siluf(lo.y));
                sts_dup(basea + 2 * 256, siluf(hi.x));
                sts_dup(basea + 3 * 256, siluf(hi.y));
            }
            __syncwarp();
        }

        // ---- heads fused: u1 = silu(ef@v1W1+v1b1), u2 = silu(ef@v2W1+v2b1) ----
        {
            u64 a10[2], a11[2], a20[2], a21[2];
#pragma unroll
            for (int e = 0; e < 2; e++) {
                a10[e] = h1lo; a11[e] = h1hi; a20[e] = h2lo; a21[e] = h2hi;
            }
#pragma unroll 4
            for (int t = 0; t < 32; t++) {
                int base = ((16 * t) & 127) + (t >> 3);
                ulonglong2 p0 = sV1_u[(base + 0) * 32 + lane];
                ulonglong2 p1 = sV1_u[(base + 4) * 32 + lane];
                ulonglong2 p2 = sV1_u[(base + 8) * 32 + lane];
                ulonglong2 p3 = sV1_u[(base + 12) * 32 + lane];
                ulonglong2 q0 = sV2_u[(base + 0) * 32 + lane];
                ulonglong2 q1 = sV2_u[(base + 4) * 32 + lane];
                ulonglong2 q2 = sV2_u[(base + 8) * 32 + lane];
                ulonglong2 q3 = sV2_u[(base + 12) * 32 + lane];
#pragma unroll
                for (int e = 0; e < 2; e++) {
                    ulonglong2 a0 = actU[e * 64 + 2 * t];
                    ulonglong2 a1 = actU[e * 64 + 2 * t + 1];
                    fma2(a10[e], a0.x, p0.x); fma2(a11[e], a0.x, p0.y);
                    fma2(a10[e], a0.y, p1.x); fma2(a11[e], a0.y, p1.y);
                    fma2(a10[e], a1.x, p2.x); fma2(a11[e], a1.x, p2.y);
                    fma2(a10[e], a1.y, p3.x); fma2(a11[e], a1.y, p3.y);
                    fma2(a20[e], a0.x, q0.x); fma2(a21[e], a0.x, q0.y);
                    fma2(a20[e], a0.y, q1.x); fma2(a21[e], a0.y, q1.y);
                    fma2(a20[e], a1.x, q2.x); fma2(a21[e], a1.x, q2.y);
                    fma2(a20[e], a1.y, q3.x); fma2(a21[e], a1.y, q3.y);
                }
            }
#pragma unroll
            for (int e = 0; e < 2; e++) {
                float2 lo = unpack2(a10[e]), hi = unpack2(a11[e]);
                float p = siluf(lo.x) * w2a.x + siluf(lo.y) * w2a.y
                        + siluf(hi.x) * w2a.z + siluf(hi.y) * w2a.w;
                float2 lo2 = unpack2(a20[e]), hi2 = unpack2(a21[e]);
                float q = siluf(lo2.x) * w2b.x + siluf(lo2.y) * w2b.y
                        + siluf(hi2.x) * w2b.z + siluf(hi2.y) * w2b.w;
#pragma unroll
                for (int off = 16; off; off >>= 1) {
                    p += __shfl_xor_sync(0xffffffffu, p, off);
                    q += __shfl_xor_sync(0xffffffffu, q, off);
                }
                if (lane == 0) { wsc[2 * e] = p + c1; wsc[2 * e + 1] = q + c2; }
            }
        }
        __syncwarp();

        // ---- scatter: lanes 0..5 -> (edge e = lane/3, component d = lane%3)
        {
            int e = lane / 3;
            int d = lane - 3 * e;
            int r = __shfl_sync(0xffffffffu, idxv, (e < 2) ? e : 0);
            int c = __shfl_sync(0xffffffffu, idxv, (e < 2) ? (2 + e) : 2);
            if (lane < 6) {
                float rp = x[c * 3 + d] - x[r * 3 + d];
                atomicAdd(&g_vec1[r * 3 + d], rp * wsc[2 * e]);
                atomicAdd(&g_vec2[r * 3 + d], rp * wsc[2 * e + 1]);
            }
        }
        __syncwarp();
    }
}

// ---------------- finalize: Gram-Schmidt per node ----------------
__global__ void ol_finalize_kernel(float* __restrict__ out) {
    int n = blockIdx.x * blockDim.x + threadIdx.x;
    if (n >= NNODES) return;
    float v1x = g_vec1[n * 3 + 0], v1y = g_vec1[n * 3 + 1], v1z = g_vec1[n * 3 + 2];
    float v2x = g_vec2[n * 3 + 0], v2y = g_vec2[n * 3 + 1], v2z = g_vec2[n * 3 + 2];

    float n1 = fmaxf(sqrtf(v1x * v1x + v1y * v1y + v1z * v1z), 1e-12f);
    float e1x = v1x / n1, e1y = v1y / n1, e1z = v1z / n1;

    float dp = e1x * v2x + e1y * v2y + e1z * v2z;
    float px = v2x - dp * e1x, py = v2y - dp * e1y, pz = v2z - dp * e1z;
    float n2 = fmaxf(sqrtf(px * px + py * py + pz * pz), 1e-12f);
    float e2x = px / n2, e2y = py / n2, e2z = pz / n2;

    float e3x = e1y * e2z - e1z * e2y;
    float e3y = e1z * e2x - e1x * e2z;
    float e3z = e1x * e2y - e1y * e2x;

    float* o = out + n * 9;     // out[n, i, j] = (e_j)[i]
    o[0] = e1x; o[1] = e2x; o[2] = e3x;
    o[3] = e1y; o[4] = e2y; o[5] = e3y;
    o[6] = e1z; o[7] = e2z; o[8] = e3z;
}

// ---------------- launch ----------------
extern "C" void kernel_launch(void* const* d_in, const int* in_sizes, int n_in,
                              void* d_out, int out_size) {
    const float* h         = (const float*)d_in[0];
    const float* x         = (const float*)d_in[1];
    const void*  ei        = d_in[2];
    const float* edge_attr = (const float*)d_in[3];
    const float* eW1 = (const float*)d_in[4];  const float* eb1 = (const float*)d_in[5];
    const float* eW2 = (const float*)d_in[6];  const float* eb2 = (const float*)d_in[7];
    const float* v1W1 = (const float*)d_in[8]; const float* v1b1 = (const float*)d_in[9];
    const float* v1W2 = (const float*)d_in[10]; const float* v1b2 = (const float*)d_in[11];
    const float* v2W1 = (const float*)d_in[12]; const float* v2b1 = (const float*)d_in[13];
    const float* v2W2 = (const float*)d_in[14]; const float* v2b2 = (const float*)d_in[15];
    float* out = (float*)d_out;

    cudaFuncSetAttribute(ol_precompute_kernel,
                         cudaFuncAttributeMaxDynamicSharedMemorySize, PRE_SMEM);
    cudaFuncSetAttribute(ol_edge_kernel,
                         cudaFuncAttributeMaxDynamicSharedMemorySize, EDGE_SMEM);

    ol_detect_kernel<<<1, 32>>>((const int*)ei);
    ol_convert_kernel<<<(NEDGES + 255) / 256, 256>>>(ei);
    ol_zero_kernel<<<(NNODES * 3 + 255) / 256, 256>>>();
    ol_precompute_kernel<<<(NNODES + 63) / 64, 256, PRE_SMEM>>>(h, eW1);
    ol_edge_kernel<<<148, 256, EDGE_SMEM>>>(x, edge_attr,
                                            eW1, eb1, eW2, eb2,
                                            v1W1, v1b1, v1W2, v1b2,
                                            v2W1, v2b1, v2W2, v2b2);
    ol_finalize_kernel<<<(NNODES + 255) / 256, 256>>>(out);
}

// round 6
// speedup vs baseline: 1.2051x; 1.2051x over previous
#include <cuda_runtime.h>
#include <math.h>

#define NNODES 50000
#define NEDGES 800000
#define HID    128
#define FE     16

typedef unsigned long long u64;
typedef unsigned int u32;

// ---------------- scratch ----------------
__device__ float g_Ha[NNODES * HID];    // h @ eW1[0:128,:]
__device__ float g_Hb[NNODES * HID];    // h @ eW1[128:256,:]
__device__ float g_vec1[NNODES * 3];
__device__ float g_vec2[NNODES * 3];
__device__ int   g_rows[NEDGES];
__device__ int   g_cols[NEDGES];
__device__ int   g_is64;

// ---------------- f32x2 helpers ----------------
__device__ __forceinline__ u64 dup2(float s) {
    u64 r; asm("mov.b64 %0, {%1, %1};" : "=l"(r) : "f"(s)); return r;
}
__device__ __forceinline__ u64 pack2(float lo, float hi) {
    u64 r; asm("mov.b64 %0, {%1, %2};" : "=l"(r) : "f"(lo), "f"(hi)); return r;
}
__device__ __forceinline__ float2 unpack2(u64 v) {
    float2 f; asm("mov.b64 {%0, %1}, %2;" : "=f"(f.x), "=f"(f.y) : "l"(v)); return f;
}
__device__ __forceinline__ void fma2(u64& c, u64 a, u64 b) {
    asm("fma.rn.f32x2 %0, %1, %2, %3;" : "=l"(c) : "l"(a), "l"(b), "l"(c));
}

__device__ __forceinline__ float siluf(float v) {
    return __fdividef(v, 1.0f + __expf(-v));
}
__device__ __forceinline__ void cpf4(float* dst, const float* src, int nfloats,
                                     int tid, int nthreads) {
    const float4* s = reinterpret_cast<const float4*>(src);
    float4* d = reinterpret_cast<float4*>(dst);
    for (int i = tid; i < nfloats / 4; i += nthreads) d[i] = s[i];
}
// Repack [K][128] row-major weights into k-pair interleaved u64 [K/2][128]:
// Wp[kp][n] = {W[2kp][n], W[2kp+1][n]}
__device__ __forceinline__ void repack_pairs(float* dst, const float* src, int K,
                                             int tid, int nthreads) {
    int total = (K / 2) * 32;
    const float4* s4 = reinterpret_cast<const float4*>(src);
    u64* d = reinterpret_cast<u64*>(dst);
    for (int i = tid; i < total; i += nthreads) {
        int kp = i >> 5, n4 = i & 31;
        float4 r0 = s4[(2 * kp) * 32 + n4];
        float4 r1 = s4[(2 * kp + 1) * 32 + n4];
        u64* o = d + kp * 128 + n4 * 4;
        o[0] = pack2(r0.x, r1.x);
        o[1] = pack2(r0.y, r1.y);
        o[2] = pack2(r0.z, r1.z);
        o[3] = pack2(r0.w, r1.w);
    }
}

// ---------------- dtype detection + index canonicalization ------------------
__global__ void ol_detect_kernel(const int* __restrict__ ei32) {
    if (threadIdx.x == 0 && blockIdx.x == 0) {
        int any = 0;
#pragma unroll
        for (int i = 0; i < 64; i++) any |= ei32[2 * i + 1];
        g_is64 = (any == 0) ? 1 : 0;
    }
}

__global__ void ol_convert_kernel(const void* __restrict__ eiv) {
    int i = blockIdx.x * blockDim.x + threadIdx.x;
    if (i >= NEDGES) return;
    if (g_is64) {
        const long long* e = (const long long*)eiv;
        g_rows[i] = (int)e[i];
        g_cols[i] = (int)e[NEDGES + i];
    } else {
        const int* e = (const int*)eiv;
        g_rows[i] = e[i];
        g_cols[i] = e[NEDGES + i];
    }
}

// ---------------- zero vec accumulators ----------------
__global__ void ol_zero_kernel() {
    int i = blockIdx.x * blockDim.x + threadIdx.x;
    if (i < NNODES * 3) { g_vec1[i] = 0.0f; g_vec2[i] = 0.0f; }
}

// ---------------- node precompute (R4 version: known 96us) ------------------
#define PRE_SMEM ((256 * 128 + 8 * 8 * 128) * 4)
__global__ void __launch_bounds__(256, 1)
ol_precompute_kernel(const float* __restrict__ h, const float* __restrict__ eW1) {
    extern __shared__ float smem[];
    float* Wab = smem;
    float* act = smem + 256 * 128;

    cpf4(Wab, eW1, 256 * 128, threadIdx.x, 256);
    __syncthreads();

    const int warp = threadIdx.x >> 5, lane = threadIdx.x & 31;
    float* myAct = act + warp * (8 * 128);
    float4* myAct4 = reinterpret_cast<float4*>(myAct);
    const int n0 = (blockIdx.x * 8 + warp) * 8;

#pragma unroll
    for (int e = 0; e < 8; e++) {
        int n = n0 + e;
        float4 v = make_float4(0.f, 0.f, 0.f, 0.f);
        if (n < NNODES) v = reinterpret_cast<const float4*>(h)[n * 32 + lane];
        myAct4[e * 32 + lane] = v;
    }
    __syncwarp();

    u64 accA0[8], accA1[8], accB0[8], accB1[8];
#pragma unroll
    for (int e = 0; e < 8; e++) {
        accA0[e] = 0ull; accA1[e] = 0ull; accB0[e] = 0ull; accB1[e] = 0ull;
    }
    const ulonglong2* Wab2 = reinterpret_cast<const ulonglong2*>(Wab);
    for (int kb = 0; kb < 32; kb++) {
        ulonglong2 wa0 = Wab2[(4 * kb + 0) * 32 + lane];
        ulonglong2 wa1 = Wab2[(4 * kb + 1) * 32 + lane];
        ulonglong2 wa2 = Wab2[(4 * kb + 2) * 32 + lane];
        ulonglong2 wa3 = Wab2[(4 * kb + 3) * 32 + lane];
        ulonglong2 wb0 = Wab2[(128 + 4 * kb + 0) * 32 + lane];
        ulonglong2 wb1 = Wab2[(128 + 4 * kb + 1) * 32 + lane];
        ulonglong2 wb2 = Wab2[(128 + 4 * kb + 2) * 32 + lane];
        ulonglong2 wb3 = Wab2[(128 + 4 * kb + 3) * 32 + lane];
#pragma unroll
        for (int e = 0; e < 8; e++) {
            float4 a = myAct4[e * 32 + kb];
            u64 dx = dup2(a.x), dy = dup2(a.y), dz = dup2(a.z), dw = dup2(a.w);
            fma2(accA0[e], dx, wa0.x); fma2(accA1[e], dx, wa0.y);
            fma2(accA0[e], dy, wa1.x); fma2(accA1[e], dy, wa1.y);
            fma2(accA0[e], dz, wa2.x); fma2(accA1[e], dz, wa2.y);
            fma2(accA0[e], dw, wa3.x); fma2(accA1[e], dw, wa3.y);
            fma2(accB0[e], dx, wb0.x); fma2(accB1[e], dx, wb0.y);
            fma2(accB0[e], dy, wb1.x); fma2(accB1[e], dy, wb1.y);
            fma2(accB0[e], dz, wb2.x); fma2(accB1[e], dz, wb2.y);
            fma2(accB0[e], dw, wb3.x); fma2(accB1[e], dw, wb3.y);
        }
    }
#pragma unroll
    for (int e = 0; e < 8; e++) {
        int n = n0 + e;
        if (n < NNODES) {
            reinterpret_cast<ulonglong2*>(g_Ha)[n * 32 + lane] =
                make_ulonglong2(accA0[e], accA1[e]);
            reinterpret_cast<ulonglong2*>(g_Hb)[n * 32 + lane] =
                make_ulonglong2(accB0[e], accB1[e]);
        }
    }
}

// ---------------- fused edge kernel (k-pair FFMA2, 8 warps x 4 edges) -------
// smem floats: W1c_p 2048 | eW2_p 16384 | v1W1_p 16384 | v2W1_p 16384 |
//              6*128 vectors | 8 warps * (act 512 + ea 64 + wsc 8)
#define EDGE_SMEM ((2048 + 3 * 16384 + 6 * 128 + 8 * 584) * 4)

__global__ void __launch_bounds__(256, 1)
ol_edge_kernel(const float* __restrict__ x,
               const float* __restrict__ edge_attr,
               const float* __restrict__ eW1, const float* __restrict__ eb1,
               const float* __restrict__ eW2, const float* __restrict__ eb2,
               const float* __restrict__ v1W1, const float* __restrict__ v1b1,
               const float* __restrict__ v1W2, const float* __restrict__ v1b2,
               const float* __restrict__ v2W1, const float* __restrict__ v2b1,
               const float* __restrict__ v2W2, const float* __restrict__ v2b2) {
    extern __shared__ float smem[];
    float* sW1c  = smem;                    // k-pair packed [8][128] u64
    float* sW2   = sW1c + 2048;             // [64][128] u64
    float* sV1   = sW2 + 16384;
    float* sV2   = sV1 + 16384;
    float* sb1   = sV2 + 16384;
    float* sb2   = sb1 + 128;
    float* sv1b1 = sb2 + 128;
    float* sv2b1 = sv1b1 + 128;
    float* sv1w2 = sv2b1 + 128;
    float* sv2w2 = sv1w2 + 128;
    float* warpbuf = sv2w2 + 128;

    const int tid = threadIdx.x;
    repack_pairs(sW1c, eW1 + 256 * 128, 16, tid, 256);
    repack_pairs(sW2, eW2, 128, tid, 256);
    repack_pairs(sV1, v1W1, 128, tid, 256);
    repack_pairs(sV2, v2W1, 128, tid, 256);
    cpf4(sb1, eb1, 128, tid, 256);
    cpf4(sb2, eb2, 128, tid, 256);
    cpf4(sv1b1, v1b1, 128, tid, 256);
    cpf4(sv2b1, v2b1, 128, tid, 256);
    cpf4(sv1w2, v1W2, 128, tid, 256);
    cpf4(sv2w2, v2W2, 128, tid, 256);
    __syncthreads();

    const float c1 = __ldg(v1b2);
    const float c2 = __ldg(v2b2);

    const int warp = tid >> 5, lane = tid & 31;
    float* act = warpbuf + warp * 584;            // 4 edges * 128 (natural float4)
    float* ea  = act + 512;                       // 4 edges * 16
    float* wsc = ea + 64;                         // 4 edges * 2
    float4* act4 = reinterpret_cast<float4*>(act);
    const ulonglong2* actU2 = reinterpret_cast<const ulonglong2*>(act);
    const ulonglong2* eaU2  = reinterpret_cast<const ulonglong2*>(ea);
    const ulonglong2* W1cp = reinterpret_cast<const ulonglong2*>(sW1c);  // [kp*64 + n/2]
    const ulonglong2* W2p  = reinterpret_cast<const ulonglong2*>(sW2);
    const ulonglong2* V1p  = reinterpret_cast<const ulonglong2*>(sV1);
    const ulonglong2* V2p  = reinterpret_cast<const ulonglong2*>(sV2);

    const float4 b1v   = reinterpret_cast<const float4*>(sb1)[lane];
    const float4 b2v   = reinterpret_cast<const float4*>(sb2)[lane];
    const float4 v1b1v = reinterpret_cast<const float4*>(sv1b1)[lane];
    const float4 v2b1v = reinterpret_cast<const float4*>(sv2b1)[lane];
    const float4 w2a   = reinterpret_cast<const float4*>(sv1w2)[lane];
    const float4 w2b   = reinterpret_cast<const float4*>(sv2w2)[lane];

    const int ntiles = NEDGES / 32;
    for (int tile = blockIdx.x; tile < ntiles; tile += gridDim.x) {
        const int e0 = tile * 32 + warp * 4;

        // ---- indices (lanes 0-3 rows, 4-7 cols), broadcast via shfl ----
        int my = 0;
        if (lane < 4)      my = g_rows[e0 + lane];
        else if (lane < 8) my = g_cols[e0 + (lane - 4)];
        const int idxv = my;
        int rows[4], cols[4];
#pragma unroll
        for (int e = 0; e < 4; e++) {
            rows[e] = __shfl_sync(0xffffffffu, idxv, e);
            cols[e] = __shfl_sync(0xffffffffu, idxv, 4 + e);
        }

        // ---- stage edge_attr (4*16 = 64 contiguous floats) ----
#pragma unroll
        for (int i = 0; i < 2; i++)
            ea[i * 32 + lane] = edge_attr[e0 * 16 + i * 32 + lane];
        __syncwarp();

        // ---- layer 1: z1 = Ha[row] + Hb[col] + ea@W1c + b1 ; y1 = silu ----
#pragma unroll
        for (int e = 0; e < 4; e++) {
            float4 ga = reinterpret_cast<const float4*>(g_Ha)[rows[e] * 32 + lane];
            float4 gb = reinterpret_cast<const float4*>(g_Hb)[cols[e] * 32 + lane];
            u64 acc0 = pack2(ga.x + gb.x + b1v.x, 0.f);
            u64 acc1 = pack2(ga.y + gb.y + b1v.y, 0.f);
            u64 acc2 = pack2(ga.z + gb.z + b1v.z, 0.f);
            u64 acc3 = pack2(ga.w + gb.w + b1v.w, 0.f);
#pragma unroll
            for (int t = 0; t < 4; t++) {
                ulonglong2 av = eaU2[e * 4 + t];   // {a4t,a4t+1},{a4t+2,a4t+3}
                ulonglong2 w00 = W1cp[(2 * t) * 64 + 2 * lane];
                ulonglong2 w01 = W1cp[(2 * t) * 64 + 2 * lane + 1];
                ulonglong2 w10 = W1cp[(2 * t + 1) * 64 + 2 * lane];
                ulonglong2 w11 = W1cp[(2 * t + 1) * 64 + 2 * lane + 1];
                fma2(acc0, av.x, w00.x); fma2(acc1, av.x, w00.y);
                fma2(acc2, av.x, w01.x); fma2(acc3, av.x, w01.y);
                fma2(acc0, av.y, w10.x); fma2(acc1, av.y, w10.y);
                fma2(acc2, av.y, w11.x); fma2(acc3, av.y, w11.y);
            }
            float2 f0 = unpack2(acc0), f1 = unpack2(acc1);
            float2 f2 = unpack2(acc2), f3 = unpack2(acc3);
            act4[e * 32 + lane] = make_float4(siluf(f0.x + f0.y), siluf(f1.x + f1.y),
                                              siluf(f2.x + f2.y), siluf(f3.x + f3.y));
        }
        __syncwarp();

        // ---- layer 2: ef = silu(y1 @ eW2 + b2) ----
        {
            u64 a0[4], a1[4], a2[4], a3[4];
#pragma unroll
            for (int e = 0; e < 4; e++) {
                a0[e] = pack2(b2v.x, 0.f); a1[e] = pack2(b2v.y, 0.f);
                a2[e] = pack2(b2v.z, 0.f); a3[e] = pack2(b2v.w, 0.f);
            }
            for (int t = 0; t < 32; t++) {
                ulonglong2 w00 = W2p[(2 * t) * 64 + 2 * lane];
                ulonglong2 w01 = W2p[(2 * t) * 64 + 2 * lane + 1];
                ulonglong2 w10 = W2p[(2 * t + 1) * 64 + 2 * lane];
                ulonglong2 w11 = W2p[(2 * t + 1) * 64 + 2 * lane + 1];
#pragma unroll
                for (int e = 0; e < 4; e++) {
                    ulonglong2 av = actU2[e * 32 + t];
                    fma2(a0[e], av.x, w00.x); fma2(a1[e], av.x, w00.y);
                    fma2(a2[e], av.x, w01.x); fma2(a3[e], av.x, w01.y);
                    fma2(a0[e], av.y, w10.x); fma2(a1[e], av.y, w10.y);
                    fma2(a2[e], av.y, w11.x); fma2(a3[e], av.y, w11.y);
                }
            }
            __syncwarp();   // everyone done reading y1
#pragma unroll
            for (int e = 0; e < 4; e++) {
                float2 f0 = unpack2(a0[e]), f1 = unpack2(a1[e]);
                float2 f2 = unpack2(a2[e]), f3 = unpack2(a3[e]);
                act4[e * 32 + lane] = make_float4(siluf(f0.x + f0.y), siluf(f1.x + f1.y),
                                                  siluf(f2.x + f2.y), siluf(f3.x + f3.y));
            }
            __syncwarp();
        }

        // ---- heads fused ----
        {
            u64 p0[4], p1[4], p2[4], p3[4], q0[4], q1[4], q2[4], q3[4];
#pragma unroll
            for (int e = 0; e < 4; e++) {
                p0[e] = pack2(v1b1v.x, 0.f); p1[e] = pack2(v1b1v.y, 0.f);
                p2[e] = pack2(v1b1v.z, 0.f); p3[e] = pack2(v1b1v.w, 0.f);
                q0[e] = pack2(v2b1v.x, 0.f); q1[e] = pack2(v2b1v.y, 0.f);
                q2[e] = pack2(v2b1v.z, 0.f); q3[e] = pack2(v2b1v.w, 0.f);
            }
            for (int t = 0; t < 32; t++) {
                ulonglong2 u00 = V1p[(2 * t) * 64 + 2 * lane];
                ulonglong2 u01 = V1p[(2 * t) * 64 + 2 * lane + 1];
                ulonglong2 u10 = V1p[(2 * t + 1) * 64 + 2 * lane];
                ulonglong2 u11 = V1p[(2 * t + 1) * 64 + 2 * lane + 1];
                ulonglong2 v00 = V2p[(2 * t) * 64 + 2 * lane];
                ulonglong2 v01 = V2p[(2 * t) * 64 + 2 * lane + 1];
                ulonglong2 v10 = V2p[(2 * t + 1) * 64 + 2 * lane];
                ulonglong2 v11 = V2p[(2 * t + 1) * 64 + 2 * lane + 1];
#pragma unroll
                for (int e = 0; e < 4; e++) {
                    ulonglong2 av = actU2[e * 32 + t];
                    fma2(p0[e], av.x, u00.x); fma2(p1[e], av.x, u00.y);
                    fma2(p2[e], av.x, u01.x); fma2(p3[e], av.x, u01.y);
                    fma2(p0[e], av.y, u10.x); fma2(p1[e], av.y, u10.y);
                    fma2(p2[e], av.y, u11.x); fma2(p3[e], av.y, u11.y);
                    fma2(q0[e], av.x, v00.x); fma2(q1[e], av.x, v00.y);
                    fma2(q2[e], av.x, v01.x); fma2(q3[e], av.x, v01.y);
                    fma2(q0[e], av.y, v10.x); fma2(q1[e], av.y, v10.y);
                    fma2(q2[e], av.y, v11.x); fma2(q3[e], av.y, v11.y);
                }
            }
#pragma unroll
            for (int e = 0; e < 4; e++) {
                float2 f0 = unpack2(p0[e]), f1 = unpack2(p1[e]);
                float2 f2 = unpack2(p2[e]), f3 = unpack2(p3[e]);
                float p = siluf(f0.x + f0.y) * w2a.x + siluf(f1.x + f1.y) * w2a.y
                        + siluf(f2.x + f2.y) * w2a.z + siluf(f3.x + f3.y) * w2a.w;
                float2 g0 = unpack2(q0[e]), g1 = unpack2(q1[e]);
                float2 g2 = unpack2(q2[e]), g3 = unpack2(q3[e]);
                float q = siluf(g0.x + g0.y) * w2b.x + siluf(g1.x + g1.y) * w2b.y
                        + siluf(g2.x + g2.y) * w2b.z + siluf(g3.x + g3.y) * w2b.w;
#pragma unroll
                for (int off = 16; off; off >>= 1) {
                    p += __shfl_xor_sync(0xffffffffu, p, off);
                    q += __shfl_xor_sync(0xffffffffu, q, off);
                }
                if (lane == 0) { wsc[2 * e] = p + c1; wsc[2 * e + 1] = q + c2; }
            }
        }
        __syncwarp();

        // ---- scatter: lanes 0..11 -> (edge e = lane/3, component d = lane%3)
        {
            int e = lane / 3;
            int d = lane - 3 * e;
            int r = __shfl_sync(0xffffffffu, idxv, (e < 4) ? e : 0);
            int c = __shfl_sync(0xffffffffu, idxv, (e < 4) ? (4 + e) : 4);
            if (lane < 12) {
                float rp = x[c * 3 + d] - x[r * 3 + d];
                atomicAdd(&g_vec1[r * 3 + d], rp * wsc[2 * e]);
                atomicAdd(&g_vec2[r * 3 + d], rp * wsc[2 * e + 1]);
            }
        }
        __syncwarp();
    }
}

// ---------------- finalize: Gram-Schmidt per node ----------------
__global__ void ol_finalize_kernel(float* __restrict__ out) {
    int n = blockIdx.x * blockDim.x + threadIdx.x;
    if (n >= NNODES) return;
    float v1x = g_vec1[n * 3 + 0], v1y = g_vec1[n * 3 + 1], v1z = g_vec1[n * 3 + 2];
    float v2x = g_vec2[n * 3 + 0], v2y = g_vec2[n * 3 + 1], v2z = g_vec2[n * 3 + 2];

    float n1 = fmaxf(sqrtf(v1x * v1x + v1y * v1y + v1z * v1z), 1e-12f);
    float e1x = v1x / n1, e1y = v1y / n1, e1z = v1z / n1;

    float dp = e1x * v2x + e1y * v2y + e1z * v2z;
    float px = v2x - dp * e1x, py = v2y - dp * e1y, pz = v2z - dp * e1z;
    float n2 = fmaxf(sqrtf(px * px + py * py + pz * pz), 1e-12f);
    float e2x = px / n2, e2y = py / n2, e2z = pz / n2;

    float e3x = e1y * e2z - e1z * e2y;
    float e3y = e1z * e2x - e1x * e2z;
    float e3z = e1x * e2y - e1y * e2x;

    float* o = out + n * 9;     // out[n, i, j] = (e_j)[i]
    o[0] = e1x; o[1] = e2x; o[2] = e3x;
    o[3] = e1y; o[4] = e2y; o[5] = e3y;
    o[6] = e1z; o[7] = e2z; o[8] = e3z;
}

// ---------------- launch ----------------
extern "C" void kernel_launch(void* const* d_in, const int* in_sizes, int n_in,
                              void* d_out, int out_size) {
    const float* h         = (const float*)d_in[0];
    const float* x         = (const float*)d_in[1];
    const void*  ei        = d_in[2];
    const float* edge_attr = (const float*)d_in[3];
    const float* eW1 = (const float*)d_in[4];  const float* eb1 = (const float*)d_in[5];
    const float* eW2 = (const float*)d_in[6];  const float* eb2 = (const float*)d_in[7];
    const float* v1W1 = (const float*)d_in[8]; const float* v1b1 = (const float*)d_in[9];
    const float* v1W2 = (const float*)d_in[10]; const float* v1b2 = (const float*)d_in[11];
    const float* v2W1 = (const float*)d_in[12]; const float* v2b1 = (const float*)d_in[13];
    const float* v2W2 = (const float*)d_in[14]; const float* v2b2 = (const float*)d_in[15];
    float* out = (float*)d_out;

    cudaFuncSetAttribute(ol_precompute_kernel,
                         cudaFuncAttributeMaxDynamicSharedMemorySize, PRE_SMEM);
    cudaFuncSetAttribute(ol_edge_kernel,
                         cudaFuncAttributeMaxDynamicSharedMemorySize, EDGE_SMEM);

    ol_detect_kernel<<<1, 32>>>((const int*)ei);
    ol_convert_kernel<<<(NEDGES + 255) / 256, 256>>>(ei);
    ol_zero_kernel<<<(NNODES * 3 + 255) / 256, 256>>>();
    ol_precompute_kernel<<<(NNODES + 63) / 64, 256, PRE_SMEM>>>(h, eW1);
    ol_edge_kernel<<<148, 256, EDGE_SMEM>>>(x, edge_attr,
                                            eW1, eb1, eW2, eb2,
                                            v1W1, v1b1, v1W2, v1b2,
                                            v2W1, v2b1, v2W2, v2b2);
    ol_finalize_kernel<<<(NNODES + 255) / 256, 256>>>(out);
}

// round 7
// speedup vs baseline: 1.3209x; 1.0961x over previous
#include <cuda_runtime.h>
#include <math.h>

#define NNODES 50000
#define NEDGES 800000
#define HID    128
#define FE     16

typedef unsigned long long u64;
typedef unsigned int u32;

// ---------------- scratch ----------------
// g_Ha/g_Hb rows are PERMUTED: float index 4*l+j of a row holds dim (l + 32*j),
// so an edge-kernel float4 load at [row*32 + lane] yields dims {lane+32j}.
__device__ float g_Ha[NNODES * HID];
__device__ float g_Hb[NNODES * HID];
__device__ float g_vec1[NNODES * 3];
__device__ float g_vec2[NNODES * 3];
__device__ int   g_rows[NEDGES];
__device__ int   g_cols[NEDGES];
__device__ int   g_is64;

// ---------------- f32x2 helpers ----------------
__device__ __forceinline__ u64 dup2(float s) {
    u64 r; asm("mov.b64 %0, {%1, %1};" : "=l"(r) : "f"(s)); return r;
}
__device__ __forceinline__ u64 pack2(float lo, float hi) {
    u64 r; asm("mov.b64 %0, {%1, %2};" : "=l"(r) : "f"(lo), "f"(hi)); return r;
}
__device__ __forceinline__ float2 unpack2(u64 v) {
    float2 f; asm("mov.b64 {%0, %1}, %2;" : "=f"(f.x), "=f"(f.y) : "l"(v)); return f;
}
__device__ __forceinline__ void fma2(u64& c, u64 a, u64 b) {
    asm("fma.rn.f32x2 %0, %1, %2, %3;" : "=l"(c) : "l"(a), "l"(b), "l"(c));
}

__device__ __forceinline__ float siluf(float v) {
    return __fdividef(v, 1.0f + __expf(-v));
}
__device__ __forceinline__ void cpf4(float* dst, const float* src, int nfloats,
                                     int tid, int nthreads) {
    const float4* s = reinterpret_cast<const float4*>(src);
    float4* d = reinterpret_cast<float4*>(dst);
    for (int i = tid; i < nfloats / 4; i += nthreads) d[i] = s[i];
}
// Repack [K][128] row-major weights into k-pair interleaved u64 layout:
// Wp[kp*128 + n] = {W[2kp][n], W[2kp+1][n]}
__device__ __forceinline__ void repack_pairs(float* dst, const float* src, int K,
                                             int tid, int nthreads) {
    int total = (K / 2) * 32;
    const float4* s4 = reinterpret_cast<const float4*>(src);
    u64* d = reinterpret_cast<u64*>(dst);
    for (int i = tid; i < total; i += nthreads) {
        int kp = i >> 5, n4 = i & 31;
        float4 r0 = s4[(2 * kp) * 32 + n4];
        float4 r1 = s4[(2 * kp + 1) * 32 + n4];
        u64* o = d + kp * 128 + n4 * 4;
        o[0] = pack2(r0.x, r1.x);
        o[1] = pack2(r0.y, r1.y);
        o[2] = pack2(r0.z, r1.z);
        o[3] = pack2(r0.w, r1.w);
    }
}

// ---------------- dtype detection + index canonicalization ------------------
__global__ void ol_detect_kernel(const int* __restrict__ ei32) {
    if (threadIdx.x == 0 && blockIdx.x == 0) {
        int any = 0;
#pragma unroll
        for (int i = 0; i < 64; i++) any |= ei32[2 * i + 1];
        g_is64 = (any == 0) ? 1 : 0;
    }
}

__global__ void ol_convert_kernel(const void* __restrict__ eiv) {
    int i = blockIdx.x * blockDim.x + threadIdx.x;
    if (i >= NEDGES) return;
    if (g_is64) {
        const long long* e = (const long long*)eiv;
        g_rows[i] = (int)e[i];
        g_cols[i] = (int)e[NEDGES + i];
    } else {
        const int* e = (const int*)eiv;
        g_rows[i] = e[i];
        g_cols[i] = e[NEDGES + i];
    }
}

// ---------------- zero vec accumulators ----------------
__global__ void ol_zero_kernel() {
    int i = blockIdx.x * blockDim.x + threadIdx.x;
    if (i < NNODES * 3) { g_vec1[i] = 0.0f; g_vec2[i] = 0.0f; }
}

// ---------------- node precompute (R4 GEMM + permuted store) ----------------
#define PRE_SMEM ((256 * 128 + 8 * 8 * 128) * 4)
__global__ void __launch_bounds__(256, 1)
ol_precompute_kernel(const float* __restrict__ h, const float* __restrict__ eW1) {
    extern __shared__ float smem[];
    float* Wab = smem;
    float* act = smem + 256 * 128;

    cpf4(Wab, eW1, 256 * 128, threadIdx.x, 256);
    __syncthreads();

    const int warp = threadIdx.x >> 5, lane = threadIdx.x & 31;
    float* myAct = act + warp * (8 * 128);
    float4* myAct4 = reinterpret_cast<float4*>(myAct);
    const int n0 = (blockIdx.x * 8 + warp) * 8;

#pragma unroll
    for (int e = 0; e < 8; e++) {
        int n = n0 + e;
        float4 v = make_float4(0.f, 0.f, 0.f, 0.f);
        if (n < NNODES) v = reinterpret_cast<const float4*>(h)[n * 32 + lane];
        myAct4[e * 32 + lane] = v;
    }
    __syncwarp();

    u64 accA0[8], accA1[8], accB0[8], accB1[8];
#pragma unroll
    for (int e = 0; e < 8; e++) {
        accA0[e] = 0ull; accA1[e] = 0ull; accB0[e] = 0ull; accB1[e] = 0ull;
    }
    const ulonglong2* Wab2 = reinterpret_cast<const ulonglong2*>(Wab);
    for (int kb = 0; kb < 32; kb++) {
        ulonglong2 wa0 = Wab2[(4 * kb + 0) * 32 + lane];
        ulonglong2 wa1 = Wab2[(4 * kb + 1) * 32 + lane];
        ulonglong2 wa2 = Wab2[(4 * kb + 2) * 32 + lane];
        ulonglong2 wa3 = Wab2[(4 * kb + 3) * 32 + lane];
        ulonglong2 wb0 = Wab2[(128 + 4 * kb + 0) * 32 + lane];
        ulonglong2 wb1 = Wab2[(128 + 4 * kb + 1) * 32 + lane];
        ulonglong2 wb2 = Wab2[(128 + 4 * kb + 2) * 32 + lane];
        ulonglong2 wb3 = Wab2[(128 + 4 * kb + 3) * 32 + lane];
#pragma unroll
        for (int e = 0; e < 8; e++) {
            float4 a = myAct4[e * 32 + kb];
            u64 dx = dup2(a.x), dy = dup2(a.y), dz = dup2(a.z), dw = dup2(a.w);
            fma2(accA0[e], dx, wa0.x); fma2(accA1[e], dx, wa0.y);
            fma2(accA0[e], dy, wa1.x); fma2(accA1[e], dy, wa1.y);
            fma2(accA0[e], dz, wa2.x); fma2(accA1[e], dz, wa2.y);
            fma2(accA0[e], dw, wa3.x); fma2(accA1[e], dw, wa3.y);
            fma2(accB0[e], dx, wb0.x); fma2(accB1[e], dx, wb0.y);
            fma2(accB0[e], dz, wb2.x); fma2(accB1[e], dz, wb2.y);
            fma2(accB0[e], dy, wb1.x); fma2(accB1[e], dy, wb1.y);
            fma2(accB0[e], dw, wb3.x); fma2(accB1[e], dw, wb3.y);
        }
    }
    __syncwarp();

    // ---- exchange to permuted layout via smem, Ha then Hb ----
    // dim d computed by this lane: d = 4*lane + j ; store at 4*(d&31) + (d>>5)
#pragma unroll
    for (int e = 0; e < 8; e++) {
        float2 a0 = unpack2(accA0[e]), a1 = unpack2(accA1[e]);
        int d = 4 * lane;
        myAct[e * 128 + 4 * ((d + 0) & 31) + ((d + 0) >> 5)] = a0.x;
        myAct[e * 128 + 4 * ((d + 1) & 31) + ((d + 1) >> 5)] = a0.y;
        myAct[e * 128 + 4 * ((d + 2) & 31) + ((d + 2) >> 5)] = a1.x;
        myAct[e * 128 + 4 * ((d + 3) & 31) + ((d + 3) >> 5)] = a1.y;
    }
    __syncwarp();
#pragma unroll
    for (int e = 0; e < 8; e++) {
        int n = n0 + e;
        if (n < NNODES)
            reinterpret_cast<float4*>(g_Ha)[n * 32 + lane] = myAct4[e * 32 + lane];
    }
    __syncwarp();
#pragma unroll
    for (int e = 0; e < 8; e++) {
        float2 b0 = unpack2(accB0[e]), b1 = unpack2(accB1[e]);
        int d = 4 * lane;
        myAct[e * 128 + 4 * ((d + 0) & 31) + ((d + 0) >> 5)] = b0.x;
        myAct[e * 128 + 4 * ((d + 1) & 31) + ((d + 1) >> 5)] = b0.y;
        myAct[e * 128 + 4 * ((d + 2) & 31) + ((d + 2) >> 5)] = b1.x;
        myAct[e * 128 + 4 * ((d + 3) & 31) + ((d + 3) >> 5)] = b1.y;
    }
    __syncwarp();
#pragma unroll
    for (int e = 0; e < 8; e++) {
        int n = n0 + e;
        if (n < NNODES)
            reinterpret_cast<float4*>(g_Hb)[n * 32 + lane] = myAct4[e * 32 + lane];
    }
}

// ---------------- fused edge kernel ----------------
// 128 threads = 4 warps, 8 edges/warp. Weights k-pair packed; lane owns output
// dims {lane, lane+32, lane+64, lane+96} -> conflict-free LDS.64 weight reads.
#define EDGE_SMEM ((2048 + 3 * 16384 + 6 * 128 + 4 * (1024 + 128 + 16)) * 4)

__global__ void __launch_bounds__(128, 1)
ol_edge_kernel(const float* __restrict__ x,
               const float* __restrict__ edge_attr,
               const float* __restrict__ eW1, const float* __restrict__ eb1,
               const float* __restrict__ eW2, const float* __restrict__ eb2,
               const float* __restrict__ v1W1, const float* __restrict__ v1b1,
               const float* __restrict__ v1W2, const float* __restrict__ v1b2,
               const float* __restrict__ v2W1, const float* __restrict__ v2b1,
               const float* __restrict__ v2W2, const float* __restrict__ v2b2) {
    extern __shared__ float smem[];
    float* sW1c  = smem;                    // packed u64 [8][128]
    float* sW2   = sW1c + 2048;             // packed u64 [64][128]
    float* sV1   = sW2 + 16384;
    float* sV2   = sV1 + 16384;
    float* sb1   = sV2 + 16384;
    float* sb2   = sb1 + 128;
    float* sv1b1 = sb2 + 128;
    float* sv2b1 = sv1b1 + 128;
    float* sv1w2 = sv2b1 + 128;
    float* sv2w2 = sv1w2 + 128;
    float* warpbuf = sv2w2 + 128;

    const int tid = threadIdx.x;
    repack_pairs(sW1c, eW1 + 256 * 128, 16, tid, 128);
    repack_pairs(sW2, eW2, 128, tid, 128);
    repack_pairs(sV1, v1W1, 128, tid, 128);
    repack_pairs(sV2, v2W1, 128, tid, 128);
    cpf4(sb1, eb1, 128, tid, 128);
    cpf4(sb2, eb2, 128, tid, 128);
    cpf4(sv1b1, v1b1, 128, tid, 128);
    cpf4(sv2b1, v2b1, 128, tid, 128);
    cpf4(sv1w2, v1W2, 128, tid, 128);
    cpf4(sv2w2, v2W2, 128, tid, 128);
    __syncthreads();

    const float c1 = __ldg(v1b2);
    const float c2 = __ldg(v2b2);

    const int warp = tid >> 5, lane = tid & 31;
    float* act = warpbuf + warp * 1168;           // 8 * 128
    float* ea  = act + 1024;                      // 8 * 16
    float* wsc = ea + 128;                        // 8 * 2
    float4* act4 = reinterpret_cast<float4*>(act);
    const ulonglong2* actU2 = reinterpret_cast<const ulonglong2*>(act);
    const ulonglong2* eaU2  = reinterpret_cast<const ulonglong2*>(ea);
    const u64* W1cp = reinterpret_cast<const u64*>(sW1c);
    const u64* W2p  = reinterpret_cast<const u64*>(sW2);
    const u64* V1p  = reinterpret_cast<const u64*>(sV1);
    const u64* V2p  = reinterpret_cast<const u64*>(sV2);

    // per-lane params at dims lane+32j
    float b1j[4], b2j[4], h1j[4], h2j[4], w2aj[4], w2bj[4];
#pragma unroll
    for (int j = 0; j < 4; j++) {
        b1j[j]  = sb1[lane + 32 * j];
        b2j[j]  = sb2[lane + 32 * j];
        h1j[j]  = sv1b1[lane + 32 * j];
        h2j[j]  = sv2b1[lane + 32 * j];
        w2aj[j] = sv1w2[lane + 32 * j];
        w2bj[j] = sv2w2[lane + 32 * j];
    }

    const int ntiles = NEDGES / 32;
    for (int tile = blockIdx.x; tile < ntiles; tile += gridDim.x) {
        const int e0 = tile * 32 + warp * 8;

        // ---- indices (lanes 0-7 rows, 8-15 cols), broadcast via shfl ----
        int my = 0;
        if (lane < 8)       my = g_rows[e0 + lane];
        else if (lane < 16) my = g_cols[e0 + (lane - 8)];
        const int idxv = my;
        int rows[8], cols[8];
#pragma unroll
        for (int e = 0; e < 8; e++) {
            rows[e] = __shfl_sync(0xffffffffu, idxv, e);
            cols[e] = __shfl_sync(0xffffffffu, idxv, 8 + e);
        }

        // ---- stage edge_attr (8*16 contiguous floats) ----
#pragma unroll
        for (int i = 0; i < 4; i++)
            ea[i * 32 + lane] = edge_attr[e0 * 16 + i * 32 + lane];
        __syncwarp();

        // ---- layer 1: z1 = Ha[row] + Hb[col] + ea@W1c + b1 ; y1 = silu ----
        {
            u64 acc[8][4];
#pragma unroll
            for (int e = 0; e < 8; e++) {
                float4 ga = reinterpret_cast<const float4*>(g_Ha)[rows[e] * 32 + lane];
                float4 gb = reinterpret_cast<const float4*>(g_Hb)[cols[e] * 32 + lane];
                acc[e][0] = pack2(ga.x + gb.x + b1j[0], 0.f);
                acc[e][1] = pack2(ga.y + gb.y + b1j[1], 0.f);
                acc[e][2] = pack2(ga.z + gb.z + b1j[2], 0.f);
                acc[e][3] = pack2(ga.w + gb.w + b1j[3], 0.f);
            }
#pragma unroll
            for (int t = 0; t < 4; t++) {
                const u64* w0 = W1cp + (2 * t) * 128 + lane;
                const u64* w1 = W1cp + (2 * t + 1) * 128 + lane;
                u64 wa0 = w0[0], wa1 = w0[32], wa2 = w0[64], wa3 = w0[96];
                u64 wb0 = w1[0], wb1 = w1[32], wb2 = w1[64], wb3 = w1[96];
#pragma unroll
                for (int e = 0; e < 8; e++) {
                    ulonglong2 av = eaU2[e * 4 + t];
                    fma2(acc[e][0], av.x, wa0); fma2(acc[e][0], av.y, wb0);
                    fma2(acc[e][1], av.x, wa1); fma2(acc[e][1], av.y, wb1);
                    fma2(acc[e][2], av.x, wa2); fma2(acc[e][2], av.y, wb2);
                    fma2(acc[e][3], av.x, wa3); fma2(acc[e][3], av.y, wb3);
                }
            }
#pragma unroll
            for (int e = 0; e < 8; e++)
#pragma unroll
                for (int j = 0; j < 4; j++) {
                    float2 f = unpack2(acc[e][j]);
                    act[e * 128 + lane + 32 * j] = siluf(f.x + f.y);
                }
        }
        __syncwarp();

        // ---- layer 2: ef = silu(y1 @ eW2 + b2) ----
        {
            u64 acc[8][4];
#pragma unroll
            for (int e = 0; e < 8; e++)
#pragma unroll
                for (int j = 0; j < 4; j++) acc[e][j] = pack2(b2j[j], 0.f);
            for (int t = 0; t < 32; t++) {
                const u64* w0 = W2p + (2 * t) * 128 + lane;
                const u64* w1 = W2p + (2 * t + 1) * 128 + lane;
                u64 wa0 = w0[0], wa1 = w0[32], wa2 = w0[64], wa3 = w0[96];
                u64 wb0 = w1[0], wb1 = w1[32], wb2 = w1[64], wb3 = w1[96];
#pragma unroll
                for (int e = 0; e < 8; e++) {
                    ulonglong2 av = actU2[e * 32 + t];
                    fma2(acc[e][0], av.x, wa0); fma2(acc[e][0], av.y, wb0);
                    fma2(acc[e][1], av.x, wa1); fma2(acc[e][1], av.y, wb1);
                    fma2(acc[e][2], av.x, wa2); fma2(acc[e][2], av.y, wb2);
                    fma2(acc[e][3], av.x, wa3); fma2(acc[e][3], av.y, wb3);
                }
            }
            __syncwarp();   // all lanes done reading y1
#pragma unroll
            for (int e = 0; e < 8; e++)
#pragma unroll
                for (int j = 0; j < 4; j++) {
                    float2 f = unpack2(acc[e][j]);
                    act[e * 128 + lane + 32 * j] = siluf(f.x + f.y);
                }
        }
        __syncwarp();

        // ---- head 1: w1 = silu(ef@v1W1+v1b1) . v1W2 + v1b2 ----
        {
            u64 acc[8][4];
#pragma unroll
            for (int e = 0; e < 8; e++)
#pragma unroll
                for (int j = 0; j < 4; j++) acc[e][j] = pack2(h1j[j], 0.f);
            for (int t = 0; t < 32; t++) {
                const u64* w0 = V1p + (2 * t) * 128 + lane;
                const u64* w1 = V1p + (2 * t + 1) * 128 + lane;
                u64 wa0 = w0[0], wa1 = w0[32], wa2 = w0[64], wa3 = w0[96];
                u64 wb0 = w1[0], wb1 = w1[32], wb2 = w1[64], wb3 = w1[96];
#pragma unroll
                for (int e = 0; e < 8; e++) {
                    ulonglong2 av = actU2[e * 32 + t];
                    fma2(acc[e][0], av.x, wa0); fma2(acc[e][0], av.y, wb0);
                    fma2(acc[e][1], av.x, wa1); fma2(acc[e][1], av.y, wb1);
                    fma2(acc[e][2], av.x, wa2); fma2(acc[e][2], av.y, wb2);
                    fma2(acc[e][3], av.x, wa3); fma2(acc[e][3], av.y, wb3);
                }
            }
#pragma unroll
            for (int e = 0; e < 8; e++) {
                float2 f0 = unpack2(acc[e][0]), f1 = unpack2(acc[e][1]);
                float2 f2 = unpack2(acc[e][2]), f3 = unpack2(acc[e][3]);
                float p = siluf(f0.x + f0.y) * w2aj[0] + siluf(f1.x + f1.y) * w2aj[1]
                        + siluf(f2.x + f2.y) * w2aj[2] + siluf(f3.x + f3.y) * w2aj[3];
#pragma unroll
                for (int off = 16; off; off >>= 1)
                    p += __shfl_xor_sync(0xffffffffu, p, off);
                if (lane == 0) wsc[2 * e] = p + c1;
            }
        }
        // ---- head 2 ----
        {
            u64 acc[8][4];
#pragma unroll
            for (int e = 0; e < 8; e++)
#pragma unroll
                for (int j = 0; j < 4; j++) acc[e][j] = pack2(h2j[j], 0.f);
            for (int t = 0; t < 32; t++) {
                const u64* w0 = V2p + (2 * t) * 128 + lane;
                const u64* w1 = V2p + (2 * t + 1) * 128 + lane;
                u64 wa0 = w0[0], wa1 = w0[32], wa2 = w0[64], wa3 = w0[96];
                u64 wb0 = w1[0], wb1 = w1[32], wb2 = w1[64], wb3 = w1[96];
#pragma unroll
                for (int e = 0; e < 8; e++) {
                    ulonglong2 av = actU2[e * 32 + t];
                    fma2(acc[e][0], av.x, wa0); fma2(acc[e][0], av.y, wb0);
                    fma2(acc[e][1], av.x, wa1); fma2(acc[e][1], av.y, wb1);
                    fma2(acc[e][2], av.x, wa2); fma2(acc[e][2], av.y, wb2);
                    fma2(acc[e][3], av.x, wa3); fma2(acc[e][3], av.y, wb3);
                }
            }
#pragma unroll
            for (int e = 0; e < 8; e++) {
                float2 f0 = unpack2(acc[e][0]), f1 = unpack2(acc[e][1]);
                float2 f2 = unpack2(acc[e][2]), f3 = unpack2(acc[e][3]);
                float q = siluf(f0.x + f0.y) * w2bj[0] + siluf(f1.x + f1.y) * w2bj[1]
                        + siluf(f2.x + f2.y) * w2bj[2] + siluf(f3.x + f3.y) * w2bj[3];
#pragma unroll
                for (int off = 16; off; off >>= 1)
                    q += __shfl_xor_sync(0xffffffffu, q, off);
                if (lane == 0) wsc[2 * e + 1] = q + c2;
            }
        }
        __syncwarp();

        // ---- scatter: lanes 0..23 -> (edge e = lane/3, component d = lane%3)
        {
            int e = lane / 3;
            int d = lane - 3 * e;
            int r = __shfl_sync(0xffffffffu, idxv, (e < 8) ? e : 0);
            int c = __shfl_sync(0xffffffffu, idxv, (e < 8) ? (8 + e) : 8);
            if (lane < 24) {
                float rp = x[c * 3 + d] - x[r * 3 + d];
                atomicAdd(&g_vec1[r * 3 + d], rp * wsc[2 * e]);
                atomicAdd(&g_vec2[r * 3 + d], rp * wsc[2 * e + 1]);
            }
        }
        __syncwarp();
    }
}

// ---------------- finalize: Gram-Schmidt per node ----------------
__global__ void ol_finalize_kernel(float* __restrict__ out) {
    int n = blockIdx.x * blockDim.x + threadIdx.x;
    if (n >= NNODES) return;
    float v1x = g_vec1[n * 3 + 0], v1y = g_vec1[n * 3 + 1], v1z = g_vec1[n * 3 + 2];
    float v2x = g_vec2[n * 3 + 0], v2y = g_vec2[n * 3 + 1], v2z = g_vec2[n * 3 + 2];

    float n1 = fmaxf(sqrtf(v1x * v1x + v1y * v1y + v1z * v1z), 1e-12f);
    float e1x = v1x / n1, e1y = v1y / n1, e1z = v1z / n1;

    float dp = e1x * v2x + e1y * v2y + e1z * v2z;
    float px = v2x - dp * e1x, py = v2y - dp * e1y, pz = v2z - dp * e1z;
    float n2 = fmaxf(sqrtf(px * px + py * py + pz * pz), 1e-12f);
    float e2x = px / n2, e2y = py / n2, e2z = pz / n2;

    float e3x = e1y * e2z - e1z * e2y;
    float e3y = e1z * e2x - e1x * e2z;
    float e3z = e1x * e2y - e1y * e2x;

    float* o = out + n * 9;     // out[n, i, j] = (e_j)[i]
    o[0] = e1x; o[1] = e2x; o[2] = e3x;
    o[3] = e1y; o[4] = e2y; o[5] = e3y;
    o[6] = e1z; o[7] = e2z; o[8] = e3z;
}

// ---------------- launch ----------------
extern "C" void kernel_launch(void* const* d_in, const int* in_sizes, int n_in,
                              void* d_out, int out_size) {
    const float* h         = (const float*)d_in[0];
    const float* x         = (const float*)d_in[1];
    const void*  ei        = d_in[2];
    const float* edge_attr = (const float*)d_in[3];
    const float* eW1 = (const float*)d_in[4];  const float* eb1 = (const float*)d_in[5];
    const float* eW2 = (const float*)d_in[6];  const float* eb2 = (const float*)d_in[7];
    const float* v1W1 = (const float*)d_in[8]; const float* v1b1 = (const float*)d_in[9];
    const float* v1W2 = (const float*)d_in[10]; const float* v1b2 = (const float*)d_in[11];
    const float* v2W1 = (const float*)d_in[12]; const float* v2b1 = (const float*)d_in[13];
    const float* v2W2 = (const float*)d_in[14]; const float* v2b2 = (const float*)d_in[15];
    float* out = (float*)d_out;

    cudaFuncSetAttribute(ol_precompute_kernel,
                         cudaFuncAttributeMaxDynamicSharedMemorySize, PRE_SMEM);
    cudaFuncSetAttribute(ol_edge_kernel,
                         cudaFuncAttributeMaxDynamicSharedMemorySize, EDGE_SMEM);

    ol_detect_kernel<<<1, 32>>>((const int*)ei);
    ol_convert_kernel<<<(NEDGES + 255) / 256, 256>>>(ei);
    ol_zero_kernel<<<(NNODES * 3 + 255) / 256, 256>>>();
    ol_precompute_kernel<<<(NNODES + 63) / 64, 256, PRE_SMEM>>>(h, eW1);
    ol_edge_kernel<<<148, 128, EDGE_SMEM>>>(x, edge_attr,
                                            eW1, eb1, eW2, eb2,
                                            v1W1, v1b1, v1W2, v1b2,
                                            v2W1, v2b1, v2W2, v2b2);
    ol_finalize_kernel<<<(NNODES + 255) / 256, 256>>>(out);
}

// round 9
// speedup vs baseline: 2.6965x; 2.0414x over previous
#include <cuda_runtime.h>
#include <cuda_bf16.h>
#include <math.h>

#define NNODES 50000
#define NEDGES 800000
#define HID    128
#define FE     16

typedef unsigned long long u64;
typedef unsigned int u32;

// ---------------- scratch ----------------
__device__ float g_Ha[NNODES * HID];
__device__ float g_Hb[NNODES * HID];
__device__ float g_vec1[NNODES * 3];
__device__ float g_vec2[NNODES * 3];
__device__ int   g_rows[NEDGES];
__device__ int   g_cols[NEDGES];
__device__ int   g_is64;

// ---------------- helpers ----------------
__device__ __forceinline__ u64 dup2(float s) {
    u64 r; asm("mov.b64 %0, {%1, %1};" : "=l"(r) : "f"(s)); return r;
}
__device__ __forceinline__ void fma2(u64& c, u64 a, u64 b) {
    asm("fma.rn.f32x2 %0, %1, %2, %3;" : "=l"(c) : "l"(a), "l"(b), "l"(c));
}
__device__ __forceinline__ float siluf(float v) {
    return __fdividef(v, 1.0f + __expf(-v));
}
__device__ __forceinline__ void cpf4(float* dst, const float* src, int nfloats,
                                     int tid, int nthreads) {
    const float4* s = reinterpret_cast<const float4*>(src);
    float4* d = reinterpret_cast<float4*>(dst);
    for (int i = tid; i < nfloats / 4; i += nthreads) d[i] = s[i];
}

// pack {even,odd} floats into one bf16x2 (even in low half)
__device__ __forceinline__ u32 packbf(float ev, float od) {
    u32 r; asm("cvt.rn.bf16x2.f32 %0, %1, %2;" : "=r"(r) : "f"(od), "f"(ev)); return r;
}
__device__ __forceinline__ float bres(float v) {
    __nv_bfloat16 b = __float2bfloat16(v);
    return v - __bfloat162float(b);
}
__device__ __forceinline__ void packsplit(float ev, float od, u32& hi, u32& lo) {
    hi = packbf(ev, od);
    lo = packbf(bres(ev), bres(od));
}

// bf16 warp MMA: D(16x8,f32) += A(16x16) * B(16x8)
__device__ __forceinline__ void mma_bf16(float* c, const u32* a, u32 b0, u32 b1) {
    asm volatile(
        "mma.sync.aligned.m16n8k16.row.col.f32.bf16.bf16.f32 "
        "{%0,%1,%2,%3}, {%4,%5,%6,%7}, {%8,%9}, {%0,%1,%2,%3};"
        : "+f"(c[0]), "+f"(c[1]), "+f"(c[2]), "+f"(c[3])
        : "r"(a[0]), "r"(a[1]), "r"(a[2]), "r"(a[3]), "r"(b0), "r"(b1));
}

// ---------------- dtype detection + index canonicalization ------------------
__global__ void ol_detect_kernel(const int* __restrict__ ei32) {
    if (threadIdx.x == 0 && blockIdx.x == 0) {
        int any = 0;
#pragma unroll
        for (int i = 0; i < 64; i++) any |= ei32[2 * i + 1];
        g_is64 = (any == 0) ? 1 : 0;
    }
}
__global__ void ol_convert_kernel(const void* __restrict__ eiv) {
    int i = blockIdx.x * blockDim.x + threadIdx.x;
    if (i >= NEDGES) return;
    if (g_is64) {
        const long long* e = (const long long*)eiv;
        g_rows[i] = (int)e[i];
        g_cols[i] = (int)e[NEDGES + i];
    } else {
        const int* e = (const int*)eiv;
        g_rows[i] = e[i];
        g_cols[i] = e[NEDGES + i];
    }
}
__global__ void ol_zero_kernel() {
    int i = blockIdx.x * blockDim.x + threadIdx.x;
    if (i < NNODES * 3) { g_vec1[i] = 0.0f; g_vec2[i] = 0.0f; }
}

// ---------------- node precompute (R4 version, known-good ~96us) ------------
#define PRE_SMEM ((256 * 128 + 8 * 8 * 128) * 4)
__global__ void __launch_bounds__(256, 1)
ol_precompute_kernel(const float* __restrict__ h, const float* __restrict__ eW1) {
    extern __shared__ float smem[];
    float* Wab = smem;
    float* act = smem + 256 * 128;

    cpf4(Wab, eW1, 256 * 128, threadIdx.x, 256);
    __syncthreads();

    const int warp = threadIdx.x >> 5, lane = threadIdx.x & 31;
    float* myAct = act + warp * (8 * 128);
    float4* myAct4 = reinterpret_cast<float4*>(myAct);
    const int n0 = (blockIdx.x * 8 + warp) * 8;

#pragma unroll
    for (int e = 0; e < 8; e++) {
        int n = n0 + e;
        float4 v = make_float4(0.f, 0.f, 0.f, 0.f);
        if (n < NNODES) v = reinterpret_cast<const float4*>(h)[n * 32 + lane];
        myAct4[e * 32 + lane] = v;
    }
    __syncwarp();

    u64 accA0[8], accA1[8], accB0[8], accB1[8];
#pragma unroll
    for (int e = 0; e < 8; e++) {
        accA0[e] = 0ull; accA1[e] = 0ull; accB0[e] = 0ull; accB1[e] = 0ull;
    }
    const ulonglong2* Wab2 = reinterpret_cast<const ulonglong2*>(Wab);
    for (int kb = 0; kb < 32; kb++) {
        ulonglong2 wa0 = Wab2[(4 * kb + 0) * 32 + lane];
        ulonglong2 wa1 = Wab2[(4 * kb + 1) * 32 + lane];
        ulonglong2 wa2 = Wab2[(4 * kb + 2) * 32 + lane];
        ulonglong2 wa3 = Wab2[(4 * kb + 3) * 32 + lane];
        ulonglong2 wb0 = Wab2[(128 + 4 * kb + 0) * 32 + lane];
        ulonglong2 wb1 = Wab2[(128 + 4 * kb + 1) * 32 + lane];
        ulonglong2 wb2 = Wab2[(128 + 4 * kb + 2) * 32 + lane];
        ulonglong2 wb3 = Wab2[(128 + 4 * kb + 3) * 32 + lane];
#pragma unroll
        for (int e = 0; e < 8; e++) {
            float4 a = myAct4[e * 32 + kb];
            u64 dx = dup2(a.x), dy = dup2(a.y), dz = dup2(a.z), dw = dup2(a.w);
            fma2(accA0[e], dx, wa0.x); fma2(accA1[e], dx, wa0.y);
            fma2(accA0[e], dy, wa1.x); fma2(accA1[e], dy, wa1.y);
            fma2(accA0[e], dz, wa2.x); fma2(accA1[e], dz, wa2.y);
            fma2(accA0[e], dw, wa3.x); fma2(accA1[e], dw, wa3.y);
            fma2(accB0[e], dx, wb0.x); fma2(accB1[e], dx, wb0.y);
            fma2(accB0[e], dy, wb1.x); fma2(accB1[e], dy, wb1.y);
            fma2(accB0[e], dz, wb2.x); fma2(accB1[e], dz, wb2.y);
            fma2(accB0[e], dw, wb3.x); fma2(accB1[e], dw, wb3.y);
        }
    }
#pragma unroll
    for (int e = 0; e < 8; e++) {
        int n = n0 + e;
        if (n < NNODES) {
            reinterpret_cast<ulonglong2*>(g_Ha)[n * 32 + lane] =
                make_ulonglong2(accA0[e], accA1[e]);
            reinterpret_cast<ulonglong2*>(g_Hb)[n * 32 + lane] =
                make_ulonglong2(accB0[e], accB1[e]);
        }
    }
}

// ---------------- fragment prepack helpers ----------------
// B-fragment order for m16n8k16: frag(kt,nt)[lane] = 2 u32:
//   u32#0 = {W[k0][n], W[k0+1][n]}, u32#1 = {W[k0+8][n], W[k0+9][n]}
//   n = nt*8 + (lane>>2), k0 = kt*16 + (lane&3)*2
__device__ void pack_wfrag(u32* Bh, u32* Bl, const float* __restrict__ W, int tid) {
    for (int idx = tid; idx < 4096; idx += 128) {
        int kt = idx >> 9, nt = (idx >> 5) & 15, l = idx & 31;
        int n = nt * 8 + (l >> 2), k0 = kt * 16 + (l & 3) * 2;
        float w00 = W[k0 * 128 + n],      w01 = W[(k0 + 1) * 128 + n];
        float w10 = W[(k0 + 8) * 128 + n], w11 = W[(k0 + 9) * 128 + n];
        u32 h0, l0, h1, l1;
        packsplit(w00, w01, h0, l0);
        packsplit(w10, w11, h1, l1);
        Bh[idx * 2] = h0; Bh[idx * 2 + 1] = h1;
        Bl[idx * 2] = l0; Bl[idx * 2 + 1] = l1;
    }
}
// W1c: 16 x 128, single ktile
__device__ void pack_w1c(u32* Bh, u32* Bl, const float* __restrict__ W, int tid) {
    for (int idx = tid; idx < 512; idx += 128) {
        int nt = idx >> 5, l = idx & 31;
        int n = nt * 8 + (l >> 2), k0 = (l & 3) * 2;
        float w00 = W[k0 * 128 + n],      w01 = W[(k0 + 1) * 128 + n];
        float w10 = W[(k0 + 8) * 128 + n], w11 = W[(k0 + 9) * 128 + n];
        u32 h0, l0, h1, l1;
        packsplit(w00, w01, h0, l0);
        packsplit(w10, w11, h1, l1);
        Bh[idx * 2] = h0; Bh[idx * 2 + 1] = h1;
        Bl[idx * 2] = l0; Bl[idx * 2 + 1] = l1;
    }
}

// one full 128-k layer: C[2 mtiles][4 ntiles][4] += act @ W (3-term split)
__device__ __forceinline__ void gemm_layer(float C[2][4][4],
                                           const u32* __restrict__ actH,
                                           const u32* __restrict__ actL,
                                           const u32* __restrict__ Bh,
                                           const u32* __restrict__ Bl,
                                           int w, int lane) {
#pragma unroll
    for (int kt = 0; kt < 8; kt++) {
        uint4 h0 = *(const uint4*)(actH + (kt * 32 + lane) * 4);
        uint4 l0 = *(const uint4*)(actL + (kt * 32 + lane) * 4);
        uint4 h1 = *(const uint4*)(actH + ((8 + kt) * 32 + lane) * 4);
        uint4 l1 = *(const uint4*)(actL + ((8 + kt) * 32 + lane) * 4);
        u32 AH0[4] = {h0.x, h0.y, h0.z, h0.w}, AL0[4] = {l0.x, l0.y, l0.z, l0.w};
        u32 AH1[4] = {h1.x, h1.y, h1.z, h1.w}, AL1[4] = {l1.x, l1.y, l1.z, l1.w};
#pragma unroll
        for (int i = 0; i < 4; i++) {
            int fo = ((kt * 16 + (w * 4 + i)) * 32 + lane) * 2;
            u32 bh0 = Bh[fo], bh1 = Bh[fo + 1];
            u32 bl0 = Bl[fo], bl1 = Bl[fo + 1];
            mma_bf16(C[0][i], AH0, bh0, bh1);
            mma_bf16(C[0][i], AL0, bh0, bh1);
            mma_bf16(C[0][i], AH0, bl0, bl1);
            mma_bf16(C[1][i], AH1, bh0, bh1);
            mma_bf16(C[1][i], AL1, bh0, bh1);
            mma_bf16(C[1][i], AH1, bl0, bl1);
        }
    }
}

// ---------------- tensor-core edge kernel ----------------
#define EDGE_SMEM 227584
#define NT_EDGE  (NEDGES / 32)

__global__ void __launch_bounds__(128, 1)
ol_edge_kernel(const float* __restrict__ x,
               const float* __restrict__ edge_attr,
               const float* __restrict__ eW1, const float* __restrict__ eb1,
               const float* __restrict__ eW2, const float* __restrict__ eb2,
               const float* __restrict__ v1W1, const float* __restrict__ v1b1,
               const float* __restrict__ v1W2, const float* __restrict__ v1b2,
               const float* __restrict__ v2W1, const float* __restrict__ v2b1,
               const float* __restrict__ v2W2, const float* __restrict__ v2b2) {
    extern __shared__ float smem[];
    u32* su = (u32*)smem;

    float* sb1   = smem + 0;
    float* sb2   = smem + 128;
    float* sv1b1 = smem + 256;
    float* sv2b1 = smem + 384;
    float* sv1w2 = smem + 512;
    float* sv2w2 = smem + 640;
    float* wsc   = smem + 768;   // 64
    float* red1  = smem + 832;   // 128
    float* red2  = smem + 960;   // 128
    u32* A1h  = su + 1088;       // 2*32*4
    u32* A1l  = su + 1344;
    u32* W1cH = su + 1600;       // 16*32*2
    u32* W1cL = su + 2624;
    u32* actH = su + 3648;       // 16*32*4
    u32* actL = su + 5696;
    u32* W2h  = su + 7744;       // 8*16*32*2
    u32* W2l  = su + 15936;
    u32* V1h  = su + 24128;
    u32* V1l  = su + 32320;
    u32* V2h  = su + 40512;
    u32* V2l  = su + 48704;

    const int tid = threadIdx.x;
    const int w = tid >> 5, lane = tid & 31;

    cpf4(sb1, eb1, 128, tid, 128);
    cpf4(sb2, eb2, 128, tid, 128);
    cpf4(sv1b1, v1b1, 128, tid, 128);
    cpf4(sv2b1, v2b1, 128, tid, 128);
    cpf4(sv1w2, v1W2, 128, tid, 128);
    cpf4(sv2w2, v2W2, 128, tid, 128);
    pack_w1c(W1cH, W1cL, eW1 + 256 * 128, tid);
    pack_wfrag(W2h, W2l, eW2, tid);
    pack_wfrag(V1h, V1l, v1W1, tid);
    pack_wfrag(V2h, V2l, v2W1, tid);
    __syncthreads();

    const float c1 = __ldg(v1b2);
    const float c2 = __ldg(v2b2);

    for (int t = blockIdx.x; t < NT_EDGE; t += 148) {
        const int tbase = t * 32;

        // ---- build A1 fragments (edge_attr, split bf16): threads 0..63 ----
        if (tid < 64) {
            int m = tid >> 5, l = tid & 31;
            int r = l >> 2, k0 = (l & 3) * 2;
            const float* ep0 = edge_attr + (size_t)(tbase + m * 16 + r) * 16;
            const float* ep1 = edge_attr + (size_t)(tbase + m * 16 + r + 8) * 16;
            float2 p0 = *(const float2*)(ep0 + k0);
            float2 p1 = *(const float2*)(ep1 + k0);
            float2 p2 = *(const float2*)(ep0 + k0 + 8);
            float2 p3 = *(const float2*)(ep1 + k0 + 8);
            int o = (m * 32 + l) * 4;
            u32 hh, ll;
            packsplit(p0.x, p0.y, hh, ll); A1h[o] = hh;     A1l[o] = ll;
            packsplit(p1.x, p1.y, hh, ll); A1h[o + 1] = hh; A1l[o + 1] = ll;
            packsplit(p2.x, p2.y, hh, ll); A1h[o + 2] = hh; A1l[o + 2] = ll;
            packsplit(p3.x, p3.y, hh, ll); A1h[o + 3] = hh; A1l[o + 3] = ll;
        }

        // ---- layer1 C init: Ha[row]+Hb[col]+b1 at fragment coords ----
        float C[2][4][4];
#pragma unroll
        for (int m = 0; m < 2; m++) {
            int e0 = tbase + m * 16 + (lane >> 2);
            int e1 = e0 + 8;
            int rA = g_rows[e0], cA = g_cols[e0];
            int rB = g_rows[e1], cB = g_cols[e1];
#pragma unroll
            for (int i = 0; i < 4; i++) {
                int n0 = (w * 4 + i) * 8 + 2 * (lane & 3);
                float2 a0 = *(const float2*)(g_Ha + (size_t)rA * 128 + n0);
                float2 b0 = *(const float2*)(g_Hb + (size_t)cA * 128 + n0);
                float2 a1 = *(const float2*)(g_Ha + (size_t)rB * 128 + n0);
                float2 b1 = *(const float2*)(g_Hb + (size_t)cB * 128 + n0);
                float2 bb = *(const float2*)(sb1 + n0);
                C[m][i][0] = a0.x + b0.x + bb.x;
                C[m][i][1] = a0.y + b0.y + bb.y;
                C[m][i][2] = a1.x + b1.x + bb.x;
                C[m][i][3] = a1.y + b1.y + bb.y;
            }
        }
        __syncthreads();   // A1 visible; prev-tile act reads long done

        // ---- layer1 MMA: += ea @ W1c (k=16) ----
        {
            uint4 h0 = *(const uint4*)(A1h + lane * 4);
            uint4 l0 = *(const uint4*)(A1l + lane * 4);
            uint4 h1 = *(const uint4*)(A1h + (32 + lane) * 4);
            uint4 l1 = *(const uint4*)(A1l + (32 + lane) * 4);
            u32 AH0[4] = {h0.x, h0.y, h0.z, h0.w}, AL0[4] = {l0.x, l0.y, l0.z, l0.w};
            u32 AH1[4] = {h1.x, h1.y, h1.z, h1.w}, AL1[4] = {l1.x, l1.y, l1.z, l1.w};
#pragma unroll
            for (int i = 0; i < 4; i++) {
                int fo = ((w * 4 + i) * 32 + lane) * 2;
                u32 bh0 = W1cH[fo], bh1 = W1cH[fo + 1];
                u32 bl0 = W1cL[fo], bl1 = W1cL[fo + 1];
                mma_bf16(C[0][i], AH0, bh0, bh1);
                mma_bf16(C[0][i], AL0, bh0, bh1);
                mma_bf16(C[0][i], AH0, bl0, bl1);
                mma_bf16(C[1][i], AH1, bh0, bh1);
                mma_bf16(C[1][i], AL1, bh0, bh1);
                mma_bf16(C[1][i], AH1, bl0, bl1);
            }
        }
        // silu + repack to act fragments (lane-preserving)
#pragma unroll
        for (int m = 0; m < 2; m++)
#pragma unroll
            for (int i = 0; i < 4; i++) {
                int g = w * 4 + i;
                int base = ((m * 8 + (g >> 1)) * 32 + lane) * 4 + (g & 1) * 2;
                u32 hh, ll;
                packsplit(siluf(C[m][i][0]), siluf(C[m][i][1]), hh, ll);
                actH[base] = hh; actL[base] = ll;
                packsplit(siluf(C[m][i][2]), siluf(C[m][i][3]), hh, ll);
                actH[base + 1] = hh; actL[base + 1] = ll;
            }
        __syncthreads();   // y1 fragments ready

        // ---- layer2: ef = silu(y1 @ eW2 + b2) ----
#pragma unroll
        for (int m = 0; m < 2; m++)
#pragma unroll
            for (int i = 0; i < 4; i++)
#pragma unroll
                for (int j = 0; j < 4; j++) C[m][i][j] = 0.f;
        gemm_layer(C, actH, actL, W2h, W2l, w, lane);
        __syncthreads();   // all reads of y1 done before overwrite
#pragma unroll
        for (int m = 0; m < 2; m++)
#pragma unroll
            for (int i = 0; i < 4; i++) {
                int g = w * 4 + i;
                int n0 = g * 8 + 2 * (lane & 3);
                float2 bb = *(const float2*)(sb2 + n0);
                int base = ((m * 8 + (g >> 1)) * 32 + lane) * 4 + (g & 1) * 2;
                u32 hh, ll;
                packsplit(siluf(C[m][i][0] + bb.x), siluf(C[m][i][1] + bb.y), hh, ll);
                actH[base] = hh; actL[base] = ll;
                packsplit(siluf(C[m][i][2] + bb.x), siluf(C[m][i][3] + bb.y), hh, ll);
                actH[base + 1] = hh; actL[base + 1] = ll;
            }
        __syncthreads();   // ef fragments ready

        // ---- head 1 ----
        {
#pragma unroll
            for (int m = 0; m < 2; m++)
#pragma unroll
                for (int i = 0; i < 4; i++)
#pragma unroll
                    for (int j = 0; j < 4; j++) C[m][i][j] = 0.f;
            gemm_layer(C, actH, actL, V1h, V1l, w, lane);
            float part[4] = {0.f, 0.f, 0.f, 0.f};
#pragma unroll
            for (int m = 0; m < 2; m++)
#pragma unroll
                for (int i = 0; i < 4; i++) {
                    int n0 = (w * 4 + i) * 8 + 2 * (lane & 3);
                    float2 bb = *(const float2*)(sv1b1 + n0);
                    float2 ww = *(const float2*)(sv1w2 + n0);
                    part[m * 2 + 0] += siluf(C[m][i][0] + bb.x) * ww.x
                                     + siluf(C[m][i][1] + bb.y) * ww.y;
                    part[m * 2 + 1] += siluf(C[m][i][2] + bb.x) * ww.x
                                     + siluf(C[m][i][3] + bb.y) * ww.y;
                }
#pragma unroll
            for (int j = 0; j < 4; j++) {
                part[j] += __shfl_xor_sync(0xffffffffu, part[j], 1);
                part[j] += __shfl_xor_sync(0xffffffffu, part[j], 2);
            }
            if ((lane & 3) == 0) {
                int r = lane >> 2;
                red1[w * 32 + r]      = part[0];
                red1[w * 32 + r + 8]  = part[1];
                red1[w * 32 + 16 + r]     = part[2];
                red1[w * 32 + 16 + r + 8] = part[3];
            }
        }
        // ---- head 2 ----
        {
#pragma unroll
            for (int m = 0; m < 2; m++)
#pragma unroll
                for (int i = 0; i < 4; i++)
#pragma unroll
                    for (int j = 0; j < 4; j++) C[m][i][j] = 0.f;
            gemm_layer(C, actH, actL, V2h, V2l, w, lane);
            float part[4] = {0.f, 0.f, 0.f, 0.f};
#pragma unroll
            for (int m = 0; m < 2; m++)
#pragma unroll
                for (int i = 0; i < 4; i++) {
                    int n0 = (w * 4 + i) * 8 + 2 * (lane & 3);
                    float2 bb = *(const float2*)(sv2b1 + n0);
                    float2 ww = *(const float2*)(sv2w2 + n0);
                    part[m * 2 + 0] += siluf(C[m][i][0] + bb.x) * ww.x
                                     + siluf(C[m][i][1] + bb.y) * ww.y;
                    part[m * 2 + 1] += siluf(C[m][i][2] + bb.x) * ww.x
                                     + siluf(C[m][i][3] + bb.y) * ww.y;
                }
#pragma unroll
            for (int j = 0; j < 4; j++) {
                part[j] += __shfl_xor_sync(0xffffffffu, part[j], 1);
                part[j] += __shfl_xor_sync(0xffffffffu, part[j], 2);
            }
            if ((lane & 3) == 0) {
                int r = lane >> 2;
                red2[w * 32 + r]      = part[0];
                red2[w * 32 + r + 8]  = part[1];
                red2[w * 32 + 16 + r]     = part[2];
                red2[w * 32 + 16 + r + 8] = part[3];
            }
        }
        __syncthreads();

        // ---- combine partials ----
        if (tid < 32) {
            float s1 = red1[tid] + red1[32 + tid] + red1[64 + tid] + red1[96 + tid];
            float s2 = red2[tid] + red2[32 + tid] + red2[64 + tid] + red2[96 + tid];
            wsc[2 * tid] = s1 + c1;
            wsc[2 * tid + 1] = s2 + c2;
        }
        __syncthreads();

        // ---- scatter: threads 0..95 -> (edge e = tid/3, comp d = tid%3) ----
        if (tid < 96) {
            int e = tid / 3, d = tid - 3 * e;
            int eg = tbase + e;
            int row = g_rows[eg], col = g_cols[eg];
            float rp = x[col * 3 + d] - x[row * 3 + d];
            atomicAdd(&g_vec1[row * 3 + d], rp * wsc[2 * e]);
            atomicAdd(&g_vec2[row * 3 + d], rp * wsc[2 * e + 1]);
        }
    }
}

// ---------------- finalize: Gram-Schmidt per node ----------------
__global__ void ol_finalize_kernel(float* __restrict__ out) {
    int n = blockIdx.x * blockDim.x + threadIdx.x;
    if (n >= NNODES) return;
    float v1x = g_vec1[n * 3 + 0], v1y = g_vec1[n * 3 + 1], v1z = g_vec1[n * 3 + 2];
    float v2x = g_vec2[n * 3 + 0], v2y = g_vec2[n * 3 + 1], v2z = g_vec2[n * 3 + 2];

    float n1 = fmaxf(sqrtf(v1x * v1x + v1y * v1y + v1z * v1z), 1e-12f);
    float e1x = v1x / n1, e1y = v1y / n1, e1z = v1z / n1;

    float dp = e1x * v2x + e1y * v2y + e1z * v2z;
    float px = v2x - dp * e1x, py = v2y - dp * e1y, pz = v2z - dp * e1z;
    float n2 = fmaxf(sqrtf(px * px + py * py + pz * pz), 1e-12f);
    float e2x = px / n2, e2y = py / n2, e2z = pz / n2;

    float e3x = e1y * e2z - e1z * e2y;
    float e3y = e1z * e2x - e1x * e2z;
    float e3z = e1x * e2y - e1y * e2x;

    float* o = out + n * 9;
    o[0] = e1x; o[1] = e2x; o[2] = e3x;
    o[3] = e1y; o[4] = e2y; o[5] = e3y;
    o[6] = e1z; o[7] = e2z; o[8] = e3z;
}

// ---------------- launch ----------------
extern "C" void kernel_launch(void* const* d_in, const int* in_sizes, int n_in,
                              void* d_out, int out_size) {
    const float* h         = (const float*)d_in[0];
    const float* x         = (const float*)d_in[1];
    const void*  ei        = d_in[2];
    const float* edge_attr = (const float*)d_in[3];
    const float* eW1 = (const float*)d_in[4];  const float* eb1 = (const float*)d_in[5];
    const float* eW2 = (const float*)d_in[6];  const float* eb2 = (const float*)d_in[7];
    const float* v1W1 = (const float*)d_in[8]; const float* v1b1 = (const float*)d_in[9];
    const float* v1W2 = (const float*)d_in[10]; const float* v1b2 = (const float*)d_in[11];
    const float* v2W1 = (const float*)d_in[12]; const float* v2b1 = (const float*)d_in[13];
    const float* v2W2 = (const float*)d_in[14]; const float* v2b2 = (const float*)d_in[15];
    float* out = (float*)d_out;

    cudaFuncSetAttribute(ol_precompute_kernel,
                         cudaFuncAttributeMaxDynamicSharedMemorySize, PRE_SMEM);
    cudaFuncSetAttribute(ol_edge_kernel,
                         cudaFuncAttributeMaxDynamicSharedMemorySize, EDGE_SMEM);

    ol_detect_kernel<<<1, 32>>>((const int*)ei);
    ol_convert_kernel<<<(NEDGES + 255) / 256, 256>>>(ei);
    ol_zero_kernel<<<(NNODES * 3 + 255) / 256, 256>>>();
    ol_precompute_kernel<<<(NNODES + 63) / 64, 256, PRE_SMEM>>>(h, eW1);
    ol_edge_kernel<<<148, 128, EDGE_SMEM>>>(x, edge_attr,
                                            eW1, eb1, eW2, eb2,
                                            v1W1, v1b1, v1W2, v1b2,
                                            v2W1, v2b1, v2W2, v2b2);
    ol_finalize_kernel<<<(NNODES + 255) / 256, 256>>>(out);
}

// round 10
// speedup vs baseline: 3.0473x; 1.1301x over previous
#include <cuda_runtime.h>
#include <cuda_bf16.h>
#include <math.h>

#define NNODES 50000
#define NEDGES 800000
#define HID    128
#define FE     16

typedef unsigned long long u64;
typedef unsigned int u32;

// ---------------- scratch ----------------
__device__ float g_Ha[NNODES * HID];
__device__ float g_Hb[NNODES * HID];
__device__ float g_vec1[NNODES * 3];
__device__ float g_vec2[NNODES * 3];
__device__ int   g_rows[NEDGES];
__device__ int   g_cols[NEDGES];
__device__ int   g_is64;

// ---------------- helpers ----------------
__device__ __forceinline__ u64 dup2(float s) {
    u64 r; asm("mov.b64 %0, {%1, %1};" : "=l"(r) : "f"(s)); return r;
}
__device__ __forceinline__ void fma2(u64& c, u64 a, u64 b) {
    asm("fma.rn.f32x2 %0, %1, %2, %3;" : "=l"(c) : "l"(a), "l"(b), "l"(c));
}
__device__ __forceinline__ float siluf(float v) {
    return __fdividef(v, 1.0f + __expf(-v));
}
__device__ __forceinline__ void cpf4(float* dst, const float* src, int nfloats,
                                     int tid, int nthreads) {
    const float4* s = reinterpret_cast<const float4*>(src);
    float4* d = reinterpret_cast<float4*>(dst);
    for (int i = tid; i < nfloats / 4; i += nthreads) d[i] = s[i];
}

__device__ __forceinline__ u32 packbf(float ev, float od) {
    u32 r; asm("cvt.rn.bf16x2.f32 %0, %1, %2;" : "=r"(r) : "f"(od), "f"(ev)); return r;
}
__device__ __forceinline__ float bres(float v) {
    __nv_bfloat16 b = __float2bfloat16(v);
    return v - __bfloat162float(b);
}
__device__ __forceinline__ void packsplit(float ev, float od, u32& hi, u32& lo) {
    hi = packbf(ev, od);
    lo = packbf(bres(ev), bres(od));
}

__device__ __forceinline__ void mma_bf16(float* c, const u32* a, u32 b0, u32 b1) {
    asm volatile(
        "mma.sync.aligned.m16n8k16.row.col.f32.bf16.bf16.f32 "
        "{%0,%1,%2,%3}, {%4,%5,%6,%7}, {%8,%9}, {%0,%1,%2,%3};"
        : "+f"(c[0]), "+f"(c[1]), "+f"(c[2]), "+f"(c[3])
        : "r"(a[0]), "r"(a[1]), "r"(a[2]), "r"(a[3]), "r"(b0), "r"(b1));
}

// ---------------- dtype detection + index canonicalization ------------------
__global__ void ol_detect_kernel(const int* __restrict__ ei32) {
    if (threadIdx.x == 0 && blockIdx.x == 0) {
        int any = 0;
#pragma unroll
        for (int i = 0; i < 64; i++) any |= ei32[2 * i + 1];
        g_is64 = (any == 0) ? 1 : 0;
    }
}
__global__ void ol_convert_kernel(const void* __restrict__ eiv) {
    int i = blockIdx.x * blockDim.x + threadIdx.x;
    if (i >= NEDGES) return;
    if (g_is64) {
        const long long* e = (const long long*)eiv;
        g_rows[i] = (int)e[i];
        g_cols[i] = (int)e[NEDGES + i];
    } else {
        const int* e = (const int*)eiv;
        g_rows[i] = e[i];
        g_cols[i] = e[NEDGES + i];
    }
}
__global__ void ol_zero_kernel() {
    int i = blockIdx.x * blockDim.x + threadIdx.x;
    if (i < NNODES * 3) { g_vec1[i] = 0.0f; g_vec2[i] = 0.0f; }
}

// ---------------- node precompute (R4 version, known-good ~96us) ------------
#define PRE_SMEM ((256 * 128 + 8 * 8 * 128) * 4)
__global__ void __launch_bounds__(256, 1)
ol_precompute_kernel(const float* __restrict__ h, const float* __restrict__ eW1) {
    extern __shared__ float smem[];
    float* Wab = smem;
    float* act = smem + 256 * 128;

    cpf4(Wab, eW1, 256 * 128, threadIdx.x, 256);
    __syncthreads();

    const int warp = threadIdx.x >> 5, lane = threadIdx.x & 31;
    float* myAct = act + warp * (8 * 128);
    float4* myAct4 = reinterpret_cast<float4*>(myAct);
    const int n0 = (blockIdx.x * 8 + warp) * 8;

#pragma unroll
    for (int e = 0; e < 8; e++) {
        int n = n0 + e;
        float4 v = make_float4(0.f, 0.f, 0.f, 0.f);
        if (n < NNODES) v = reinterpret_cast<const float4*>(h)[n * 32 + lane];
        myAct4[e * 32 + lane] = v;
    }
    __syncwarp();

    u64 accA0[8], accA1[8], accB0[8], accB1[8];
#pragma unroll
    for (int e = 0; e < 8; e++) {
        accA0[e] = 0ull; accA1[e] = 0ull; accB0[e] = 0ull; accB1[e] = 0ull;
    }
    const ulonglong2* Wab2 = reinterpret_cast<const ulonglong2*>(Wab);
    for (int kb = 0; kb < 32; kb++) {
        ulonglong2 wa0 = Wab2[(4 * kb + 0) * 32 + lane];
        ulonglong2 wa1 = Wab2[(4 * kb + 1) * 32 + lane];
        ulonglong2 wa2 = Wab2[(4 * kb + 2) * 32 + lane];
        ulonglong2 wa3 = Wab2[(4 * kb + 3) * 32 + lane];
        ulonglong2 wb0 = Wab2[(128 + 4 * kb + 0) * 32 + lane];
        ulonglong2 wb1 = Wab2[(128 + 4 * kb + 1) * 32 + lane];
        ulonglong2 wb2 = Wab2[(128 + 4 * kb + 2) * 32 + lane];
        ulonglong2 wb3 = Wab2[(128 + 4 * kb + 3) * 32 + lane];
#pragma unroll
        for (int e = 0; e < 8; e++) {
            float4 a = myAct4[e * 32 + kb];
            u64 dx = dup2(a.x), dy = dup2(a.y), dz = dup2(a.z), dw = dup2(a.w);
            fma2(accA0[e], dx, wa0.x); fma2(accA1[e], dx, wa0.y);
            fma2(accA0[e], dy, wa1.x); fma2(accA1[e], dy, wa1.y);
            fma2(accA0[e], dz, wa2.x); fma2(accA1[e], dz, wa2.y);
            fma2(accA0[e], dw, wa3.x); fma2(accA1[e], dw, wa3.y);
            fma2(accB0[e], dx, wb0.x); fma2(accB1[e], dx, wb0.y);
            fma2(accB0[e], dy, wb1.x); fma2(accB1[e], dy, wb1.y);
            fma2(accB0[e], dz, wb2.x); fma2(accB1[e], dz, wb2.y);
            fma2(accB0[e], dw, wb3.x); fma2(accB1[e], dw, wb3.y);
        }
    }
#pragma unroll
    for (int e = 0; e < 8; e++) {
        int n = n0 + e;
        if (n < NNODES) {
            reinterpret_cast<ulonglong2*>(g_Ha)[n * 32 + lane] =
                make_ulonglong2(accA0[e], accA1[e]);
            reinterpret_cast<ulonglong2*>(g_Hb)[n * 32 + lane] =
                make_ulonglong2(accB0[e], accB1[e]);
        }
    }
}

// ---------------- fragment prepack helpers ----------------
__device__ void pack_wfrag(u32* Bh, u32* Bl, const float* __restrict__ W,
                           int tid, int nthreads) {
    for (int idx = tid; idx < 4096; idx += nthreads) {
        int kt = idx >> 9, nt = (idx >> 5) & 15, l = idx & 31;
        int n = nt * 8 + (l >> 2), k0 = kt * 16 + (l & 3) * 2;
        float w00 = W[k0 * 128 + n],      w01 = W[(k0 + 1) * 128 + n];
        float w10 = W[(k0 + 8) * 128 + n], w11 = W[(k0 + 9) * 128 + n];
        u32 h0, l0, h1, l1;
        packsplit(w00, w01, h0, l0);
        packsplit(w10, w11, h1, l1);
        Bh[idx * 2] = h0; Bh[idx * 2 + 1] = h1;
        Bl[idx * 2] = l0; Bl[idx * 2 + 1] = l1;
    }
}
__device__ void pack_w1c(u32* Bh, u32* Bl, const float* __restrict__ W,
                         int tid, int nthreads) {
    for (int idx = tid; idx < 512; idx += nthreads) {
        int nt = idx >> 5, l = idx & 31;
        int n = nt * 8 + (l >> 2), k0 = (l & 3) * 2;
        float w00 = W[k0 * 128 + n],      w01 = W[(k0 + 1) * 128 + n];
        float w10 = W[(k0 + 8) * 128 + n], w11 = W[(k0 + 9) * 128 + n];
        u32 h0, l0, h1, l1;
        packsplit(w00, w01, h0, l0);
        packsplit(w10, w11, h1, l1);
        Bh[idx * 2] = h0; Bh[idx * 2 + 1] = h1;
        Bl[idx * 2] = l0; Bl[idx * 2 + 1] = l1;
    }
}

// ---------------- tensor-core edge kernel (256 threads, 8 warps) ------------
#define EDGE_SMEM (57152 * 4)
#define NT_EDGE  (NEDGES / 32)

__global__ void __launch_bounds__(256, 1)
ol_edge_kernel(const float* __restrict__ x,
               const float* __restrict__ edge_attr,
               const float* __restrict__ eW1, const float* __restrict__ eb1,
               const float* __restrict__ eW2, const float* __restrict__ eb2,
               const float* __restrict__ v1W1, const float* __restrict__ v1b1,
               const float* __restrict__ v1W2, const float* __restrict__ v1b2,
               const float* __restrict__ v2W1, const float* __restrict__ v2b1,
               const float* __restrict__ v2W2, const float* __restrict__ v2b2) {
    extern __shared__ float smem[];
    u32* su = (u32*)smem;

    float* sb1   = smem + 0;
    float* sb2   = smem + 128;
    float* sv1b1 = smem + 256;
    float* sv2b1 = smem + 384;
    float* sv1w2 = smem + 512;
    float* sv2w2 = smem + 640;
    float* wsc   = smem + 768;    // 64
    float* red1  = smem + 832;    // 256 (8 warps x 32)
    float* red2  = smem + 1088;   // 256
    u32* A1h  = su + 1344;        // 2*32*4
    u32* A1l  = su + 1600;
    u32* W1cH = su + 1856;        // 16*32*2
    u32* W1cL = su + 2880;
    u32* actH = su + 3904;        // 16*32*4
    u32* actL = su + 5952;
    u32* W2h  = su + 8000;        // 8*16*32*2
    u32* W2l  = su + 16192;
    u32* V1h  = su + 24384;
    u32* V1l  = su + 32576;
    u32* V2h  = su + 40768;
    u32* V2l  = su + 48960;       // end 57152

    const int tid = threadIdx.x;
    const int w = tid >> 5, lane = tid & 31;

    cpf4(sb1, eb1, 128, tid, 256);
    cpf4(sb2, eb2, 128, tid, 256);
    cpf4(sv1b1, v1b1, 128, tid, 256);
    cpf4(sv2b1, v2b1, 128, tid, 256);
    cpf4(sv1w2, v1W2, 128, tid, 256);
    cpf4(sv2w2, v2W2, 128, tid, 256);
    pack_w1c(W1cH, W1cL, eW1 + 256 * 128, tid, 256);
    pack_wfrag(W2h, W2l, eW2, tid, 256);
    pack_wfrag(V1h, V1l, v1W1, tid, 256);
    pack_wfrag(V2h, V2l, v2W1, tid, 256);
    __syncthreads();

    const float c1 = __ldg(v1b2);
    const float c2 = __ldg(v2b2);

    for (int t = blockIdx.x; t < NT_EDGE; t += 148) {
        const int tbase = t * 32;

        // ---- build A1 fragments (edge_attr): threads 0..63 ----
        if (tid < 64) {
            int m = tid >> 5, l = tid & 31;
            int r = l >> 2, k0 = (l & 3) * 2;
            const float* ep0 = edge_attr + (size_t)(tbase + m * 16 + r) * 16;
            const float* ep1 = edge_attr + (size_t)(tbase + m * 16 + r + 8) * 16;
            float2 p0 = *(const float2*)(ep0 + k0);
            float2 p1 = *(const float2*)(ep1 + k0);
            float2 p2 = *(const float2*)(ep0 + k0 + 8);
            float2 p3 = *(const float2*)(ep1 + k0 + 8);
            int o = (m * 32 + l) * 4;
            u32 hh, ll;
            packsplit(p0.x, p0.y, hh, ll); A1h[o] = hh;     A1l[o] = ll;
            packsplit(p1.x, p1.y, hh, ll); A1h[o + 1] = hh; A1l[o + 1] = ll;
            packsplit(p2.x, p2.y, hh, ll); A1h[o + 2] = hh; A1l[o + 2] = ll;
            packsplit(p3.x, p3.y, hh, ll); A1h[o + 3] = hh; A1l[o + 3] = ll;
        }

        // ---- layer1 C init: Ha[row]+Hb[col]+b1 at fragment coords ----
        float C[2][2][4];
#pragma unroll
        for (int m = 0; m < 2; m++) {
            int e0 = tbase + m * 16 + (lane >> 2);
            int e1 = e0 + 8;
            int rA = g_rows[e0], cA = g_cols[e0];
            int rB = g_rows[e1], cB = g_cols[e1];
#pragma unroll
            for (int i = 0; i < 2; i++) {
                int n0 = (w * 2 + i) * 8 + 2 * (lane & 3);
                float2 a0 = *(const float2*)(g_Ha + (size_t)rA * 128 + n0);
                float2 b0 = *(const float2*)(g_Hb + (size_t)cA * 128 + n0);
                float2 a1 = *(const float2*)(g_Ha + (size_t)rB * 128 + n0);
                float2 b1 = *(const float2*)(g_Hb + (size_t)cB * 128 + n0);
                float2 bb = *(const float2*)(sb1 + n0);
                C[m][i][0] = a0.x + b0.x + bb.x;
                C[m][i][1] = a0.y + b0.y + bb.y;
                C[m][i][2] = a1.x + b1.x + bb.x;
                C[m][i][3] = a1.y + b1.y + bb.y;
            }
        }
        __syncthreads();   // A1 visible

        // ---- layer1 MMA: += ea @ W1c (k=16) ----
        {
            uint4 h0 = *(const uint4*)(A1h + lane * 4);
            uint4 l0 = *(const uint4*)(A1l + lane * 4);
            uint4 h1 = *(const uint4*)(A1h + (32 + lane) * 4);
            uint4 l1 = *(const uint4*)(A1l + (32 + lane) * 4);
            u32 AH0[4] = {h0.x, h0.y, h0.z, h0.w}, AL0[4] = {l0.x, l0.y, l0.z, l0.w};
            u32 AH1[4] = {h1.x, h1.y, h1.z, h1.w}, AL1[4] = {l1.x, l1.y, l1.z, l1.w};
#pragma unroll
            for (int i = 0; i < 2; i++) {
                int fo = ((w * 2 + i) * 32 + lane) * 2;
                u32 bh0 = W1cH[fo], bh1 = W1cH[fo + 1];
                u32 bl0 = W1cL[fo], bl1 = W1cL[fo + 1];
                mma_bf16(C[0][i], AH0, bh0, bh1);
                mma_bf16(C[0][i], AL0, bh0, bh1);
                mma_bf16(C[0][i], AH0, bl0, bl1);
                mma_bf16(C[1][i], AH1, bh0, bh1);
                mma_bf16(C[1][i], AL1, bh0, bh1);
                mma_bf16(C[1][i], AH1, bl0, bl1);
            }
        }
        // silu + repack to act fragments (lane-preserving)
#pragma unroll
        for (int m = 0; m < 2; m++)
#pragma unroll
            for (int i = 0; i < 2; i++) {
                int g = w * 2 + i;
                int base = ((m * 8 + (g >> 1)) * 32 + lane) * 4 + (g & 1) * 2;
                u32 hh, ll;
                packsplit(siluf(C[m][i][0]), siluf(C[m][i][1]), hh, ll);
                actH[base] = hh; actL[base] = ll;
                packsplit(siluf(C[m][i][2]), siluf(C[m][i][3]), hh, ll);
                actH[base + 1] = hh; actL[base + 1] = ll;
            }
        __syncthreads();   // y1 fragments ready

        // ---- layer2: ef = silu(y1 @ eW2 + b2) ----
#pragma unroll
        for (int m = 0; m < 2; m++)
#pragma unroll
            for (int i = 0; i < 2; i++)
#pragma unroll
                for (int j = 0; j < 4; j++) C[m][i][j] = 0.f;
#pragma unroll
        for (int kt = 0; kt < 8; kt++) {
            uint4 h0 = *(const uint4*)(actH + (kt * 32 + lane) * 4);
            uint4 l0 = *(const uint4*)(actL + (kt * 32 + lane) * 4);
            uint4 h1 = *(const uint4*)(actH + ((8 + kt) * 32 + lane) * 4);
            uint4 l1 = *(const uint4*)(actL + ((8 + kt) * 32 + lane) * 4);
            u32 AH0[4] = {h0.x, h0.y, h0.z, h0.w}, AL0[4] = {l0.x, l0.y, l0.z, l0.w};
            u32 AH1[4] = {h1.x, h1.y, h1.z, h1.w}, AL1[4] = {l1.x, l1.y, l1.z, l1.w};
#pragma unroll
            for (int i = 0; i < 2; i++) {
                int fo = ((kt * 16 + (w * 2 + i)) * 32 + lane) * 2;
                u32 bh0 = W2h[fo], bh1 = W2h[fo + 1];
                u32 bl0 = W2l[fo], bl1 = W2l[fo + 1];
                mma_bf16(C[0][i], AH0, bh0, bh1);
                mma_bf16(C[0][i], AL0, bh0, bh1);
                mma_bf16(C[0][i], AH0, bl0, bl1);
                mma_bf16(C[1][i], AH1, bh0, bh1);
                mma_bf16(C[1][i], AL1, bh0, bh1);
                mma_bf16(C[1][i], AH1, bl0, bl1);
            }
        }
        __syncthreads();   // all reads of y1 done before overwrite
#pragma unroll
        for (int m = 0; m < 2; m++)
#pragma unroll
            for (int i = 0; i < 2; i++) {
                int g = w * 2 + i;
                int n0 = g * 8 + 2 * (lane & 3);
                float2 bb = *(const float2*)(sb2 + n0);
                int base = ((m * 8 + (g >> 1)) * 32 + lane) * 4 + (g & 1) * 2;
                u32 hh, ll;
                packsplit(siluf(C[m][i][0] + bb.x), siluf(C[m][i][1] + bb.y), hh, ll);
                actH[base] = hh; actL[base] = ll;
                packsplit(siluf(C[m][i][2] + bb.x), siluf(C[m][i][3] + bb.y), hh, ll);
                actH[base + 1] = hh; actL[base + 1] = ll;
            }
        __syncthreads();   // ef fragments ready

        // ---- heads fused: both V1 and V2 in one act pass ----
        {
            float C1[2][2][4], C2[2][2][4];
#pragma unroll
            for (int m = 0; m < 2; m++)
#pragma unroll
                for (int i = 0; i < 2; i++)
#pragma unroll
                    for (int j = 0; j < 4; j++) { C1[m][i][j] = 0.f; C2[m][i][j] = 0.f; }
#pragma unroll
            for (int kt = 0; kt < 8; kt++) {
                uint4 h0 = *(const uint4*)(actH + (kt * 32 + lane) * 4);
                uint4 l0 = *(const uint4*)(actL + (kt * 32 + lane) * 4);
                uint4 h1 = *(const uint4*)(actH + ((8 + kt) * 32 + lane) * 4);
                uint4 l1 = *(const uint4*)(actL + ((8 + kt) * 32 + lane) * 4);
                u32 AH0[4] = {h0.x, h0.y, h0.z, h0.w}, AL0[4] = {l0.x, l0.y, l0.z, l0.w};
                u32 AH1[4] = {h1.x, h1.y, h1.z, h1.w}, AL1[4] = {l1.x, l1.y, l1.z, l1.w};
#pragma unroll
                for (int i = 0; i < 2; i++) {
                    int fo = ((kt * 16 + (w * 2 + i)) * 32 + lane) * 2;
                    u32 p0 = V1h[fo], p1 = V1h[fo + 1];
                    u32 q0 = V1l[fo], q1 = V1l[fo + 1];
                    mma_bf16(C1[0][i], AH0, p0, p1);
                    mma_bf16(C1[0][i], AL0, p0, p1);
                    mma_bf16(C1[0][i], AH0, q0, q1);
                    mma_bf16(C1[1][i], AH1, p0, p1);
                    mma_bf16(C1[1][i], AL1, p0, p1);
                    mma_bf16(C1[1][i], AH1, q0, q1);
                    u32 r0 = V2h[fo], r1 = V2h[fo + 1];
                    u32 s0 = V2l[fo], s1 = V2l[fo + 1];
                    mma_bf16(C2[0][i], AH0, r0, r1);
                    mma_bf16(C2[0][i], AL0, r0, r1);
                    mma_bf16(C2[0][i], AH0, s0, s1);
                    mma_bf16(C2[1][i], AH1, r0, r1);
                    mma_bf16(C2[1][i], AL1, r0, r1);
                    mma_bf16(C2[1][i], AH1, s0, s1);
                }
            }
            // epilogue: silu + dot with head-2 vectors, partial reduce
            float p1a[4] = {0.f, 0.f, 0.f, 0.f};
            float p2a[4] = {0.f, 0.f, 0.f, 0.f};
#pragma unroll
            for (int m = 0; m < 2; m++)
#pragma unroll
                for (int i = 0; i < 2; i++) {
                    int n0 = (w * 2 + i) * 8 + 2 * (lane & 3);
                    float2 bb1 = *(const float2*)(sv1b1 + n0);
                    float2 ww1 = *(const float2*)(sv1w2 + n0);
                    float2 bb2 = *(const float2*)(sv2b1 + n0);
                    float2 ww2 = *(const float2*)(sv2w2 + n0);
                    p1a[m * 2 + 0] += siluf(C1[m][i][0] + bb1.x) * ww1.x
                                    + siluf(C1[m][i][1] + bb1.y) * ww1.y;
                    p1a[m * 2 + 1] += siluf(C1[m][i][2] + bb1.x) * ww1.x
                                    + siluf(C1[m][i][3] + bb1.y) * ww1.y;
                    p2a[m * 2 + 0] += siluf(C2[m][i][0] + bb2.x) * ww2.x
                                    + siluf(C2[m][i][1] + bb2.y) * ww2.y;
                    p2a[m * 2 + 1] += siluf(C2[m][i][2] + bb2.x) * ww2.x
                                    + siluf(C2[m][i][3] + bb2.y) * ww2.y;
                }
#pragma unroll
            for (int j = 0; j < 4; j++) {
                p1a[j] += __shfl_xor_sync(0xffffffffu, p1a[j], 1);
                p1a[j] += __shfl_xor_sync(0xffffffffu, p1a[j], 2);
                p2a[j] += __shfl_xor_sync(0xffffffffu, p2a[j], 1);
                p2a[j] += __shfl_xor_sync(0xffffffffu, p2a[j], 2);
            }
            if ((lane & 3) == 0) {
                int r = lane >> 2;
                red1[w * 32 + r]           = p1a[0];
                red1[w * 32 + r + 8]       = p1a[1];
                red1[w * 32 + 16 + r]      = p1a[2];
                red1[w * 32 + 16 + r + 8]  = p1a[3];
                red2[w * 32 + r]           = p2a[0];
                red2[w * 32 + r + 8]       = p2a[1];
                red2[w * 32 + 16 + r]      = p2a[2];
                red2[w * 32 + 16 + r + 8]  = p2a[3];
            }
        }
        __syncthreads();

        // ---- combine partials (8 warps) ----
        if (tid < 32) {
            float s1 = 0.f, s2 = 0.f;
#pragma unroll
            for (int k = 0; k < 8; k++) {
                s1 += red1[k * 32 + tid];
                s2 += red2[k * 32 + tid];
            }
            wsc[2 * tid] = s1 + c1;
            wsc[2 * tid + 1] = s2 + c2;
        }
        __syncthreads();

        // ---- scatter: threads 0..95 -> (edge e = tid/3, comp d = tid%3) ----
        if (tid < 96) {
            int e = tid / 3, d = tid - 3 * e;
            int eg = tbase + e;
            int row = g_rows[eg], col = g_cols[eg];
            float rp = x[col * 3 + d] - x[row * 3 + d];
            atomicAdd(&g_vec1[row * 3 + d], rp * wsc[2 * e]);
            atomicAdd(&g_vec2[row * 3 + d], rp * wsc[2 * e + 1]);
        }
    }
}

// ---------------- finalize: Gram-Schmidt per node ----------------
__global__ void ol_finalize_kernel(float* __restrict__ out) {
    int n = blockIdx.x * blockDim.x + threadIdx.x;
    if (n >= NNODES) return;
    float v1x = g_vec1[n * 3 + 0], v1y = g_vec1[n * 3 + 1], v1z = g_vec1[n * 3 + 2];
    float v2x = g_vec2[n * 3 + 0], v2y = g_vec2[n * 3 + 1], v2z = g_vec2[n * 3 + 2];

    float n1 = fmaxf(sqrtf(v1x * v1x + v1y * v1y + v1z * v1z), 1e-12f);
    float e1x = v1x / n1, e1y = v1y / n1, e1z = v1z / n1;

    float dp = e1x * v2x + e1y * v2y + e1z * v2z;
    float px = v2x - dp * e1x, py = v2y - dp * e1y, pz = v2z - dp * e1z;
    float n2 = fmaxf(sqrtf(px * px + py * py + pz * pz), 1e-12f);
    float e2x = px / n2, e2y = py / n2, e2z = pz / n2;

    float e3x = e1y * e2z - e1z * e2y;
    float e3y = e1z * e2x - e1x * e2z;
    float e3z = e1x * e2y - e1y * e2x;

    float* o = out + n * 9;
    o[0] = e1x; o[1] = e2x; o[2] = e3x;
    o[3] = e1y; o[4] = e2y; o[5] = e3y;
    o[6] = e1z; o[7] = e2z; o[8] = e3z;
}

// ---------------- launch ----------------
extern "C" void kernel_launch(void* const* d_in, const int* in_sizes, int n_in,
                              void* d_out, int out_size) {
    const float* h         = (const float*)d_in[0];
    const float* x         = (const float*)d_in[1];
    const void*  ei        = d_in[2];
    const float* edge_attr = (const float*)d_in[3];
    const float* eW1 = (const float*)d_in[4];  const float* eb1 = (const float*)d_in[5];
    const float* eW2 = (const float*)d_in[6];  const float* eb2 = (const float*)d_in[7];
    const float* v1W1 = (const float*)d_in[8]; const float* v1b1 = (const float*)d_in[9];
    const float* v1W2 = (const float*)d_in[10]; const float* v1b2 = (const float*)d_in[11];
    const float* v2W1 = (const float*)d_in[12]; const float* v2b1 = (const float*)d_in[13];
    const float* v2W2 = (const float*)d_in[14]; const float* v2b2 = (const float*)d_in[15];
    float* out = (float*)d_out;

    cudaFuncSetAttribute(ol_precompute_kernel,
                         cudaFuncAttributeMaxDynamicSharedMemorySize, PRE_SMEM);
    cudaFuncSetAttribute(ol_edge_kernel,
                         cudaFuncAttributeMaxDynamicSharedMemorySize, EDGE_SMEM);

    ol_detect_kernel<<<1, 32>>>((const int*)ei);
    ol_convert_kernel<<<(NEDGES + 255) / 256, 256>>>(ei);
    ol_zero_kernel<<<(NNODES * 3 + 255) / 256, 256>>>();
    ol_precompute_kernel<<<(NNODES + 63) / 64, 256, PRE_SMEM>>>(h, eW1);
    ol_edge_kernel<<<148, 256, EDGE_SMEM>>>(x, edge_attr,
                                            eW1, eb1, eW2, eb2,
                                            v1W1, v1b1, v1W2, v1b2,
                                            v2W1, v2b1, v2W2, v2b2);
    ol_finalize_kernel<<<(NNODES + 255) / 256, 256>>>(out);
}

// round 11
// speedup vs baseline: 3.2558x; 1.0684x over previous
#include <cuda_runtime.h>
#include <cuda_bf16.h>
#include <math.h>

#define NNODES 50000
#define NEDGES 800000
#define HID    128
#define FE     16

typedef unsigned long long u64;
typedef unsigned int u32;

// ---------------- scratch ----------------
__device__ float g_Ha[NNODES * HID];
__device__ float g_Hb[NNODES * HID];
__device__ float g_vec1[NNODES * 3];
__device__ float g_vec2[NNODES * 3];
__device__ int   g_rows[NEDGES];
__device__ int   g_cols[NEDGES];
__device__ int   g_is64;

// ---------------- helpers ----------------
__device__ __forceinline__ u64 dup2(float s) {
    u64 r; asm("mov.b64 %0, {%1, %1};" : "=l"(r) : "f"(s)); return r;
}
__device__ __forceinline__ void fma2(u64& c, u64 a, u64 b) {
    asm("fma.rn.f32x2 %0, %1, %2, %3;" : "=l"(c) : "l"(a), "l"(b), "l"(c));
}
__device__ __forceinline__ float siluf(float v) {
    return __fdividef(v, 1.0f + __expf(-v));
}
__device__ __forceinline__ void cpf4(float* dst, const float* src, int nfloats,
                                     int tid, int nthreads) {
    const float4* s = reinterpret_cast<const float4*>(src);
    float4* d = reinterpret_cast<float4*>(dst);
    for (int i = tid; i < nfloats / 4; i += nthreads) d[i] = s[i];
}

__device__ __forceinline__ u32 packbf(float ev, float od) {
    u32 r; asm("cvt.rn.bf16x2.f32 %0, %1, %2;" : "=r"(r) : "f"(od), "f"(ev)); return r;
}
__device__ __forceinline__ float bres(float v) {
    __nv_bfloat16 b = __float2bfloat16(v);
    return v - __bfloat162float(b);
}
__device__ __forceinline__ void packsplit(float ev, float od, u32& hi, u32& lo) {
    hi = packbf(ev, od);
    lo = packbf(bres(ev), bres(od));
}

__device__ __forceinline__ void mma_bf16(float* c, const u32* a, u32 b0, u32 b1) {
    asm volatile(
        "mma.sync.aligned.m16n8k16.row.col.f32.bf16.bf16.f32 "
        "{%0,%1,%2,%3}, {%4,%5,%6,%7}, {%8,%9}, {%0,%1,%2,%3};"
        : "+f"(c[0]), "+f"(c[1]), "+f"(c[2]), "+f"(c[3])
        : "r"(a[0]), "r"(a[1]), "r"(a[2]), "r"(a[3]), "r"(b0), "r"(b1));
}

// ---------------- dtype detection + index canonicalization ------------------
__global__ void ol_detect_kernel(const int* __restrict__ ei32) {
    if (threadIdx.x == 0 && blockIdx.x == 0) {
        int any = 0;
#pragma unroll
        for (int i = 0; i < 64; i++) any |= ei32[2 * i + 1];
        g_is64 = (any == 0) ? 1 : 0;
    }
}
__global__ void ol_convert_kernel(const void* __restrict__ eiv) {
    int i = blockIdx.x * blockDim.x + threadIdx.x;
    if (i >= NEDGES) return;
    if (g_is64) {
        const long long* e = (const long long*)eiv;
        g_rows[i] = (int)e[i];
        g_cols[i] = (int)e[NEDGES + i];
    } else {
        const int* e = (const int*)eiv;
        g_rows[i] = e[i];
        g_cols[i] = e[NEDGES + i];
    }
}
__global__ void ol_zero_kernel() {
    int i = blockIdx.x * blockDim.x + threadIdx.x;
    if (i < NNODES * 3) { g_vec1[i] = 0.0f; g_vec2[i] = 0.0f; }
}

// ---------------- node precompute (R4 version, known-good ~96us) ------------
#define PRE_SMEM ((256 * 128 + 8 * 8 * 128) * 4)
__global__ void __launch_bounds__(256, 1)
ol_precompute_kernel(const float* __restrict__ h, const float* __restrict__ eW1) {
    extern __shared__ float smem[];
    float* Wab = smem;
    float* act = smem + 256 * 128;

    cpf4(Wab, eW1, 256 * 128, threadIdx.x, 256);
    __syncthreads();

    const int warp = threadIdx.x >> 5, lane = threadIdx.x & 31;
    float* myAct = act + warp * (8 * 128);
    float4* myAct4 = reinterpret_cast<float4*>(myAct);
    const int n0 = (blockIdx.x * 8 + warp) * 8;

#pragma unroll
    for (int e = 0; e < 8; e++) {
        int n = n0 + e;
        float4 v = make_float4(0.f, 0.f, 0.f, 0.f);
        if (n < NNODES) v = reinterpret_cast<const float4*>(h)[n * 32 + lane];
        myAct4[e * 32 + lane] = v;
    }
    __syncwarp();

    u64 accA0[8], accA1[8], accB0[8], accB1[8];
#pragma unroll
    for (int e = 0; e < 8; e++) {
        accA0[e] = 0ull; accA1[e] = 0ull; accB0[e] = 0ull; accB1[e] = 0ull;
    }
    const ulonglong2* Wab2 = reinterpret_cast<const ulonglong2*>(Wab);
    for (int kb = 0; kb < 32; kb++) {
        ulonglong2 wa0 = Wab2[(4 * kb + 0) * 32 + lane];
        ulonglong2 wa1 = Wab2[(4 * kb + 1) * 32 + lane];
        ulonglong2 wa2 = Wab2[(4 * kb + 2) * 32 + lane];
        ulonglong2 wa3 = Wab2[(4 * kb + 3) * 32 + lane];
        ulonglong2 wb0 = Wab2[(128 + 4 * kb + 0) * 32 + lane];
        ulonglong2 wb1 = Wab2[(128 + 4 * kb + 1) * 32 + lane];
        ulonglong2 wb2 = Wab2[(128 + 4 * kb + 2) * 32 + lane];
        ulonglong2 wb3 = Wab2[(128 + 4 * kb + 3) * 32 + lane];
#pragma unroll
        for (int e = 0; e < 8; e++) {
            float4 a = myAct4[e * 32 + kb];
            u64 dx = dup2(a.x), dy = dup2(a.y), dz = dup2(a.z), dw = dup2(a.w);
            fma2(accA0[e], dx, wa0.x); fma2(accA1[e], dx, wa0.y);
            fma2(accA0[e], dy, wa1.x); fma2(accA1[e], dy, wa1.y);
            fma2(accA0[e], dz, wa2.x); fma2(accA1[e], dz, wa2.y);
            fma2(accA0[e], dw, wa3.x); fma2(accA1[e], dw, wa3.y);
            fma2(accB0[e], dx, wb0.x); fma2(accB1[e], dx, wb0.y);
            fma2(accB0[e], dy, wb1.x); fma2(accB1[e], dy, wb1.y);
            fma2(accB0[e], dz, wb2.x); fma2(accB1[e], dz, wb2.y);
            fma2(accB0[e], dw, wb3.x); fma2(accB1[e], dw, wb3.y);
        }
    }
#pragma unroll
    for (int e = 0; e < 8; e++) {
        int n = n0 + e;
        if (n < NNODES) {
            reinterpret_cast<ulonglong2*>(g_Ha)[n * 32 + lane] =
                make_ulonglong2(accA0[e], accA1[e]);
            reinterpret_cast<ulonglong2*>(g_Hb)[n * 32 + lane] =
                make_ulonglong2(accB0[e], accB1[e]);
        }
    }
}

// ---------------- fragment prepack helpers ----------------
__device__ void pack_wfrag(u32* Bh, u32* Bl, const float* __restrict__ W,
                           int tid, int nthreads) {
    for (int idx = tid; idx < 4096; idx += nthreads) {
        int kt = idx >> 9, nt = (idx >> 5) & 15, l = idx & 31;
        int n = nt * 8 + (l >> 2), k0 = kt * 16 + (l & 3) * 2;
        float w00 = W[k0 * 128 + n],      w01 = W[(k0 + 1) * 128 + n];
        float w10 = W[(k0 + 8) * 128 + n], w11 = W[(k0 + 9) * 128 + n];
        u32 h0, l0, h1, l1;
        packsplit(w00, w01, h0, l0);
        packsplit(w10, w11, h1, l1);
        Bh[idx * 2] = h0; Bh[idx * 2 + 1] = h1;
        Bl[idx * 2] = l0; Bl[idx * 2 + 1] = l1;
    }
}
__device__ void pack_w1c(u32* Bh, u32* Bl, const float* __restrict__ W,
                         int tid, int nthreads) {
    for (int idx = tid; idx < 512; idx += nthreads) {
        int nt = idx >> 5, l = idx & 31;
        int n = nt * 8 + (l >> 2), k0 = (l & 3) * 2;
        float w00 = W[k0 * 128 + n],      w01 = W[(k0 + 1) * 128 + n];
        float w10 = W[(k0 + 8) * 128 + n], w11 = W[(k0 + 9) * 128 + n];
        u32 h0, l0, h1, l1;
        packsplit(w00, w01, h0, l0);
        packsplit(w10, w11, h1, l1);
        Bh[idx * 2] = h0; Bh[idx * 2 + 1] = h1;
        Bl[idx * 2] = l0; Bl[idx * 2 + 1] = l1;
    }
}

// ---------------- tensor-core edge kernel (256 threads, pipelined gathers) --
#define EDGE_SMEM (57152 * 4)
#define NT_EDGE  (NEDGES / 32)

__global__ void __launch_bounds__(256, 1)
ol_edge_kernel(const float* __restrict__ x,
               const float* __restrict__ edge_attr,
               const float* __restrict__ eW1, const float* __restrict__ eb1,
               const float* __restrict__ eW2, const float* __restrict__ eb2,
               const float* __restrict__ v1W1, const float* __restrict__ v1b1,
               const float* __restrict__ v1W2, const float* __restrict__ v1b2,
               const float* __restrict__ v2W1, const float* __restrict__ v2b1,
               const float* __restrict__ v2W2, const float* __restrict__ v2b2) {
    extern __shared__ float smem[];
    u32* su = (u32*)smem;

    float* sb1   = smem + 0;
    float* sb2   = smem + 128;
    float* sv1b1 = smem + 256;
    float* sv2b1 = smem + 384;
    float* sv1w2 = smem + 512;
    float* sv2w2 = smem + 640;
    float* wsc   = smem + 768;    // 64
    float* red1  = smem + 832;    // 256
    float* red2  = smem + 1088;   // 256
    u32* A1h  = su + 1344;
    u32* A1l  = su + 1600;
    u32* W1cH = su + 1856;
    u32* W1cL = su + 2880;
    u32* actH = su + 3904;
    u32* actL = su + 5952;
    u32* W2h  = su + 8000;
    u32* W2l  = su + 16192;
    u32* V1h  = su + 24384;
    u32* V1l  = su + 32576;
    u32* V2h  = su + 40768;
    u32* V2l  = su + 48960;

    const int tid = threadIdx.x;
    const int w = tid >> 5, lane = tid & 31;

    cpf4(sb1, eb1, 128, tid, 256);
    cpf4(sb2, eb2, 128, tid, 256);
    cpf4(sv1b1, v1b1, 128, tid, 256);
    cpf4(sv2b1, v2b1, 128, tid, 256);
    cpf4(sv1w2, v1W2, 128, tid, 256);
    cpf4(sv2w2, v2W2, 128, tid, 256);
    pack_w1c(W1cH, W1cL, eW1 + 256 * 128, tid, 256);
    pack_wfrag(W2h, W2l, eW2, tid, 256);
    pack_wfrag(V1h, V1l, v1W1, tid, 256);
    pack_wfrag(V2h, V2l, v2W1, tid, 256);
    __syncthreads();

    const float c1 = __ldg(v1b2);
    const float c2 = __ldg(v2b2);

    // ---- pipelined gather state (registers) ----
    float2 Pa0[2][2], Pb0[2][2], Pa1[2][2], Pb1[2][2];  // Ha/Hb at fragment coords
    float2 Q0, Q1, Q2, Q3;                              // edge_attr pieces (tid<64)

#define DO_PREFETCH(TB) do {                                                   \
    _Pragma("unroll")                                                          \
    for (int m = 0; m < 2; m++) {                                              \
        int e0 = (TB) + m * 16 + (lane >> 2);                                  \
        int e1 = e0 + 8;                                                       \
        int rA = g_rows[e0], cA = g_cols[e0];                                  \
        int rB = g_rows[e1], cB = g_cols[e1];                                  \
        _Pragma("unroll")                                                      \
        for (int i = 0; i < 2; i++) {                                          \
            int n0 = (w * 2 + i) * 8 + 2 * (lane & 3);                         \
            Pa0[m][i] = *(const float2*)(g_Ha + (size_t)rA * 128 + n0);        \
            Pb0[m][i] = *(const float2*)(g_Hb + (size_t)cA * 128 + n0);        \
            Pa1[m][i] = *(const float2*)(g_Ha + (size_t)rB * 128 + n0);        \
            Pb1[m][i] = *(const float2*)(g_Hb + (size_t)cB * 128 + n0);        \
        }                                                                      \
    }                                                                          \
    if (tid < 64) {                                                            \
        int m = tid >> 5, l = tid & 31;                                        \
        int r = l >> 2, k0 = (l & 3) * 2;                                      \
        const float* ep0 = edge_attr + (size_t)((TB) + m * 16 + r) * 16;       \
        const float* ep1 = edge_attr + (size_t)((TB) + m * 16 + r + 8) * 16;   \
        Q0 = *(const float2*)(ep0 + k0);                                       \
        Q1 = *(const float2*)(ep1 + k0);                                       \
        Q2 = *(const float2*)(ep0 + k0 + 8);                                   \
        Q3 = *(const float2*)(ep1 + k0 + 8);                                   \
    }                                                                          \
} while (0)

    if (blockIdx.x < NT_EDGE) DO_PREFETCH(blockIdx.x * 32);

    for (int t = blockIdx.x; t < NT_EDGE; t += 148) {
        const int tbase = t * 32;

        // ---- A1 store from prefetched edge_attr (tid<64) ----
        if (tid < 64) {
            int m = tid >> 5, l = tid & 31;
            int o = (m * 32 + l) * 4;
            u32 hh, ll;
            packsplit(Q0.x, Q0.y, hh, ll); A1h[o] = hh;     A1l[o] = ll;
            packsplit(Q1.x, Q1.y, hh, ll); A1h[o + 1] = hh; A1l[o + 1] = ll;
            packsplit(Q2.x, Q2.y, hh, ll); A1h[o + 2] = hh; A1l[o + 2] = ll;
            packsplit(Q3.x, Q3.y, hh, ll); A1h[o + 3] = hh; A1l[o + 3] = ll;
        }

        // ---- layer1 C init from prefetched Ha/Hb ----
        float C[2][2][4];
#pragma unroll
        for (int m = 0; m < 2; m++)
#pragma unroll
            for (int i = 0; i < 2; i++) {
                int n0 = (w * 2 + i) * 8 + 2 * (lane & 3);
                float2 bb = *(const float2*)(sb1 + n0);
                C[m][i][0] = Pa0[m][i].x + Pb0[m][i].x + bb.x;
                C[m][i][1] = Pa0[m][i].y + Pb0[m][i].y + bb.y;
                C[m][i][2] = Pa1[m][i].x + Pb1[m][i].x + bb.x;
                C[m][i][3] = Pa1[m][i].y + Pb1[m][i].y + bb.y;
            }

        // ---- issue next tile's gathers (overlap with rest of tile) ----
        {
            int tn = t + 148;
            if (tn < NT_EDGE) DO_PREFETCH(tn * 32);
        }
        __syncthreads();   // A1 visible

        // ---- layer1 MMA: += ea @ W1c (k=16) ----
        {
            uint4 h0 = *(const uint4*)(A1h + lane * 4);
            uint4 l0 = *(const uint4*)(A1l + lane * 4);
            uint4 h1 = *(const uint4*)(A1h + (32 + lane) * 4);
            uint4 l1 = *(const uint4*)(A1l + (32 + lane) * 4);
            u32 AH0[4] = {h0.x, h0.y, h0.z, h0.w}, AL0[4] = {l0.x, l0.y, l0.z, l0.w};
            u32 AH1[4] = {h1.x, h1.y, h1.z, h1.w}, AL1[4] = {l1.x, l1.y, l1.z, l1.w};
#pragma unroll
            for (int i = 0; i < 2; i++) {
                int fo = ((w * 2 + i) * 32 + lane) * 2;
                u32 bh0 = W1cH[fo], bh1 = W1cH[fo + 1];
                u32 bl0 = W1cL[fo], bl1 = W1cL[fo + 1];
                mma_bf16(C[0][i], AH0, bh0, bh1);
                mma_bf16(C[0][i], AL0, bh0, bh1);
                mma_bf16(C[0][i], AH0, bl0, bl1);
                mma_bf16(C[1][i], AH1, bh0, bh1);
                mma_bf16(C[1][i], AL1, bh0, bh1);
                mma_bf16(C[1][i], AH1, bl0, bl1);
            }
        }
#pragma unroll
        for (int m = 0; m < 2; m++)
#pragma unroll
            for (int i = 0; i < 2; i++) {
                int g = w * 2 + i;
                int base = ((m * 8 + (g >> 1)) * 32 + lane) * 4 + (g & 1) * 2;
                u32 hh, ll;
                packsplit(siluf(C[m][i][0]), siluf(C[m][i][1]), hh, ll);
                actH[base] = hh; actL[base] = ll;
                packsplit(siluf(C[m][i][2]), siluf(C[m][i][3]), hh, ll);
                actH[base + 1] = hh; actL[base + 1] = ll;
            }
        __syncthreads();   // y1 fragments ready

        // ---- layer2: ef = silu(y1 @ eW2 + b2) ----
#pragma unroll
        for (int m = 0; m < 2; m++)
#pragma unroll
            for (int i = 0; i < 2; i++)
#pragma unroll
                for (int j = 0; j < 4; j++) C[m][i][j] = 0.f;
#pragma unroll
        for (int kt = 0; kt < 8; kt++) {
            uint4 h0 = *(const uint4*)(actH + (kt * 32 + lane) * 4);
            uint4 l0 = *(const uint4*)(actL + (kt * 32 + lane) * 4);
            uint4 h1 = *(const uint4*)(actH + ((8 + kt) * 32 + lane) * 4);
            uint4 l1 = *(const uint4*)(actL + ((8 + kt) * 32 + lane) * 4);
            u32 AH0[4] = {h0.x, h0.y, h0.z, h0.w}, AL0[4] = {l0.x, l0.y, l0.z, l0.w};
            u32 AH1[4] = {h1.x, h1.y, h1.z, h1.w}, AL1[4] = {l1.x, l1.y, l1.z, l1.w};
#pragma unroll
            for (int i = 0; i < 2; i++) {
                int fo = ((kt * 16 + (w * 2 + i)) * 32 + lane) * 2;
                u32 bh0 = W2h[fo], bh1 = W2h[fo + 1];
                u32 bl0 = W2l[fo], bl1 = W2l[fo + 1];
                mma_bf16(C[0][i], AH0, bh0, bh1);
                mma_bf16(C[0][i], AL0, bh0, bh1);
                mma_bf16(C[0][i], AH0, bl0, bl1);
                mma_bf16(C[1][i], AH1, bh0, bh1);
                mma_bf16(C[1][i], AL1, bh0, bh1);
                mma_bf16(C[1][i], AH1, bl0, bl1);
            }
        }
        __syncthreads();   // all reads of y1 done before overwrite
#pragma unroll
        for (int m = 0; m < 2; m++)
#pragma unroll
            for (int i = 0; i < 2; i++) {
                int g = w * 2 + i;
                int n0 = g * 8 + 2 * (lane & 3);
                float2 bb = *(const float2*)(sb2 + n0);
                int base = ((m * 8 + (g >> 1)) * 32 + lane) * 4 + (g & 1) * 2;
                u32 hh, ll;
                packsplit(siluf(C[m][i][0] + bb.x), siluf(C[m][i][1] + bb.y), hh, ll);
                actH[base] = hh; actL[base] = ll;
                packsplit(siluf(C[m][i][2] + bb.x), siluf(C[m][i][3] + bb.y), hh, ll);
                actH[base + 1] = hh; actL[base + 1] = ll;
            }
        __syncthreads();   // ef fragments ready

        // ---- heads fused ----
        {
            float C1[2][2][4], C2[2][2][4];
#pragma unroll
            for (int m = 0; m < 2; m++)
#pragma unroll
                for (int i = 0; i < 2; i++)
#pragma unroll
                    for (int j = 0; j < 4; j++) { C1[m][i][j] = 0.f; C2[m][i][j] = 0.f; }
#pragma unroll
            for (int kt = 0; kt < 8; kt++) {
                uint4 h0 = *(const uint4*)(actH + (kt * 32 + lane) * 4);
                uint4 l0 = *(const uint4*)(actL + (kt * 32 + lane) * 4);
                uint4 h1 = *(const uint4*)(actH + ((8 + kt) * 32 + lane) * 4);
                uint4 l1 = *(const uint4*)(actL + ((8 + kt) * 32 + lane) * 4);
                u32 AH0[4] = {h0.x, h0.y, h0.z, h0.w}, AL0[4] = {l0.x, l0.y, l0.z, l0.w};
                u32 AH1[4] = {h1.x, h1.y, h1.z, h1.w}, AL1[4] = {l1.x, l1.y, l1.z, l1.w};
#pragma unroll
                for (int i = 0; i < 2; i++) {
                    int fo = ((kt * 16 + (w * 2 + i)) * 32 + lane) * 2;
                    u32 p0 = V1h[fo], p1 = V1h[fo + 1];
                    u32 q0 = V1l[fo], q1 = V1l[fo + 1];
                    mma_bf16(C1[0][i], AH0, p0, p1);
                    mma_bf16(C1[0][i], AL0, p0, p1);
                    mma_bf16(C1[0][i], AH0, q0, q1);
                    mma_bf16(C1[1][i], AH1, p0, p1);
                    mma_bf16(C1[1][i], AL1, p0, p1);
                    mma_bf16(C1[1][i], AH1, q0, q1);
                    u32 r0 = V2h[fo], r1 = V2h[fo + 1];
                    u32 s0 = V2l[fo], s1 = V2l[fo + 1];
                    mma_bf16(C2[0][i], AH0, r0, r1);
                    mma_bf16(C2[0][i], AL0, r0, r1);
                    mma_bf16(C2[0][i], AH0, s0, s1);
                    mma_bf16(C2[1][i], AH1, r0, r1);
                    mma_bf16(C2[1][i], AL1, r0, r1);
                    mma_bf16(C2[1][i], AH1, s0, s1);
                }
            }
            float p1a[4] = {0.f, 0.f, 0.f, 0.f};
            float p2a[4] = {0.f, 0.f, 0.f, 0.f};
#pragma unroll
            for (int m = 0; m < 2; m++)
#pragma unroll
                for (int i = 0; i < 2; i++) {
                    int n0 = (w * 2 + i) * 8 + 2 * (lane & 3);
                    float2 bb1 = *(const float2*)(sv1b1 + n0);
                    float2 ww1 = *(const float2*)(sv1w2 + n0);
                    float2 bb2 = *(const float2*)(sv2b1 + n0);
                    float2 ww2 = *(const float2*)(sv2w2 + n0);
                    p1a[m * 2 + 0] += siluf(C1[m][i][0] + bb1.x) * ww1.x
                                    + siluf(C1[m][i][1] + bb1.y) * ww1.y;
                    p1a[m * 2 + 1] += siluf(C1[m][i][2] + bb1.x) * ww1.x
                                    + siluf(C1[m][i][3] + bb1.y) * ww1.y;
                    p2a[m * 2 + 0] += siluf(C2[m][i][0] + bb2.x) * ww2.x
                                    + siluf(C2[m][i][1] + bb2.y) * ww2.y;
                    p2a[m * 2 + 1] += siluf(C2[m][i][2] + bb2.x) * ww2.x
                                    + siluf(C2[m][i][3] + bb2.y) * ww2.y;
                }
#pragma unroll
            for (int j = 0; j < 4; j++) {
                p1a[j] += __shfl_xor_sync(0xffffffffu, p1a[j], 1);
                p1a[j] += __shfl_xor_sync(0xffffffffu, p1a[j], 2);
                p2a[j] += __shfl_xor_sync(0xffffffffu, p2a[j], 1);
                p2a[j] += __shfl_xor_sync(0xffffffffu, p2a[j], 2);
            }
            if ((lane & 3) == 0) {
                int r = lane >> 2;
                red1[w * 32 + r]           = p1a[0];
                red1[w * 32 + r + 8]       = p1a[1];
                red1[w * 32 + 16 + r]      = p1a[2];
                red1[w * 32 + 16 + r + 8]  = p1a[3];
                red2[w * 32 + r]           = p2a[0];
                red2[w * 32 + r + 8]       = p2a[1];
                red2[w * 32 + 16 + r]      = p2a[2];
                red2[w * 32 + 16 + r + 8]  = p2a[3];
            }
        }
        __syncthreads();

        // ---- combine partials + scatter ----
        if (tid < 32) {
            float s1 = 0.f, s2 = 0.f;
#pragma unroll
            for (int k = 0; k < 8; k++) {
                s1 += red1[k * 32 + tid];
                s2 += red2[k * 32 + tid];
            }
            wsc[2 * tid] = s1 + c1;
            wsc[2 * tid + 1] = s2 + c2;
        }
        __syncthreads();

        if (tid < 96) {
            int e = tid / 3, d = tid - 3 * e;
            int eg = tbase + e;
            int row = g_rows[eg], col = g_cols[eg];
            float rp = x[col * 3 + d] - x[row * 3 + d];
            atomicAdd(&g_vec1[row * 3 + d], rp * wsc[2 * e]);
            atomicAdd(&g_vec2[row * 3 + d], rp * wsc[2 * e + 1]);
        }
    }
#undef DO_PREFETCH
}

// ---------------- finalize: Gram-Schmidt per node ----------------
__global__ void ol_finalize_kernel(float* __restrict__ out) {
    int n = blockIdx.x * blockDim.x + threadIdx.x;
    if (n >= NNODES) return;
    float v1x = g_vec1[n * 3 + 0], v1y = g_vec1[n * 3 + 1], v1z = g_vec1[n * 3 + 2];
    float v2x = g_vec2[n * 3 + 0], v2y = g_vec2[n * 3 + 1], v2z = g_vec2[n * 3 + 2];

    float n1 = fmaxf(sqrtf(v1x * v1x + v1y * v1y + v1z * v1z), 1e-12f);
    float e1x = v1x / n1, e1y = v1y / n1, e1z = v1z / n1;

    float dp = e1x * v2x + e1y * v2y + e1z * v2z;
    float px = v2x - dp * e1x, py = v2y - dp * e1y, pz = v2z - dp * e1z;
    float n2 = fmaxf(sqrtf(px * px + py * py + pz * pz), 1e-12f);
    float e2x = px / n2, e2y = py / n2, e2z = pz / n2;

    float e3x = e1y * e2z - e1z * e2y;
    float e3y = e1z * e2x - e1x * e2z;
    float e3z = e1x * e2y - e1y * e2x;

    float* o = out + n * 9;
    o[0] = e1x; o[1] = e2x; o[2] = e3x;
    o[3] = e1y; o[4] = e2y; o[5] = e3y;
    o[6] = e1z; o[7] = e2z; o[8] = e3z;
}

// ---------------- launch ----------------
extern "C" void kernel_launch(void* const* d_in, const int* in_sizes, int n_in,
                              void* d_out, int out_size) {
    const float* h         = (const float*)d_in[0];
    const float* x         = (const float*)d_in[1];
    const void*  ei        = d_in[2];
    const float* edge_attr = (const float*)d_in[3];
    const float* eW1 = (const float*)d_in[4];  const float* eb1 = (const float*)d_in[5];
    const float* eW2 = (const float*)d_in[6];  const float* eb2 = (const float*)d_in[7];
    const float* v1W1 = (const float*)d_in[8]; const float* v1b1 = (const float*)d_in[9];
    const float* v1W2 = (const float*)d_in[10]; const float* v1b2 = (const float*)d_in[11];
    const float* v2W1 = (const float*)d_in[12]; const float* v2b1 = (const float*)d_in[13];
    const float* v2W2 = (const float*)d_in[14]; const float* v2b2 = (const float*)d_in[15];
    float* out = (float*)d_out;

    cudaFuncSetAttribute(ol_precompute_kernel,
                         cudaFuncAttributeMaxDynamicSharedMemorySize, PRE_SMEM);
    cudaFuncSetAttribute(ol_edge_kernel,
                         cudaFuncAttributeMaxDynamicSharedMemorySize, EDGE_SMEM);

    ol_detect_kernel<<<1, 32>>>((const int*)ei);
    ol_convert_kernel<<<(NEDGES + 255) / 256, 256>>>(ei);
    ol_zero_kernel<<<(NNODES * 3 + 255) / 256, 256>>>();
    ol_precompute_kernel<<<(NNODES + 63) / 64, 256, PRE_SMEM>>>(h, eW1);
    ol_edge_kernel<<<148, 256, EDGE_SMEM>>>(x, edge_attr,
                                            eW1, eb1, eW2, eb2,
                                            v1W1, v1b1, v1W2, v1b2,
                                            v2W1, v2b1, v2W2, v2b2);
    ol_finalize_kernel<<<(NNODES + 255) / 256, 256>>>(out);
}

// round 13
// speedup vs baseline: 3.8860x; 1.1936x over previous
#include <cuda_runtime.h>
#include <cuda_fp16.h>
#include <math.h>

#define NNODES 50000
#define NEDGES 800000
#define HID    128
#define FE     16

typedef unsigned long long u64;
typedef unsigned int u32;

// ---------------- scratch ----------------
__device__ float g_Ha[NNODES * HID];
__device__ float g_Hb[NNODES * HID];
__device__ float g_vec1[NNODES * 3];
__device__ float g_vec2[NNODES * 3];
__device__ int   g_rows[NEDGES];
__device__ int   g_cols[NEDGES];
__device__ int   g_is64;

// ---------------- helpers ----------------
__device__ __forceinline__ u64 dup2(float s) {
    u64 r; asm("mov.b64 %0, {%1, %1};" : "=l"(r) : "f"(s)); return r;
}
__device__ __forceinline__ void fma2(u64& c, u64 a, u64 b) {
    asm("fma.rn.f32x2 %0, %1, %2, %3;" : "=l"(c) : "l"(a), "l"(b), "l"(c));
}
__device__ __forceinline__ float siluf(float v) {
    return __fdividef(v, 1.0f + __expf(-v));
}
__device__ __forceinline__ void cpf4(float* dst, const float* src, int nfloats,
                                     int tid, int nthreads) {
    const float4* s = reinterpret_cast<const float4*>(src);
    float4* d = reinterpret_cast<float4*>(dst);
    for (int i = tid; i < nfloats / 4; i += nthreads) d[i] = s[i];
}

// fp16x2 pack: even in low half
__device__ __forceinline__ u32 packh(float ev, float od) {
    u32 r; asm("cvt.rn.f16x2.f32 %0, %1, %2;" : "=r"(r) : "f"(od), "f"(ev)); return r;
}
__device__ __forceinline__ float hres(float v) {
    return v - __half2float(__float2half_rn(v));
}
__device__ __forceinline__ void packsplit(float ev, float od, u32& hi, u32& lo) {
    hi = packh(ev, od);
    lo = packh(hres(ev), hres(od));
}

// fp16 warp MMA: D(16x8,f32) += A(16x16) * B(16x8)
__device__ __forceinline__ void mma_f16(float* c, const u32* a, u32 b0, u32 b1) {
    asm volatile(
        "mma.sync.aligned.m16n8k16.row.col.f32.f16.f16.f32 "
        "{%0,%1,%2,%3}, {%4,%5,%6,%7}, {%8,%9}, {%0,%1,%2,%3};"
        : "+f"(c[0]), "+f"(c[1]), "+f"(c[2]), "+f"(c[3])
        : "r"(a[0]), "r"(a[1]), "r"(a[2]), "r"(a[3]), "r"(b0), "r"(b1));
}

// ---------------- dtype detection + index canonicalization ------------------
__global__ void ol_detect_kernel(const int* __restrict__ ei32) {
    if (threadIdx.x == 0 && blockIdx.x == 0) {
        int any = 0;
#pragma unroll
        for (int i = 0; i < 64; i++) any |= ei32[2 * i + 1];
        g_is64 = (any == 0) ? 1 : 0;
    }
}
__global__ void ol_convert_kernel(const void* __restrict__ eiv) {
    int i = blockIdx.x * blockDim.x + threadIdx.x;
    if (i >= NEDGES) return;
    if (g_is64) {
        const long long* e = (const long long*)eiv;
        g_rows[i] = (int)e[i];
        g_cols[i] = (int)e[NEDGES + i];
    } else {
        const int* e = (const int*)eiv;
        g_rows[i] = e[i];
        g_cols[i] = e[NEDGES + i];
    }
}
__global__ void ol_zero_kernel() {
    int i = blockIdx.x * blockDim.x + threadIdx.x;
    if (i < NNODES * 3) { g_vec1[i] = 0.0f; g_vec2[i] = 0.0f; }
}

// ---------------- node precompute (R4 version, known-good ~96us, no spill) --
#define PRE_SMEM ((256 * 128 + 8 * 8 * 128) * 4)
__global__ void __launch_bounds__(256, 1)
ol_precompute_kernel(const float* __restrict__ h, const float* __restrict__ eW1) {
    extern __shared__ float smem[];
    float* Wab = smem;
    float* act = smem + 256 * 128;

    cpf4(Wab, eW1, 256 * 128, threadIdx.x, 256);
    __syncthreads();

    const int warp = threadIdx.x >> 5, lane = threadIdx.x & 31;
    float* myAct = act + warp * (8 * 128);
    float4* myAct4 = reinterpret_cast<float4*>(myAct);
    const int n0 = (blockIdx.x * 8 + warp) * 8;

#pragma unroll
    for (int e = 0; e < 8; e++) {
        int n = n0 + e;
        float4 v = make_float4(0.f, 0.f, 0.f, 0.f);
        if (n < NNODES) v = reinterpret_cast<const float4*>(h)[n * 32 + lane];
        myAct4[e * 32 + lane] = v;
    }
    __syncwarp();

    u64 accA0[8], accA1[8], accB0[8], accB1[8];
#pragma unroll
    for (int e = 0; e < 8; e++) {
        accA0[e] = 0ull; accA1[e] = 0ull; accB0[e] = 0ull; accB1[e] = 0ull;
    }
    const ulonglong2* Wab2 = reinterpret_cast<const ulonglong2*>(Wab);
    for (int kb = 0; kb < 32; kb++) {
        ulonglong2 wa0 = Wab2[(4 * kb + 0) * 32 + lane];
        ulonglong2 wa1 = Wab2[(4 * kb + 1) * 32 + lane];
        ulonglong2 wa2 = Wab2[(4 * kb + 2) * 32 + lane];
        ulonglong2 wa3 = Wab2[(4 * kb + 3) * 32 + lane];
        ulonglong2 wb0 = Wab2[(128 + 4 * kb + 0) * 32 + lane];
        ulonglong2 wb1 = Wab2[(128 + 4 * kb + 1) * 32 + lane];
        ulonglong2 wb2 = Wab2[(128 + 4 * kb + 2) * 32 + lane];
        ulonglong2 wb3 = Wab2[(128 + 4 * kb + 3) * 32 + lane];
#pragma unroll
        for (int e = 0; e < 8; e++) {
            float4 a = myAct4[e * 32 + kb];
            u64 dx = dup2(a.x), dy = dup2(a.y), dz = dup2(a.z), dw = dup2(a.w);
            fma2(accA0[e], dx, wa0.x); fma2(accA1[e], dx, wa0.y);
            fma2(accA0[e], dy, wa1.x); fma2(accA1[e], dy, wa1.y);
            fma2(accA0[e], dz, wa2.x); fma2(accA1[e], dz, wa2.y);
            fma2(accA0[e], dw, wa3.x); fma2(accA1[e], dw, wa3.y);
            fma2(accB0[e], dx, wb0.x); fma2(accB1[e], dx, wb0.y);
            fma2(accB0[e], dy, wb1.x); fma2(accB1[e], dy, wb1.y);
            fma2(accB0[e], dz, wb2.x); fma2(accB1[e], dz, wb2.y);
            fma2(accB0[e], dw, wb3.x); fma2(accB1[e], dw, wb3.y);
        }
    }
#pragma unroll
    for (int e = 0; e < 8; e++) {
        int n = n0 + e;
        if (n < NNODES) {
            reinterpret_cast<ulonglong2*>(g_Ha)[n * 32 + lane] =
                make_ulonglong2(accA0[e], accA1[e]);
            reinterpret_cast<ulonglong2*>(g_Hb)[n * 32 + lane] =
                make_ulonglong2(accB0[e], accB1[e]);
        }
    }
}

// ---------------- fragment prepack (fp16 hi only) ----------------
__device__ void pack_wfrag(u32* Bh, const float* __restrict__ W,
                           int tid, int nthreads) {
    for (int idx = tid; idx < 4096; idx += nthreads) {
        int kt = idx >> 9, nt = (idx >> 5) & 15, l = idx & 31;
        int n = nt * 8 + (l >> 2), k0 = kt * 16 + (l & 3) * 2;
        Bh[idx * 2]     = packh(W[k0 * 128 + n],       W[(k0 + 1) * 128 + n]);
        Bh[idx * 2 + 1] = packh(W[(k0 + 8) * 128 + n], W[(k0 + 9) * 128 + n]);
    }
}
__device__ void pack_w1c(u32* Bh, const float* __restrict__ W,
                         int tid, int nthreads) {
    for (int idx = tid; idx < 512; idx += nthreads) {
        int nt = idx >> 5, l = idx & 31;
        int n = nt * 8 + (l >> 2), k0 = (l & 3) * 2;
        Bh[idx * 2]     = packh(W[k0 * 128 + n],       W[(k0 + 1) * 128 + n]);
        Bh[idx * 2 + 1] = packh(W[(k0 + 8) * 128 + n], W[(k0 + 9) * 128 + n]);
    }
}

// ---------------- tensor-core edge kernel (fp16 2-term) ----------
// smem u32 layout:
//  0 sb1 |128 sb2 |256 sv1b1 |384 sv2b1 |512 sv1w2 |640 sv2w2 |
//  768 red1(256) |1024 red2(256) |1280 A1h(256) |1536 A1l(256) |
//  1792 W1cH(1024) |2816 actH(2048) |4864 actL(2048) |
//  6912 W2h(8192) |15104 V1h(8192) |23296 V2h(8192) | end 31488
#define EDGE_SMEM (31488 * 4)
#define NT_EDGE  (NEDGES / 32)

__global__ void __launch_bounds__(256, 1)
ol_edge_kernel(const float* __restrict__ x,
               const float* __restrict__ edge_attr,
               const float* __restrict__ eW1, const float* __restrict__ eb1,
               const float* __restrict__ eW2, const float* __restrict__ eb2,
               const float* __restrict__ v1W1, const float* __restrict__ v1b1,
               const float* __restrict__ v1W2, const float* __restrict__ v1b2,
               const float* __restrict__ v2W1, const float* __restrict__ v2b1,
               const float* __restrict__ v2W2, const float* __restrict__ v2b2) {
    extern __shared__ float smem[];
    u32* su = (u32*)smem;

    float* sb1   = smem + 0;
    float* sb2   = smem + 128;
    float* sv1b1 = smem + 256;
    float* sv2b1 = smem + 384;
    float* sv1w2 = smem + 512;
    float* sv2w2 = smem + 640;
    float* red1  = smem + 768;    // 8 warps x 32
    float* red2  = smem + 1024;
    u32* A1h  = su + 1280;
    u32* A1l  = su + 1536;
    u32* W1cH = su + 1792;
    u32* actH = su + 2816;
    u32* actL = su + 4864;
    u32* W2h  = su + 6912;
    u32* V1h  = su + 15104;
    u32* V2h  = su + 23296;

    const int tid = threadIdx.x;
    const int w = tid >> 5, lane = tid & 31;

    cpf4(sb1, eb1, 128, tid, 256);
    cpf4(sb2, eb2, 128, tid, 256);
    cpf4(sv1b1, v1b1, 128, tid, 256);
    cpf4(sv2b1, v2b1, 128, tid, 256);
    cpf4(sv1w2, v1W2, 128, tid, 256);
    cpf4(sv2w2, v2W2, 128, tid, 256);
    pack_w1c(W1cH, eW1 + 256 * 128, tid, 256);
    pack_wfrag(W2h, eW2, tid, 256);
    pack_wfrag(V1h, v1W1, tid, 256);
    pack_wfrag(V2h, v2W1, tid, 256);
    __syncthreads();

    const float c1 = __ldg(v1b2);
    const float c2 = __ldg(v2b2);

    // ---- pipelined gather state (registers) ----
    float2 Pa0[2][2], Pb0[2][2], Pa1[2][2], Pb1[2][2];
    float2 Q0, Q1, Q2, Q3;

#define DO_PREFETCH(TB) do {                                                   \
    _Pragma("unroll")                                                          \
    for (int m = 0; m < 2; m++) {                                              \
        int e0 = (TB) + m * 16 + (lane >> 2);                                  \
        int e1 = e0 + 8;                                                       \
        int rA = g_rows[e0], cA = g_cols[e0];                                  \
        int rB = g_rows[e1], cB = g_cols[e1];                                  \
        _Pragma("unroll")                                                      \
        for (int i = 0; i < 2; i++) {                                          \
            int n0 = (w * 2 + i) * 8 + 2 * (lane & 3);                         \
            Pa0[m][i] = *(const float2*)(g_Ha + (size_t)rA * 128 + n0);        \
            Pb0[m][i] = *(const float2*)(g_Hb + (size_t)cA * 128 + n0);        \
            Pa1[m][i] = *(const float2*)(g_Ha + (size_t)rB * 128 + n0);        \
            Pb1[m][i] = *(const float2*)(g_Hb + (size_t)cB * 128 + n0);        \
        }                                                                      \
    }                                                                          \
    if (tid < 64) {                                                            \
        int m = tid >> 5, l = tid & 31;                                        \
        int r = l >> 2, k0 = (l & 3) * 2;                                      \
        const float* ep0 = edge_attr + (size_t)((TB) + m * 16 + r) * 16;       \
        const float* ep1 = edge_attr + (size_t)((TB) + m * 16 + r + 8) * 16;   \
        Q0 = *(const float2*)(ep0 + k0);                                       \
        Q1 = *(const float2*)(ep1 + k0);                                       \
        Q2 = *(const float2*)(ep0 + k0 + 8);                                   \
        Q3 = *(const float2*)(ep1 + k0 + 8);                                   \
    }                                                                          \
} while (0)

    if (blockIdx.x < NT_EDGE) DO_PREFETCH(blockIdx.x * 32);

    for (int t = blockIdx.x; t < NT_EDGE; t += 148) {
        const int tbase = t * 32;

        // ---- A1 store from prefetched edge_attr (tid<64) ----
        if (tid < 64) {
            int m = tid >> 5, l = tid & 31;
            int o = (m * 32 + l) * 4;
            u32 hh, ll;
            packsplit(Q0.x, Q0.y, hh, ll); A1h[o] = hh;     A1l[o] = ll;
            packsplit(Q1.x, Q1.y, hh, ll); A1h[o + 1] = hh; A1l[o + 1] = ll;
            packsplit(Q2.x, Q2.y, hh, ll); A1h[o + 2] = hh; A1l[o + 2] = ll;
            packsplit(Q3.x, Q3.y, hh, ll); A1h[o + 3] = hh; A1l[o + 3] = ll;
        }

        // ---- layer1 C init from prefetched Ha/Hb ----
        float C[2][2][4];
#pragma unroll
        for (int m = 0; m < 2; m++)
#pragma unroll
            for (int i = 0; i < 2; i++) {
                int n0 = (w * 2 + i) * 8 + 2 * (lane & 3);
                float2 bb = *(const float2*)(sb1 + n0);
                C[m][i][0] = Pa0[m][i].x + Pb0[m][i].x + bb.x;
                C[m][i][1] = Pa0[m][i].y + Pb0[m][i].y + bb.y;
                C[m][i][2] = Pa1[m][i].x + Pb1[m][i].x + bb.x;
                C[m][i][3] = Pa1[m][i].y + Pb1[m][i].y + bb.y;
            }

        // ---- issue next tile's gathers ----
        {
            int tn = t + 148;
            if (tn < NT_EDGE) DO_PREFETCH(tn * 32);
        }
        __syncthreads();   // A1 visible

        // ---- layer1 MMA: += ea @ W1c (k=16, 2-term) ----
        {
            uint4 h0 = *(const uint4*)(A1h + lane * 4);
            uint4 l0 = *(const uint4*)(A1l + lane * 4);
            uint4 h1 = *(const uint4*)(A1h + (32 + lane) * 4);
            uint4 l1 = *(const uint4*)(A1l + (32 + lane) * 4);
            u32 AH0[4] = {h0.x, h0.y, h0.z, h0.w}, AL0[4] = {l0.x, l0.y, l0.z, l0.w};
            u32 AH1[4] = {h1.x, h1.y, h1.z, h1.w}, AL1[4] = {l1.x, l1.y, l1.z, l1.w};
#pragma unroll
            for (int i = 0; i < 2; i++) {
                int fo = ((w * 2 + i) * 32 + lane) * 2;
                u32 bh0 = W1cH[fo], bh1 = W1cH[fo + 1];
                mma_f16(C[0][i], AH0, bh0, bh1);
                mma_f16(C[0][i], AL0, bh0, bh1);
                mma_f16(C[1][i], AH1, bh0, bh1);
                mma_f16(C[1][i], AL1, bh0, bh1);
            }
        }
#pragma unroll
        for (int m = 0; m < 2; m++)
#pragma unroll
            for (int i = 0; i < 2; i++) {
                int g = w * 2 + i;
                int base = ((m * 8 + (g >> 1)) * 32 + lane) * 4 + (g & 1) * 2;
                u32 hh, ll;
                packsplit(siluf(C[m][i][0]), siluf(C[m][i][1]), hh, ll);
                actH[base] = hh; actL[base] = ll;
                packsplit(siluf(C[m][i][2]), siluf(C[m][i][3]), hh, ll);
                actH[base + 1] = hh; actL[base + 1] = ll;
            }
        __syncthreads();   // y1 fragments ready

        // ---- layer2: ef = silu(y1 @ eW2 + b2) (2-term) ----
#pragma unroll
        for (int m = 0; m < 2; m++)
#pragma unroll
            for (int i = 0; i < 2; i++)
#pragma unroll
                for (int j = 0; j < 4; j++) C[m][i][j] = 0.f;
#pragma unroll
        for (int kt = 0; kt < 8; kt++) {
            uint4 h0 = *(const uint4*)(actH + (kt * 32 + lane) * 4);
            uint4 l0 = *(const uint4*)(actL + (kt * 32 + lane) * 4);
            uint4 h1 = *(const uint4*)(actH + ((8 + kt) * 32 + lane) * 4);
            uint4 l1 = *(const uint4*)(actL + ((8 + kt) * 32 + lane) * 4);
            u32 AH0[4] = {h0.x, h0.y, h0.z, h0.w}, AL0[4] = {l0.x, l0.y, l0.z, l0.w};
            u32 AH1[4] = {h1.x, h1.y, h1.z, h1.w}, AL1[4] = {l1.x, l1.y, l1.z, l1.w};
#pragma unroll
            for (int i = 0; i < 2; i++) {
                int fo = ((kt * 16 + (w * 2 + i)) * 32 + lane) * 2;
                u32 bh0 = W2h[fo], bh1 = W2h[fo + 1];
                mma_f16(C[0][i], AH0, bh0, bh1);
                mma_f16(C[0][i], AL0, bh0, bh1);
                mma_f16(C[1][i], AH1, bh0, bh1);
                mma_f16(C[1][i], AL1, bh0, bh1);
            }
        }
        __syncthreads();   // all reads of y1 done before overwrite
#pragma unroll
        for (int m = 0; m < 2; m++)
#pragma unroll
            for (int i = 0; i < 2; i++) {
                int g = w * 2 + i;
                int n0 = g * 8 + 2 * (lane & 3);
                float2 bb = *(const float2*)(sb2 + n0);
                int base = ((m * 8 + (g >> 1)) * 32 + lane) * 4 + (g & 1) * 2;
                u32 hh, ll;
                packsplit(siluf(C[m][i][0] + bb.x), siluf(C[m][i][1] + bb.y), hh, ll);
                actH[base] = hh; actL[base] = ll;
                packsplit(siluf(C[m][i][2] + bb.x), siluf(C[m][i][3] + bb.y), hh, ll);
                actH[base + 1] = hh; actL[base + 1] = ll;
            }
        __syncthreads();   // ef fragments ready

        // ---- heads fused (2-term each) ----
        {
            float C1[2][2][4], C2[2][2][4];
#pragma unroll
            for (int m = 0; m < 2; m++)
#pragma unroll
                for (int i = 0; i < 2; i++)
#pragma unroll
                    for (int j = 0; j < 4; j++) { C1[m][i][j] = 0.f; C2[m][i][j] = 0.f; }
#pragma unroll
            for (int kt = 0; kt < 8; kt++) {
                uint4 h0 = *(const uint4*)(actH + (kt * 32 + lane) * 4);
                uint4 l0 = *(const uint4*)(actL + (kt * 32 + lane) * 4);
                uint4 h1 = *(const uint4*)(actH + ((8 + kt) * 32 + lane) * 4);
                uint4 l1 = *(const uint4*)(actL + ((8 + kt) * 32 + lane) * 4);
                u32 AH0[4] = {h0.x, h0.y, h0.z, h0.w}, AL0[4] = {l0.x, l0.y, l0.z, l0.w};
                u32 AH1[4] = {h1.x, h1.y, h1.z, h1.w}, AL1[4] = {l1.x, l1.y, l1.z, l1.w};
#pragma unroll
                for (int i = 0; i < 2; i++) {
                    int fo = ((kt * 16 + (w * 2 + i)) * 32 + lane) * 2;
                    u32 p0 = V1h[fo], p1 = V1h[fo + 1];
                    mma_f16(C1[0][i], AH0, p0, p1);
                    mma_f16(C1[0][i], AL0, p0, p1);
                    mma_f16(C1[1][i], AH1, p0, p1);
                    mma_f16(C1[1][i], AL1, p0, p1);
                    u32 r0 = V2h[fo], r1 = V2h[fo + 1];
                    mma_f16(C2[0][i], AH0, r0, r1);
                    mma_f16(C2[0][i], AL0, r0, r1);
                    mma_f16(C2[1][i], AH1, r0, r1);
                    mma_f16(C2[1][i], AL1, r0, r1);
                }
            }
            float p1a[4] = {0.f, 0.f, 0.f, 0.f};
            float p2a[4] = {0.f, 0.f, 0.f, 0.f};
#pragma unroll
            for (int m = 0; m < 2; m++)
#pragma unroll
                for (int i = 0; i < 2; i++) {
                    int n0 = (w * 2 + i) * 8 + 2 * (lane & 3);
                    float2 bb1 = *(const float2*)(sv1b1 + n0);
                    float2 ww1 = *(const float2*)(sv1w2 + n0);
                    float2 bb2 = *(const float2*)(sv2b1 + n0);
                    float2 ww2 = *(const float2*)(sv2w2 + n0);
                    p1a[m * 2 + 0] += siluf(C1[m][i][0] + bb1.x) * ww1.x
                                    + siluf(C1[m][i][1] + bb1.y) * ww1.y;
                    p1a[m * 2 + 1] += siluf(C1[m][i][2] + bb1.x) * ww1.x
                                    + siluf(C1[m][i][3] + bb1.y) * ww1.y;
                    p2a[m * 2 + 0] += siluf(C2[m][i][0] + bb2.x) * ww2.x
                                    + siluf(C2[m][i][1] + bb2.y) * ww2.y;
                    p2a[m * 2 + 1] += siluf(C2[m][i][2] + bb2.x) * ww2.x
                                    + siluf(C2[m][i][3] + bb2.y) * ww2.y;
                }
#pragma unroll
            for (int j = 0; j < 4; j++) {
                p1a[j] += __shfl_xor_sync(0xffffffffu, p1a[j], 1);
                p1a[j] += __shfl_xor_sync(0xffffffffu, p1a[j], 2);
                p2a[j] += __shfl_xor_sync(0xffffffffu, p2a[j], 1);
                p2a[j] += __shfl_xor_sync(0xffffffffu, p2a[j], 2);
            }
            if ((lane & 3) == 0) {
                int r = lane >> 2;
                red1[w * 32 + r]           = p1a[0];
                red1[w * 32 + r + 8]       = p1a[1];
                red1[w * 32 + 16 + r]      = p1a[2];
                red1[w * 32 + 16 + r + 8]  = p1a[3];
                red2[w * 32 + r]           = p2a[0];
                red2[w * 32 + r + 8]       = p2a[1];
                red2[w * 32 + 16 + r]      = p2a[2];
                red2[w * 32 + 16 + r + 8]  = p2a[3];
            }
        }
        __syncthreads();

        // ---- scatter: sum partials directly (no extra barrier) ----
        if (tid < 96) {
            int e = tid / 3, d = tid - 3 * e;
            float s1 = c1, s2 = c2;
#pragma unroll
            for (int k = 0; k < 8; k++) {
                s1 += red1[k * 32 + e];
                s2 += red2[k * 32 + e];
            }
            int eg = tbase + e;
            int row = g_rows[eg], col = g_cols[eg];
            float rp = x[col * 3 + d] - x[row * 3 + d];
            atomicAdd(&g_vec1[row * 3 + d], rp * s1);
            atomicAdd(&g_vec2[row * 3 + d], rp * s2);
        }
    }
#undef DO_PREFETCH
}

// ---------------- finalize: Gram-Schmidt per node ----------------
__global__ void ol_finalize_kernel(float* __restrict__ out) {
    int n = blockIdx.x * blockDim.x + threadIdx.x;
    if (n >= NNODES) return;
    float v1x = g_vec1[n * 3 + 0], v1y = g_vec1[n * 3 + 1], v1z = g_vec1[n * 3 + 2];
    float v2x = g_vec2[n * 3 + 0], v2y = g_vec2[n * 3 + 1], v2z = g_vec2[n * 3 + 2];

    float n1 = fmaxf(sqrtf(v1x * v1x + v1y * v1y + v1z * v1z), 1e-12f);
    float e1x = v1x / n1, e1y = v1y / n1, e1z = v1z / n1;

    float dp = e1x * v2x + e1y * v2y + e1z * v2z;
    float px = v2x - dp * e1x, py = v2y - dp * e1y, pz = v2z - dp * e1z;
    float n2 = fmaxf(sqrtf(px * px + py * py + pz * pz), 1e-12f);
    float e2x = px / n2, e2y = py / n2, e2z = pz / n2;

    float e3x = e1y * e2z - e1z * e2y;
    float e3y = e1z * e2x - e1x * e2z;
    float e3z = e1x * e2y - e1y * e2x;

    float* o = out + n * 9;
    o[0] = e1x; o[1] = e2x; o[2] = e3x;
    o[3] = e1y; o[4] = e2y; o[5] = e3y;
    o[6] = e1z; o[7] = e2z; o[8] = e3z;
}

// ---------------- launch ----------------
extern "C" void kernel_launch(void* const* d_in, const int* in_sizes, int n_in,
                              void* d_out, int out_size) {
    const float* h         = (const float*)d_in[0];
    const float* x         = (const float*)d_in[1];
    const void*  ei        = d_in[2];
    const float* edge_attr = (const float*)d_in[3];
    const float* eW1 = (const float*)d_in[4];  const float* eb1 = (const float*)d_in[5];
    const float* eW2 = (const float*)d_in[6];  const float* eb2 = (const float*)d_in[7];
    const float* v1W1 = (const float*)d_in[8]; const float* v1b1 = (const float*)d_in[9];
    const float* v1W2 = (const float*)d_in[10]; const float* v1b2 = (const float*)d_in[11];
    const float* v2W1 = (const float*)d_in[12]; const float* v2b1 = (const float*)d_in[13];
    const float* v2W2 = (const float*)d_in[14]; const float* v2b2 = (const float*)d_in[15];
    float* out = (float*)d_out;

    cudaFuncSetAttribute(ol_precompute_kernel,
                         cudaFuncAttributeMaxDynamicSharedMemorySize, PRE_SMEM);
    cudaFuncSetAttribute(ol_edge_kernel,
                         cudaFuncAttributeMaxDynamicSharedMemorySize, EDGE_SMEM);

    ol_detect_kernel<<<1, 32>>>((const int*)ei);
    ol_convert_kernel<<<(NEDGES + 255) / 256, 256>>>(ei);
    ol_zero_kernel<<<(NNODES * 3 + 255) / 256, 256>>>();
    ol_precompute_kernel<<<(NNODES + 63) / 64, 256, PRE_SMEM>>>(h, eW1);
    ol_edge_kernel<<<148, 256, EDGE_SMEM>>>(x, edge_attr,
                                            eW1, eb1, eW2, eb2,
                                            v1W1, v1b1, v1W2, v1b2,
                                            v2W1, v2b1, v2W2, v2b2);
    ol_finalize_kernel<<<(NNODES + 255) / 256, 256>>>(out);
}

// round 15
// speedup vs baseline: 4.2723x; 1.0994x over previous
#include <cuda_runtime.h>
#include <cuda_fp16.h>
#include <math.h>

#define NNODES 50000
#define NEDGES 800000
#define HID    128
#define FE     16

typedef unsigned long long u64;
typedef unsigned int u32;

// ---------------- scratch ----------------
__device__ float g_Ha[NNODES * HID];
__device__ float g_Hb[NNODES * HID];
__device__ float g_vec1[NNODES * 3];
__device__ float g_vec2[NNODES * 3];
__device__ int   g_rows[NEDGES];
__device__ int   g_cols[NEDGES];
__device__ int   g_is64;

// ---------------- helpers ----------------
__device__ __forceinline__ u64 dup2(float s) {
    u64 r; asm("mov.b64 %0, {%1, %1};" : "=l"(r) : "f"(s)); return r;
}
__device__ __forceinline__ void fma2(u64& c, u64 a, u64 b) {
    asm("fma.rn.f32x2 %0, %1, %2, %3;" : "=l"(c) : "l"(a), "l"(b), "l"(c));
}
// silu via single-MUFU tanh: silu(x) = 0.5x(1 + tanh(x/2))
__device__ __forceinline__ float siluf(float v) {
    float hx = 0.5f * v, th;
    asm("tanh.approx.f32 %0, %1;" : "=f"(th) : "f"(hx));
    return fmaf(hx, th, hx);
}
__device__ __forceinline__ void cpf4(float* dst, const float* src, int nfloats,
                                     int tid, int nthreads) {
    const float4* s = reinterpret_cast<const float4*>(src);
    float4* d = reinterpret_cast<float4*>(dst);
    for (int i = tid; i < nfloats / 4; i += nthreads) d[i] = s[i];
}

// fp16x2 pack: even in low half
__device__ __forceinline__ u32 packh(float ev, float od) {
    u32 r; asm("cvt.rn.f16x2.f32 %0, %1, %2;" : "=r"(r) : "f"(od), "f"(ev)); return r;
}
__device__ __forceinline__ float hres(float v) {
    return v - __half2float(__float2half_rn(v));
}
__device__ __forceinline__ void packsplit(float ev, float od, u32& hi, u32& lo) {
    hi = packh(ev, od);
    lo = packh(hres(ev), hres(od));
}

// fp16 warp MMA: D(16x8,f32) += A(16x16) * B(16x8)
__device__ __forceinline__ void mma_f16(float* c, const u32* a, u32 b0, u32 b1) {
    asm volatile(
        "mma.sync.aligned.m16n8k16.row.col.f32.f16.f16.f32 "
        "{%0,%1,%2,%3}, {%4,%5,%6,%7}, {%8,%9}, {%0,%1,%2,%3};"
        : "+f"(c[0]), "+f"(c[1]), "+f"(c[2]), "+f"(c[3])
        : "r"(a[0]), "r"(a[1]), "r"(a[2]), "r"(a[3]), "r"(b0), "r"(b1));
}

// ---------------- dtype detection + index canonicalization ------------------
__global__ void ol_detect_kernel(const int* __restrict__ ei32) {
    if (threadIdx.x == 0 && blockIdx.x == 0) {
        int any = 0;
#pragma unroll
        for (int i = 0; i < 64; i++) any |= ei32[2 * i + 1];
        g_is64 = (any == 0) ? 1 : 0;
    }
}
__global__ void ol_convert_kernel(const void* __restrict__ eiv) {
    int i = blockIdx.x * blockDim.x + threadIdx.x;
    if (i >= NEDGES) return;
    if (g_is64) {
        const long long* e = (const long long*)eiv;
        g_rows[i] = (int)e[i];
        g_cols[i] = (int)e[NEDGES + i];
    } else {
        const int* e = (const int*)eiv;
        g_rows[i] = e[i];
        g_cols[i] = e[NEDGES + i];
    }
}
__global__ void ol_zero_kernel() {
    int i = blockIdx.x * blockDim.x + threadIdx.x;
    if (i < NNODES * 3) { g_vec1[i] = 0.0f; g_vec2[i] = 0.0f; }
}

// ---------------- node precompute (R4 version, known-good ~96us, no spill) --
#define PRE_SMEM ((256 * 128 + 8 * 8 * 128) * 4)
__global__ void __launch_bounds__(256, 1)
ol_precompute_kernel(const float* __restrict__ h, const float* __restrict__ eW1) {
    extern __shared__ float smem[];
    float* Wab = smem;
    float* act = smem + 256 * 128;

    cpf4(Wab, eW1, 256 * 128, threadIdx.x, 256);
    __syncthreads();

    const int warp = threadIdx.x >> 5, lane = threadIdx.x & 31;
    float* myAct = act + warp * (8 * 128);
    float4* myAct4 = reinterpret_cast<float4*>(myAct);
    const int n0 = (blockIdx.x * 8 + warp) * 8;

#pragma unroll
    for (int e = 0; e < 8; e++) {
        int n = n0 + e;
        float4 v = make_float4(0.f, 0.f, 0.f, 0.f);
        if (n < NNODES) v = reinterpret_cast<const float4*>(h)[n * 32 + lane];
        myAct4[e * 32 + lane] = v;
    }
    __syncwarp();

    u64 accA0[8], accA1[8], accB0[8], accB1[8];
#pragma unroll
    for (int e = 0; e < 8; e++) {
        accA0[e] = 0ull; accA1[e] = 0ull; accB0[e] = 0ull; accB1[e] = 0ull;
    }
    const ulonglong2* Wab2 = reinterpret_cast<const ulonglong2*>(Wab);
    for (int kb = 0; kb < 32; kb++) {
        ulonglong2 wa0 = Wab2[(4 * kb + 0) * 32 + lane];
        ulonglong2 wa1 = Wab2[(4 * kb + 1) * 32 + lane];
        ulonglong2 wa2 = Wab2[(4 * kb + 2) * 32 + lane];
        ulonglong2 wa3 = Wab2[(4 * kb + 3) * 32 + lane];
        ulonglong2 wb0 = Wab2[(128 + 4 * kb + 0) * 32 + lane];
        ulonglong2 wb1 = Wab2[(128 + 4 * kb + 1) * 32 + lane];
        ulonglong2 wb2 = Wab2[(128 + 4 * kb + 2) * 32 + lane];
        ulonglong2 wb3 = Wab2[(128 + 4 * kb + 3) * 32 + lane];
#pragma unroll
        for (int e = 0; e < 8; e++) {
            float4 a = myAct4[e * 32 + kb];
            u64 dx = dup2(a.x), dy = dup2(a.y), dz = dup2(a.z), dw = dup2(a.w);
            fma2(accA0[e], dx, wa0.x); fma2(accA1[e], dx, wa0.y);
            fma2(accA0[e], dy, wa1.x); fma2(accA1[e], dy, wa1.y);
            fma2(accA0[e], dz, wa2.x); fma2(accA1[e], dz, wa2.y);
            fma2(accA0[e], dw, wa3.x); fma2(accA1[e], dw, wa3.y);
            fma2(accB0[e], dx, wb0.x); fma2(accB1[e], dx, wb0.y);
            fma2(accB0[e], dy, wb1.x); fma2(accB1[e], dy, wb1.y);
            fma2(accB0[e], dz, wb2.x); fma2(accB1[e], dz, wb2.y);
            fma2(accB0[e], dw, wb3.x); fma2(accB1[e], dw, wb3.y);
        }
    }
#pragma unroll
    for (int e = 0; e < 8; e++) {
        int n = n0 + e;
        if (n < NNODES) {
            reinterpret_cast<ulonglong2*>(g_Ha)[n * 32 + lane] =
                make_ulonglong2(accA0[e], accA1[e]);
            reinterpret_cast<ulonglong2*>(g_Hb)[n * 32 + lane] =
                make_ulonglong2(accB0[e], accB1[e]);
        }
    }
}

// ---------------- fragment prepack (fp16 hi only) ----------------
__device__ void pack_wfrag(u32* Bh, const float* __restrict__ W,
                           int tid, int nthreads) {
    for (int idx = tid; idx < 4096; idx += nthreads) {
        int kt = idx >> 9, nt = (idx >> 5) & 15, l = idx & 31;
        int n = nt * 8 + (l >> 2), k0 = kt * 16 + (l & 3) * 2;
        Bh[idx * 2]     = packh(W[k0 * 128 + n],       W[(k0 + 1) * 128 + n]);
        Bh[idx * 2 + 1] = packh(W[(k0 + 8) * 128 + n], W[(k0 + 9) * 128 + n]);
    }
}
__device__ void pack_w1c(u32* Bh, const float* __restrict__ W,
                         int tid, int nthreads) {
    for (int idx = tid; idx < 512; idx += nthreads) {
        int nt = idx >> 5, l = idx & 31;
        int n = nt * 8 + (l >> 2), k0 = (l & 3) * 2;
        Bh[idx * 2]     = packh(W[k0 * 128 + n],       W[(k0 + 1) * 128 + n]);
        Bh[idx * 2 + 1] = packh(W[(k0 + 8) * 128 + n], W[(k0 + 9) * 128 + n]);
    }
}

// ---------------- tensor-core edge kernel (fp16 2-term, ping-pong act) ------
// smem u32 layout:
//  0 sb1 |128 sb2 |256 sv1b1 |384 sv2b1 |512 sv1w2 |640 sv2w2 |
//  768 red1(256) |1024 red2(256) |1280 A1h(256) |1536 A1l(256) |
//  1792 W1cH(1024) |2816 actHA(2048) |4864 actLA(2048) |
//  6912 W2h(8192) |15104 V1h(8192) |23296 V2h(8192) |
//  31488 actHB(2048) |33536 actLB(2048) | end 35584
#define EDGE_SMEM (35584 * 4)
#define NT_EDGE  (NEDGES / 32)

__global__ void __launch_bounds__(256, 1)
ol_edge_kernel(const float* __restrict__ x,
               const float* __restrict__ edge_attr,
               const float* __restrict__ eW1, const float* __restrict__ eb1,
               const float* __restrict__ eW2, const float* __restrict__ eb2,
               const float* __restrict__ v1W1, const float* __restrict__ v1b1,
               const float* __restrict__ v1W2, const float* __restrict__ v1b2,
               const float* __restrict__ v2W1, const float* __restrict__ v2b1,
               const float* __restrict__ v2W2, const float* __restrict__ v2b2) {
    extern __shared__ float smem[];
    u32* su = (u32*)smem;

    float* sb1   = smem + 0;
    float* sb2   = smem + 128;
    float* sv1b1 = smem + 256;
    float* sv2b1 = smem + 384;
    float* sv1w2 = smem + 512;
    float* sv2w2 = smem + 640;
    float* red1  = smem + 768;    // 8 warps x 32
    float* red2  = smem + 1024;
    u32* A1h   = su + 1280;
    u32* A1l   = su + 1536;
    u32* W1cH  = su + 1792;
    u32* actHA = su + 2816;
    u32* actLA = su + 4864;
    u32* W2h   = su + 6912;
    u32* V1h   = su + 15104;
    u32* V2h   = su + 23296;
    u32* actHB = su + 31488;
    u32* actLB = su + 33536;

    const int tid = threadIdx.x;
    const int w = tid >> 5, lane = tid & 31;

    cpf4(sb1, eb1, 128, tid, 256);
    cpf4(sb2, eb2, 128, tid, 256);
    cpf4(sv1b1, v1b1, 128, tid, 256);
    cpf4(sv2b1, v2b1, 128, tid, 256);
    cpf4(sv1w2, v1W2, 128, tid, 256);
    cpf4(sv2w2, v2W2, 128, tid, 256);
    pack_w1c(W1cH, eW1 + 256 * 128, tid, 256);
    pack_wfrag(W2h, eW2, tid, 256);
    pack_wfrag(V1h, v1W1, tid, 256);
    pack_wfrag(V2h, v2W1, tid, 256);
    __syncthreads();

    const float c1 = __ldg(v1b2);
    const float c2 = __ldg(v2b2);

    // ---- pipelined gather state (registers) ----
    float2 Pa0[2][2], Pb0[2][2], Pa1[2][2], Pb1[2][2];
    float2 Q0, Q1, Q2, Q3;

#define DO_PREFETCH(TB) do {                                                   \
    _Pragma("unroll")                                                          \
    for (int m = 0; m < 2; m++) {                                              \
        int e0 = (TB) + m * 16 + (lane >> 2);                                  \
        int e1 = e0 + 8;                                                       \
        int rA = g_rows[e0], cA = g_cols[e0];                                  \
        int rB = g_rows[e1], cB = g_cols[e1];                                  \
        _Pragma("unroll")                                                      \
        for (int i = 0; i < 2; i++) {                                          \
            int n0 = (w * 2 + i) * 8 + 2 * (lane & 3);                         \
            Pa0[m][i] = *(const float2*)(g_Ha + (size_t)rA * 128 + n0);        \
            Pb0[m][i] = *(const float2*)(g_Hb + (size_t)cA * 128 + n0);        \
            Pa1[m][i] = *(const float2*)(g_Ha + (size_t)rB * 128 + n0);        \
            Pb1[m][i] = *(const float2*)(g_Hb + (size_t)cB * 128 + n0);        \
        }                                                                      \
    }                                                                          \
    if (tid < 64) {                                                            \
        int m = tid >> 5, l = tid & 31;                                        \
        int r = l >> 2, k0 = (l & 3) * 2;                                      \
        const float* ep0 = edge_attr + (size_t)((TB) + m * 16 + r) * 16;       \
        const float* ep1 = edge_attr + (size_t)((TB) + m * 16 + r + 8) * 16;   \
        Q0 = *(const float2*)(ep0 + k0);                                       \
        Q1 = *(const float2*)(ep1 + k0);                                       \
        Q2 = *(const float2*)(ep0 + k0 + 8);                                   \
        Q3 = *(const float2*)(ep1 + k0 + 8);                                   \
    }                                                                          \
} while (0)

    if (blockIdx.x < NT_EDGE) DO_PREFETCH(blockIdx.x * 32);

    for (int t = blockIdx.x; t < NT_EDGE; t += 148) {
        const int tbase = t * 32;

        // ---- A1 store from prefetched edge_attr (tid<64) ----
        if (tid < 64) {
            int m = tid >> 5, l = tid & 31;
            int o = (m * 32 + l) * 4;
            u32 hh, ll;
            packsplit(Q0.x, Q0.y, hh, ll); A1h[o] = hh;     A1l[o] = ll;
            packsplit(Q1.x, Q1.y, hh, ll); A1h[o + 1] = hh; A1l[o + 1] = ll;
            packsplit(Q2.x, Q2.y, hh, ll); A1h[o + 2] = hh; A1l[o + 2] = ll;
            packsplit(Q3.x, Q3.y, hh, ll); A1h[o + 3] = hh; A1l[o + 3] = ll;
        }

        // ---- layer1 C init from prefetched Ha/Hb ----
        float C[2][2][4];
#pragma unroll
        for (int m = 0; m < 2; m++)
#pragma unroll
            for (int i = 0; i < 2; i++) {
                int n0 = (w * 2 + i) * 8 + 2 * (lane & 3);
                float2 bb = *(const float2*)(sb1 + n0);
                C[m][i][0] = Pa0[m][i].x + Pb0[m][i].x + bb.x;
                C[m][i][1] = Pa0[m][i].y + Pb0[m][i].y + bb.y;
                C[m][i][2] = Pa1[m][i].x + Pb1[m][i].x + bb.x;
                C[m][i][3] = Pa1[m][i].y + Pb1[m][i].y + bb.y;
            }

        // ---- issue next tile's gathers ----
        {
            int tn = t + 148;
            if (tn < NT_EDGE) DO_PREFETCH(tn * 32);
        }
        __syncthreads();   // barrier 1: A1 visible; prev-tile bufA reads done

        // ---- layer1 MMA: += ea @ W1c (k=16, 2-term) ----
        {
            uint4 h0 = *(const uint4*)(A1h + lane * 4);
            uint4 l0 = *(const uint4*)(A1l + lane * 4);
            uint4 h1 = *(const uint4*)(A1h + (32 + lane) * 4);
            uint4 l1 = *(const uint4*)(A1l + (32 + lane) * 4);
            u32 AH0[4] = {h0.x, h0.y, h0.z, h0.w}, AL0[4] = {l0.x, l0.y, l0.z, l0.w};
            u32 AH1[4] = {h1.x, h1.y, h1.z, h1.w}, AL1[4] = {l1.x, l1.y, l1.z, l1.w};
#pragma unroll
            for (int i = 0; i < 2; i++) {
                int fo = ((w * 2 + i) * 32 + lane) * 2;
                u32 bh0 = W1cH[fo], bh1 = W1cH[fo + 1];
                mma_f16(C[0][i], AH0, bh0, bh1);
                mma_f16(C[0][i], AL0, bh0, bh1);
                mma_f16(C[1][i], AH1, bh0, bh1);
                mma_f16(C[1][i], AL1, bh0, bh1);
            }
        }
        // y1 -> bufA
#pragma unroll
        for (int m = 0; m < 2; m++)
#pragma unroll
            for (int i = 0; i < 2; i++) {
                int g = w * 2 + i;
                int base = ((m * 8 + (g >> 1)) * 32 + lane) * 4 + (g & 1) * 2;
                u32 hh, ll;
                packsplit(siluf(C[m][i][0]), siluf(C[m][i][1]), hh, ll);
                actHA[base] = hh; actLA[base] = ll;
                packsplit(siluf(C[m][i][2]), siluf(C[m][i][3]), hh, ll);
                actHA[base + 1] = hh; actLA[base + 1] = ll;
            }
        __syncthreads();   // barrier 2: y1 (bufA) ready

        // ---- layer2: ef = silu(y1 @ eW2 + b2) -> bufB (no WAR barrier) ----
#pragma unroll
        for (int m = 0; m < 2; m++)
#pragma unroll
            for (int i = 0; i < 2; i++)
#pragma unroll
                for (int j = 0; j < 4; j++) C[m][i][j] = 0.f;
#pragma unroll
        for (int kt = 0; kt < 8; kt++) {
            uint4 h0 = *(const uint4*)(actHA + (kt * 32 + lane) * 4);
            uint4 l0 = *(const uint4*)(actLA + (kt * 32 + lane) * 4);
            uint4 h1 = *(const uint4*)(actHA + ((8 + kt) * 32 + lane) * 4);
            uint4 l1 = *(const uint4*)(actLA + ((8 + kt) * 32 + lane) * 4);
            u32 AH0[4] = {h0.x, h0.y, h0.z, h0.w}, AL0[4] = {l0.x, l0.y, l0.z, l0.w};
            u32 AH1[4] = {h1.x, h1.y, h1.z, h1.w}, AL1[4] = {l1.x, l1.y, l1.z, l1.w};
#pragma unroll
            for (int i = 0; i < 2; i++) {
                int fo = ((kt * 16 + (w * 2 + i)) * 32 + lane) * 2;
                u32 bh0 = W2h[fo], bh1 = W2h[fo + 1];
                mma_f16(C[0][i], AH0, bh0, bh1);
                mma_f16(C[0][i], AL0, bh0, bh1);
                mma_f16(C[1][i], AH1, bh0, bh1);
                mma_f16(C[1][i], AL1, bh0, bh1);
            }
        }
#pragma unroll
        for (int m = 0; m < 2; m++)
#pragma unroll
            for (int i = 0; i < 2; i++) {
                int g = w * 2 + i;
                int n0 = g * 8 + 2 * (lane & 3);
                float2 bb = *(const float2*)(sb2 + n0);
                int base = ((m * 8 + (g >> 1)) * 32 + lane) * 4 + (g & 1) * 2;
                u32 hh, ll;
                packsplit(siluf(C[m][i][0] + bb.x), siluf(C[m][i][1] + bb.y), hh, ll);
                actHB[base] = hh; actLB[base] = ll;
                packsplit(siluf(C[m][i][2] + bb.x), siluf(C[m][i][3] + bb.y), hh, ll);
                actHB[base + 1] = hh; actLB[base + 1] = ll;
            }
        __syncthreads();   // barrier 3: ef (bufB) ready

        // ---- heads fused (2-term each), read bufB ----
        {
            float C1[2][2][4], C2[2][2][4];
#pragma unroll
            for (int m = 0; m < 2; m++)
#pragma unroll
                for (int i = 0; i < 2; i++)
#pragma unroll
                    for (int j = 0; j < 4; j++) { C1[m][i][j] = 0.f; C2[m][i][j] = 0.f; }
#pragma unroll
            for (int kt = 0; kt < 8; kt++) {
                uint4 h0 = *(const uint4*)(actHB + (kt * 32 + lane) * 4);
                uint4 l0 = *(const uint4*)(actLB + (kt * 32 + lane) * 4);
                uint4 h1 = *(const uint4*)(actHB + ((8 + kt) * 32 + lane) * 4);
                uint4 l1 = *(const uint4*)(actLB + ((8 + kt) * 32 + lane) * 4);
                u32 AH0[4] = {h0.x, h0.y, h0.z, h0.w}, AL0[4] = {l0.x, l0.y, l0.z, l0.w};
                u32 AH1[4] = {h1.x, h1.y, h1.z, h1.w}, AL1[4] = {l1.x, l1.y, l1.z, l1.w};
#pragma unroll
                for (int i = 0; i < 2; i++) {
                    int fo = ((kt * 16 + (w * 2 + i)) * 32 + lane) * 2;
                    u32 p0 = V1h[fo], p1 = V1h[fo + 1];
                    mma_f16(C1[0][i], AH0, p0, p1);
                    mma_f16(C1[0][i], AL0, p0, p1);
                    mma_f16(C1[1][i], AH1, p0, p1);
                    mma_f16(C1[1][i], AL1, p0, p1);
                    u32 r0 = V2h[fo], r1 = V2h[fo + 1];
                    mma_f16(C2[0][i], AH0, r0, r1);
                    mma_f16(C2[0][i], AL0, r0, r1);
                    mma_f16(C2[1][i], AH1, r0, r1);
                    mma_f16(C2[1][i], AL1, r0, r1);
                }
            }
            float p1a[4] = {0.f, 0.f, 0.f, 0.f};
            float p2a[4] = {0.f, 0.f, 0.f, 0.f};
#pragma unroll
            for (int m = 0; m < 2; m++)
#pragma unroll
                for (int i = 0; i < 2; i++) {
                    int n0 = (w * 2 + i) * 8 + 2 * (lane & 3);
                    float2 bb1 = *(const float2*)(sv1b1 + n0);
                    float2 ww1 = *(const float2*)(sv1w2 + n0);
                    float2 bb2 = *(const float2*)(sv2b1 + n0);
                    float2 ww2 = *(const float2*)(sv2w2 + n0);
                    p1a[m * 2 + 0] += siluf(C1[m][i][0] + bb1.x) * ww1.x
                                    + siluf(C1[m][i][1] + bb1.y) * ww1.y;
                    p1a[m * 2 + 1] += siluf(C1[m][i][2] + bb1.x) * ww1.x
                                    + siluf(C1[m][i][3] + bb1.y) * ww1.y;
                    p2a[m * 2 + 0] += siluf(C2[m][i][0] + bb2.x) * ww2.x
                                    + siluf(C2[m][i][1] + bb2.y) * ww2.y;
                    p2a[m * 2 + 1] += siluf(C2[m][i][2] + bb2.x) * ww2.x
                                    + siluf(C2[m][i][3] + bb2.y) * ww2.y;
                }
#pragma unroll
            for (int j = 0; j < 4; j++) {
                p1a[j] += __shfl_xor_sync(0xffffffffu, p1a[j], 1);
                p1a[j] += __shfl_xor_sync(0xffffffffu, p1a[j], 2);
                p2a[j] += __shfl_xor_sync(0xffffffffu, p2a[j], 1);
                p2a[j] += __shfl_xor_sync(0xffffffffu, p2a[j], 2);
            }
            if ((lane & 3) == 0) {
                int r = lane >> 2;
                red1[w * 32 + r]           = p1a[0];
                red1[w * 32 + r + 8]       = p1a[1];
                red1[w * 32 + 16 + r]      = p1a[2];
                red1[w * 32 + 16 + r + 8]  = p1a[3];
                red2[w * 32 + r]           = p2a[0];
                red2[w * 32 + r + 8]       = p2a[1];
                red2[w * 32 + 16 + r]      = p2a[2];
                red2[w * 32 + 16 + r + 8]  = p2a[3];
            }
        }
        __syncthreads();   // barrier 4: reductions visible

        // ---- scatter: sum partials directly ----
        if (tid < 96) {
            int e = tid / 3, d = tid - 3 * e;
            float s1 = c1, s2 = c2;
#pragma unroll
            for (int k = 0; k < 8; k++) {
                s1 += red1[k * 32 + e];
                s2 += red2[k * 32 + e];
            }
            int eg = tbase + e;
            int row = g_rows[eg], col = g_cols[eg];
            float rp = x[col * 3 + d] - x[row * 3 + d];
            atomicAdd(&g_vec1[row * 3 + d], rp * s1);
            atomicAdd(&g_vec2[row * 3 + d], rp * s2);
        }
    }
#undef DO_PREFETCH
}

// ---------------- finalize: Gram-Schmidt per node ----------------
__global__ void ol_finalize_kernel(float* __restrict__ out) {
    int n = blockIdx.x * blockDim.x + threadIdx.x;
    if (n >= NNODES) return;
    float v1x = g_vec1[n * 3 + 0], v1y = g_vec1[n * 3 + 1], v1z = g_vec1[n * 3 + 2];
    float v2x = g_vec2[n * 3 + 0], v2y = g_vec2[n * 3 + 1], v2z = g_vec2[n * 3 + 2];

    float n1 = fmaxf(sqrtf(v1x * v1x + v1y * v1y + v1z * v1z), 1e-12f);
    float e1x = v1x / n1, e1y = v1y / n1, e1z = v1z / n1;

    float dp = e1x * v2x + e1y * v2y + e1z * v2z;
    float px = v2x - dp * e1x, py = v2y - dp * e1y, pz = v2z - dp * e1z;
    float n2 = fmaxf(sqrtf(px * px + py * py + pz * pz), 1e-12f);
    float e2x = px / n2, e2y = py / n2, e2z = pz / n2;

    float e3x = e1y * e2z - e1z * e2y;
    float e3y = e1z * e2x - e1x * e2z;
    float e3z = e1x * e2y - e1y * e2x;

    float* o = out + n * 9;
    o[0] = e1x; o[1] = e2x; o[2] = e3x;
    o[3] = e1y; o[4] = e2y; o[5] = e3y;
    o[6] = e1z; o[7] = e2z; o[8] = e3z;
}

// ---------------- launch ----------------
extern "C" void kernel_launch(void* const* d_in, const int* in_sizes, int n_in,
                              void* d_out, int out_size) {
    const float* h         = (const float*)d_in[0];
    const float* x         = (const float*)d_in[1];
    const void*  ei        = d_in[2];
    const float* edge_attr = (const float*)d_in[3];
    const float* eW1 = (const float*)d_in[4];  const float* eb1 = (const float*)d_in[5];
    const float* eW2 = (const float*)d_in[6];  const float* eb2 = (const float*)d_in[7];
    const float* v1W1 = (const float*)d_in[8]; const float* v1b1 = (const float*)d_in[9];
    const float* v1W2 = (const float*)d_in[10]; const float* v1b2 = (const float*)d_in[11];
    const float* v2W1 = (const float*)d_in[12]; const float* v2b1 = (const float*)d_in[13];
    const float* v2W2 = (const float*)d_in[14]; const float* v2b2 = (const float*)d_in[15];
    float* out = (float*)d_out;

    cudaFuncSetAttribute(ol_precompute_kernel,
                         cudaFuncAttributeMaxDynamicSharedMemorySize, PRE_SMEM);
    cudaFuncSetAttribute(ol_edge_kernel,
                         cudaFuncAttributeMaxDynamicSharedMemorySize, EDGE_SMEM);

    ol_detect_kernel<<<1, 32>>>((const int*)ei);
    ol_convert_kernel<<<(NEDGES + 255) / 256, 256>>>(ei);
    ol_zero_kernel<<<(NNODES * 3 + 255) / 256, 256>>>();
    ol_precompute_kernel<<<(NNODES + 63) / 64, 256, PRE_SMEM>>>(h, eW1);
    ol_edge_kernel<<<148, 256, EDGE_SMEM>>>(x, edge_attr,
                                            eW1, eb1, eW2, eb2,
                                            v1W1, v1b1, v1W2, v1b2,
                                            v2W1, v2b1, v2W2, v2b2);
    ol_finalize_kernel<<<(NNODES + 255) / 256, 256>>>(out);
}

// round 16
// speedup vs baseline: 4.6860x; 1.0968x over previous
#include <cuda_runtime.h>
#include <cuda_fp16.h>
#include <math.h>

#define NNODES 50000
#define NEDGES 800000
#define HID    128
#define FE     16

typedef unsigned long long u64;
typedef unsigned int u32;

// ---------------- scratch ----------------
__device__ float g_Ha[NNODES * HID];
__device__ float g_Hb[NNODES * HID];
__device__ float g_vec1[NNODES * 3];
__device__ float g_vec2[NNODES * 3];
__device__ int   g_rows[NEDGES];
__device__ int   g_cols[NEDGES];
__device__ int   g_is64;

// ---------------- helpers ----------------
__device__ __forceinline__ u64 dup2(float s) {
    u64 r; asm("mov.b64 %0, {%1, %1};" : "=l"(r) : "f"(s)); return r;
}
__device__ __forceinline__ void fma2(u64& c, u64 a, u64 b) {
    asm("fma.rn.f32x2 %0, %1, %2, %3;" : "=l"(c) : "l"(a), "l"(b), "l"(c));
}
// silu via single-MUFU tanh: silu(x) = 0.5x(1 + tanh(x/2))
__device__ __forceinline__ float siluf(float v) {
    float hx = 0.5f * v, th;
    asm("tanh.approx.f32 %0, %1;" : "=f"(th) : "f"(hx));
    return fmaf(hx, th, hx);
}
__device__ __forceinline__ void cpf4(float* dst, const float* src, int nfloats,
                                     int tid, int nthreads) {
    const float4* s = reinterpret_cast<const float4*>(src);
    float4* d = reinterpret_cast<float4*>(dst);
    for (int i = tid; i < nfloats / 4; i += nthreads) d[i] = s[i];
}

// fp16x2 pack: even in low half
__device__ __forceinline__ u32 packh(float ev, float od) {
    u32 r; asm("cvt.rn.f16x2.f32 %0, %1, %2;" : "=r"(r) : "f"(od), "f"(ev)); return r;
}
__device__ __forceinline__ float hres(float v) {
    return v - __half2float(__float2half_rn(v));
}
__device__ __forceinline__ void packsplit(float ev, float od, u32& hi, u32& lo) {
    hi = packh(ev, od);
    lo = packh(hres(ev), hres(od));
}

// fp16 warp MMA: D(16x8,f32) += A(16x16) * B(16x8)
__device__ __forceinline__ void mma_f16(float* c, const u32* a, u32 b0, u32 b1) {
    asm volatile(
        "mma.sync.aligned.m16n8k16.row.col.f32.f16.f16.f32 "
        "{%0,%1,%2,%3}, {%4,%5,%6,%7}, {%8,%9}, {%0,%1,%2,%3};"
        : "+f"(c[0]), "+f"(c[1]), "+f"(c[2]), "+f"(c[3])
        : "r"(a[0]), "r"(a[1]), "r"(a[2]), "r"(a[3]), "r"(b0), "r"(b1));
}

// ---------------- dtype detection + index canonicalization ------------------
__global__ void ol_detect_kernel(const int* __restrict__ ei32) {
    if (threadIdx.x == 0 && blockIdx.x == 0) {
        int any = 0;
#pragma unroll
        for (int i = 0; i < 64; i++) any |= ei32[2 * i + 1];
        g_is64 = (any == 0) ? 1 : 0;
    }
}
__global__ void ol_convert_kernel(const void* __restrict__ eiv) {
    int i = blockIdx.x * blockDim.x + threadIdx.x;
    if (i >= NEDGES) return;
    if (g_is64) {
        const long long* e = (const long long*)eiv;
        g_rows[i] = (int)e[i];
        g_cols[i] = (int)e[NEDGES + i];
    } else {
        const int* e = (const int*)eiv;
        g_rows[i] = e[i];
        g_cols[i] = e[NEDGES + i];
    }
}
__global__ void ol_zero_kernel() {
    int i = blockIdx.x * blockDim.x + threadIdx.x;
    if (i < NNODES * 3) { g_vec1[i] = 0.0f; g_vec2[i] = 0.0f; }
}

// ---------------- node precompute (R4 version, known-good ~96us, no spill) --
#define PRE_SMEM ((256 * 128 + 8 * 8 * 128) * 4)
__global__ void __launch_bounds__(256, 1)
ol_precompute_kernel(const float* __restrict__ h, const float* __restrict__ eW1) {
    extern __shared__ float smem[];
    float* Wab = smem;
    float* act = smem + 256 * 128;

    cpf4(Wab, eW1, 256 * 128, threadIdx.x, 256);
    __syncthreads();

    const int warp = threadIdx.x >> 5, lane = threadIdx.x & 31;
    float* myAct = act + warp * (8 * 128);
    float4* myAct4 = reinterpret_cast<float4*>(myAct);
    const int n0 = (blockIdx.x * 8 + warp) * 8;

#pragma unroll
    for (int e = 0; e < 8; e++) {
        int n = n0 + e;
        float4 v = make_float4(0.f, 0.f, 0.f, 0.f);
        if (n < NNODES) v = reinterpret_cast<const float4*>(h)[n * 32 + lane];
        myAct4[e * 32 + lane] = v;
    }
    __syncwarp();

    u64 accA0[8], accA1[8], accB0[8], accB1[8];
#pragma unroll
    for (int e = 0; e < 8; e++) {
        accA0[e] = 0ull; accA1[e] = 0ull; accB0[e] = 0ull; accB1[e] = 0ull;
    }
    const ulonglong2* Wab2 = reinterpret_cast<const ulonglong2*>(Wab);
    for (int kb = 0; kb < 32; kb++) {
        ulonglong2 wa0 = Wab2[(4 * kb + 0) * 32 + lane];
        ulonglong2 wa1 = Wab2[(4 * kb + 1) * 32 + lane];
        ulonglong2 wa2 = Wab2[(4 * kb + 2) * 32 + lane];
        ulonglong2 wa3 = Wab2[(4 * kb + 3) * 32 + lane];
        ulonglong2 wb0 = Wab2[(128 + 4 * kb + 0) * 32 + lane];
        ulonglong2 wb1 = Wab2[(128 + 4 * kb + 1) * 32 + lane];
        ulonglong2 wb2 = Wab2[(128 + 4 * kb + 2) * 32 + lane];
        ulonglong2 wb3 = Wab2[(128 + 4 * kb + 3) * 32 + lane];
#pragma unroll
        for (int e = 0; e < 8; e++) {
            float4 a = myAct4[e * 32 + kb];
            u64 dx = dup2(a.x), dy = dup2(a.y), dz = dup2(a.z), dw = dup2(a.w);
            fma2(accA0[e], dx, wa0.x); fma2(accA1[e], dx, wa0.y);
            fma2(accA0[e], dy, wa1.x); fma2(accA1[e], dy, wa1.y);
            fma2(accA0[e], dz, wa2.x); fma2(accA1[e], dz, wa2.y);
            fma2(accA0[e], dw, wa3.x); fma2(accA1[e], dw, wa3.y);
            fma2(accB0[e], dx, wb0.x); fma2(accB1[e], dx, wb0.y);
            fma2(accB0[e], dy, wb1.x); fma2(accB1[e], dy, wb1.y);
            fma2(accB0[e], dz, wb2.x); fma2(accB1[e], dz, wb2.y);
            fma2(accB0[e], dw, wb3.x); fma2(accB1[e], dw, wb3.y);
        }
    }
#pragma unroll
    for (int e = 0; e < 8; e++) {
        int n = n0 + e;
        if (n < NNODES) {
            reinterpret_cast<ulonglong2*>(g_Ha)[n * 32 + lane] =
                make_ulonglong2(accA0[e], accA1[e]);
            reinterpret_cast<ulonglong2*>(g_Hb)[n * 32 + lane] =
                make_ulonglong2(accB0[e], accB1[e]);
        }
    }
}

// ---------------- fragment prepack (fp16 hi only) ----------------
__device__ void pack_wfrag(u32* Bh, const float* __restrict__ W,
                           int tid, int nthreads) {
    for (int idx = tid; idx < 4096; idx += nthreads) {
        int kt = idx >> 9, nt = (idx >> 5) & 15, l = idx & 31;
        int n = nt * 8 + (l >> 2), k0 = kt * 16 + (l & 3) * 2;
        Bh[idx * 2]     = packh(W[k0 * 128 + n],       W[(k0 + 1) * 128 + n]);
        Bh[idx * 2 + 1] = packh(W[(k0 + 8) * 128 + n], W[(k0 + 9) * 128 + n]);
    }
}
__device__ void pack_w1c(u32* Bh, const float* __restrict__ W,
                         int tid, int nthreads) {
    for (int idx = tid; idx < 512; idx += nthreads) {
        int nt = idx >> 5, l = idx & 31;
        int n = nt * 8 + (l >> 2), k0 = (l & 3) * 2;
        Bh[idx * 2]     = packh(W[k0 * 128 + n],       W[(k0 + 1) * 128 + n]);
        Bh[idx * 2 + 1] = packh(W[(k0 + 8) * 128 + n], W[(k0 + 9) * 128 + n]);
    }
}

// ---------------- tensor-core edge kernel (fp16 2-term, 64-edge tiles) ------
// smem u32 layout:
//  0 sb1 |128 sb2 |256 sv1b1 |384 sv2b1 |512 sv1w2 |640 sv2w2 |
//  768 red1(512) |1280 red2(512) |1792 A1h(512) |2304 A1l(512) |
//  2816 W1cH(1024) |3840 W2h(8192) |12032 V1h(8192) |20224 V2h(8192) |
//  28416 actHA(4096) |32512 actLA(4096) |36608 actHB(4096) |40704 actLB(4096)
//  end 44800
#define EDGE_SMEM (44800 * 4)
#define NT_EDGE  (NEDGES / 64)

__global__ void __launch_bounds__(256, 1)
ol_edge_kernel(const float* __restrict__ x,
               const float* __restrict__ edge_attr,
               const float* __restrict__ eW1, const float* __restrict__ eb1,
               const float* __restrict__ eW2, const float* __restrict__ eb2,
               const float* __restrict__ v1W1, const float* __restrict__ v1b1,
               const float* __restrict__ v1W2, const float* __restrict__ v1b2,
               const float* __restrict__ v2W1, const float* __restrict__ v2b1,
               const float* __restrict__ v2W2, const float* __restrict__ v2b2) {
    extern __shared__ float smem[];
    u32* su = (u32*)smem;

    float* sb1   = smem + 0;
    float* sb2   = smem + 128;
    float* sv1b1 = smem + 256;
    float* sv2b1 = smem + 384;
    float* sv1w2 = smem + 512;
    float* sv2w2 = smem + 640;
    float* red1  = smem + 768;    // 8 warps x 64
    float* red2  = smem + 1280;
    u32* A1h   = su + 1792;
    u32* A1l   = su + 2304;
    u32* W1cH  = su + 2816;
    u32* W2h   = su + 3840;
    u32* V1h   = su + 12032;
    u32* V2h   = su + 20224;
    u32* actHA = su + 28416;
    u32* actLA = su + 32512;
    u32* actHB = su + 36608;
    u32* actLB = su + 40704;

    const int tid = threadIdx.x;
    const int w = tid >> 5, lane = tid & 31;

    cpf4(sb1, eb1, 128, tid, 256);
    cpf4(sb2, eb2, 128, tid, 256);
    cpf4(sv1b1, v1b1, 128, tid, 256);
    cpf4(sv2b1, v2b1, 128, tid, 256);
    cpf4(sv1w2, v1W2, 128, tid, 256);
    cpf4(sv2w2, v2W2, 128, tid, 256);
    pack_w1c(W1cH, eW1 + 256 * 128, tid, 256);
    pack_wfrag(W2h, eW2, tid, 256);
    pack_wfrag(V1h, v1W1, tid, 256);
    pack_wfrag(V2h, v2W1, tid, 256);
    __syncthreads();

    const float c1 = __ldg(v1b2);
    const float c2 = __ldg(v2b2);

    // ---- pipelined gather state (registers), 4 m-tiles ----
    float2 Pa0[4][2], Pb0[4][2], Pa1[4][2], Pb1[4][2];
    float2 Q0, Q1, Q2, Q3;

#define DO_PREFETCH(TB) do {                                                   \
    _Pragma("unroll")                                                          \
    for (int m = 0; m < 4; m++) {                                              \
        int e0 = (TB) + m * 16 + (lane >> 2);                                  \
        int e1 = e0 + 8;                                                       \
        int rA = g_rows[e0], cA = g_cols[e0];                                  \
        int rB = g_rows[e1], cB = g_cols[e1];                                  \
        _Pragma("unroll")                                                      \
        for (int i = 0; i < 2; i++) {                                          \
            int n0 = (w * 2 + i) * 8 + 2 * (lane & 3);                         \
            Pa0[m][i] = *(const float2*)(g_Ha + (size_t)rA * 128 + n0);        \
            Pb0[m][i] = *(const float2*)(g_Hb + (size_t)cA * 128 + n0);        \
            Pa1[m][i] = *(const float2*)(g_Ha + (size_t)rB * 128 + n0);        \
            Pb1[m][i] = *(const float2*)(g_Hb + (size_t)cB * 128 + n0);        \
        }                                                                      \
    }                                                                          \
    if (tid < 128) {                                                           \
        int m = tid >> 5, l = tid & 31;                                        \
        int r = l >> 2, k0 = (l & 3) * 2;                                      \
        const float* ep0 = edge_attr + (size_t)((TB) + m * 16 + r) * 16;       \
        const float* ep1 = edge_attr + (size_t)((TB) + m * 16 + r + 8) * 16;   \
        Q0 = *(const float2*)(ep0 + k0);                                       \
        Q1 = *(const float2*)(ep1 + k0);                                       \
        Q2 = *(const float2*)(ep0 + k0 + 8);                                   \
        Q3 = *(const float2*)(ep1 + k0 + 8);                                   \
    }                                                                          \
} while (0)

    if (blockIdx.x < NT_EDGE) DO_PREFETCH(blockIdx.x * 64);

    for (int t = blockIdx.x; t < NT_EDGE; t += 148) {
        const int tbase = t * 64;

        // ---- A1 store from prefetched edge_attr (tid<128) ----
        if (tid < 128) {
            int m = tid >> 5, l = tid & 31;
            int o = (m * 32 + l) * 4;
            u32 hh, ll;
            packsplit(Q0.x, Q0.y, hh, ll); A1h[o] = hh;     A1l[o] = ll;
            packsplit(Q1.x, Q1.y, hh, ll); A1h[o + 1] = hh; A1l[o + 1] = ll;
            packsplit(Q2.x, Q2.y, hh, ll); A1h[o + 2] = hh; A1l[o + 2] = ll;
            packsplit(Q3.x, Q3.y, hh, ll); A1h[o + 3] = hh; A1l[o + 3] = ll;
        }

        // ---- layer1 C init from prefetched Ha/Hb ----
        float C[4][2][4];
#pragma unroll
        for (int m = 0; m < 4; m++)
#pragma unroll
            for (int i = 0; i < 2; i++) {
                int n0 = (w * 2 + i) * 8 + 2 * (lane & 3);
                float2 bb = *(const float2*)(sb1 + n0);
                C[m][i][0] = Pa0[m][i].x + Pb0[m][i].x + bb.x;
                C[m][i][1] = Pa0[m][i].y + Pb0[m][i].y + bb.y;
                C[m][i][2] = Pa1[m][i].x + Pb1[m][i].x + bb.x;
                C[m][i][3] = Pa1[m][i].y + Pb1[m][i].y + bb.y;
            }

        // ---- issue next tile's gathers ----
        {
            int tn = t + 148;
            if (tn < NT_EDGE) DO_PREFETCH(tn * 64);
        }
        __syncthreads();   // barrier 1: A1 visible; prev-tile bufA reads done

        // ---- layer1 MMA: += ea @ W1c (k=16, 2-term) ----
        {
            uint4 hf[4], lf[4];
#pragma unroll
            for (int m = 0; m < 4; m++) {
                hf[m] = *(const uint4*)(A1h + (m * 32 + lane) * 4);
                lf[m] = *(const uint4*)(A1l + (m * 32 + lane) * 4);
            }
#pragma unroll
            for (int i = 0; i < 2; i++) {
                int fo = ((w * 2 + i) * 32 + lane) * 2;
                u32 bh0 = W1cH[fo], bh1 = W1cH[fo + 1];
#pragma unroll
                for (int m = 0; m < 4; m++) {
                    u32 AH[4] = {hf[m].x, hf[m].y, hf[m].z, hf[m].w};
                    u32 AL[4] = {lf[m].x, lf[m].y, lf[m].z, lf[m].w};
                    mma_f16(C[m][i], AH, bh0, bh1);
                    mma_f16(C[m][i], AL, bh0, bh1);
                }
            }
        }
        // y1 -> bufA
#pragma unroll
        for (int m = 0; m < 4; m++)
#pragma unroll
            for (int i = 0; i < 2; i++) {
                int g = w * 2 + i;
                int base = ((m * 8 + (g >> 1)) * 32 + lane) * 4 + (g & 1) * 2;
                u32 hh, ll;
                packsplit(siluf(C[m][i][0]), siluf(C[m][i][1]), hh, ll);
                actHA[base] = hh; actLA[base] = ll;
                packsplit(siluf(C[m][i][2]), siluf(C[m][i][3]), hh, ll);
                actHA[base + 1] = hh; actLA[base + 1] = ll;
            }
        __syncthreads();   // barrier 2: y1 (bufA) ready

        // ---- layer2: ef = silu(y1 @ eW2 + b2) -> bufB ----
#pragma unroll
        for (int m = 0; m < 4; m++)
#pragma unroll
            for (int i = 0; i < 2; i++)
#pragma unroll
                for (int j = 0; j < 4; j++) C[m][i][j] = 0.f;
#pragma unroll
        for (int kt = 0; kt < 8; kt++) {
            uint4 hf[4], lf[4];
#pragma unroll
            for (int m = 0; m < 4; m++) {
                hf[m] = *(const uint4*)(actHA + ((m * 8 + kt) * 32 + lane) * 4);
                lf[m] = *(const uint4*)(actLA + ((m * 8 + kt) * 32 + lane) * 4);
            }
#pragma unroll
            for (int i = 0; i < 2; i++) {
                int fo = ((kt * 16 + (w * 2 + i)) * 32 + lane) * 2;
                u32 bh0 = W2h[fo], bh1 = W2h[fo + 1];
#pragma unroll
                for (int m = 0; m < 4; m++) {
                    u32 AH[4] = {hf[m].x, hf[m].y, hf[m].z, hf[m].w};
                    u32 AL[4] = {lf[m].x, lf[m].y, lf[m].z, lf[m].w};
                    mma_f16(C[m][i], AH, bh0, bh1);
                    mma_f16(C[m][i], AL, bh0, bh1);
                }
            }
        }
#pragma unroll
        for (int m = 0; m < 4; m++)
#pragma unroll
            for (int i = 0; i < 2; i++) {
                int g = w * 2 + i;
                int n0 = g * 8 + 2 * (lane & 3);
                float2 bb = *(const float2*)(sb2 + n0);
                int base = ((m * 8 + (g >> 1)) * 32 + lane) * 4 + (g & 1) * 2;
                u32 hh, ll;
                packsplit(siluf(C[m][i][0] + bb.x), siluf(C[m][i][1] + bb.y), hh, ll);
                actHB[base] = hh; actLB[base] = ll;
                packsplit(siluf(C[m][i][2] + bb.x), siluf(C[m][i][3] + bb.y), hh, ll);
                actHB[base + 1] = hh; actLB[base + 1] = ll;
            }
        __syncthreads();   // barrier 3: ef (bufB) ready

        // ---- heads fused (2-term each), read bufB ----
        {
            float C1[4][2][4], C2[4][2][4];
#pragma unroll
            for (int m = 0; m < 4; m++)
#pragma unroll
                for (int i = 0; i < 2; i++)
#pragma unroll
                    for (int j = 0; j < 4; j++) { C1[m][i][j] = 0.f; C2[m][i][j] = 0.f; }
#pragma unroll
            for (int kt = 0; kt < 8; kt++) {
                uint4 hf[4], lf[4];
#pragma unroll
                for (int m = 0; m < 4; m++) {
                    hf[m] = *(const uint4*)(actHB + ((m * 8 + kt) * 32 + lane) * 4);
                    lf[m] = *(const uint4*)(actLB + ((m * 8 + kt) * 32 + lane) * 4);
                }
#pragma unroll
                for (int i = 0; i < 2; i++) {
                    int fo = ((kt * 16 + (w * 2 + i)) * 32 + lane) * 2;
                    u32 p0 = V1h[fo], p1 = V1h[fo + 1];
                    u32 r0 = V2h[fo], r1 = V2h[fo + 1];
#pragma unroll
                    for (int m = 0; m < 4; m++) {
                        u32 AH[4] = {hf[m].x, hf[m].y, hf[m].z, hf[m].w};
                        u32 AL[4] = {lf[m].x, lf[m].y, lf[m].z, lf[m].w};
                        mma_f16(C1[m][i], AH, p0, p1);
                        mma_f16(C1[m][i], AL, p0, p1);
                        mma_f16(C2[m][i], AH, r0, r1);
                        mma_f16(C2[m][i], AL, r0, r1);
                    }
                }
            }
            float p1a[8], p2a[8];
#pragma unroll
            for (int j = 0; j < 8; j++) { p1a[j] = 0.f; p2a[j] = 0.f; }
#pragma unroll
            for (int m = 0; m < 4; m++)
#pragma unroll
                for (int i = 0; i < 2; i++) {
                    int n0 = (w * 2 + i) * 8 + 2 * (lane & 3);
                    float2 bb1 = *(const float2*)(sv1b1 + n0);
                    float2 ww1 = *(const float2*)(sv1w2 + n0);
                    float2 bb2 = *(const float2*)(sv2b1 + n0);
                    float2 ww2 = *(const float2*)(sv2w2 + n0);
                    p1a[m * 2 + 0] += siluf(C1[m][i][0] + bb1.x) * ww1.x
                                    + siluf(C1[m][i][1] + bb1.y) * ww1.y;
                    p1a[m * 2 + 1] += siluf(C1[m][i][2] + bb1.x) * ww1.x
                                    + siluf(C1[m][i][3] + bb1.y) * ww1.y;
                    p2a[m * 2 + 0] += siluf(C2[m][i][0] + bb2.x) * ww2.x
                                    + siluf(C2[m][i][1] + bb2.y) * ww2.y;
                    p2a[m * 2 + 1] += siluf(C2[m][i][2] + bb2.x) * ww2.x
                                    + siluf(C2[m][i][3] + bb2.y) * ww2.y;
                }
#pragma unroll
            for (int j = 0; j < 8; j++) {
                p1a[j] += __shfl_xor_sync(0xffffffffu, p1a[j], 1);
                p1a[j] += __shfl_xor_sync(0xffffffffu, p1a[j], 2);
                p2a[j] += __shfl_xor_sync(0xffffffffu, p2a[j], 1);
                p2a[j] += __shfl_xor_sync(0xffffffffu, p2a[j], 2);
            }
            if ((lane & 3) == 0) {
                int r = lane >> 2;
#pragma unroll
                for (int m = 0; m < 4; m++) {
                    red1[w * 64 + m * 16 + r]     = p1a[2 * m];
                    red1[w * 64 + m * 16 + r + 8] = p1a[2 * m + 1];
                    red2[w * 64 + m * 16 + r]     = p2a[2 * m];
                    red2[w * 64 + m * 16 + r + 8] = p2a[2 * m + 1];
                }
            }
        }
        __syncthreads();   // barrier 4: reductions visible

        // ---- scatter: 192 threads -> (edge e = tid/3, comp d = tid%3) ----
        if (tid < 192) {
            int e = tid / 3, d = tid - 3 * e;
            float s1 = c1, s2 = c2;
#pragma unroll
            for (int k = 0; k < 8; k++) {
                s1 += red1[k * 64 + e];
                s2 += red2[k * 64 + e];
            }
            int eg = tbase + e;
            int row = g_rows[eg], col = g_cols[eg];
            float rp = x[col * 3 + d] - x[row * 3 + d];
            atomicAdd(&g_vec1[row * 3 + d], rp * s1);
            atomicAdd(&g_vec2[row * 3 + d], rp * s2);
        }
    }
#undef DO_PREFETCH
}

// ---------------- finalize: Gram-Schmidt per node ----------------
__global__ void ol_finalize_kernel(float* __restrict__ out) {
    int n = blockIdx.x * blockDim.x + threadIdx.x;
    if (n >= NNODES) return;
    float v1x = g_vec1[n * 3 + 0], v1y = g_vec1[n * 3 + 1], v1z = g_vec1[n * 3 + 2];
    float v2x = g_vec2[n * 3 + 0], v2y = g_vec2[n * 3 + 1], v2z = g_vec2[n * 3 + 2];

    float n1 = fmaxf(sqrtf(v1x * v1x + v1y * v1y + v1z * v1z), 1e-12f);
    float e1x = v1x / n1, e1y = v1y / n1, e1z = v1z / n1;

    float dp = e1x * v2x + e1y * v2y + e1z * v2z;
    float px = v2x - dp * e1x, py = v2y - dp * e1y, pz = v2z - dp * e1z;
    float n2 = fmaxf(sqrtf(px * px + py * py + pz * pz), 1e-12f);
    float e2x = px / n2, e2y = py / n2, e2z = pz / n2;

    float e3x = e1y * e2z - e1z * e2y;
    float e3y = e1z * e2x - e1x * e2z;
    float e3z = e1x * e2y - e1y * e2x;

    float* o = out + n * 9;
    o[0] = e1x; o[1] = e2x; o[2] = e3x;
    o[3] = e1y; o[4] = e2y; o[5] = e3y;
    o[6] = e1z; o[7] = e2z; o[8] = e3z;
}

// ---------------- launch ----------------
extern "C" void kernel_launch(void* const* d_in, const int* in_sizes, int n_in,
                              void* d_out, int out_size) {
    const float* h         = (const float*)d_in[0];
    const float* x         = (const float*)d_in[1];
    const void*  ei        = d_in[2];
    const float* edge_attr = (const float*)d_in[3];
    const float* eW1 = (const float*)d_in[4];  const float* eb1 = (const float*)d_in[5];
    const float* eW2 = (const float*)d_in[6];  const float* eb2 = (const float*)d_in[7];
    const float* v1W1 = (const float*)d_in[8]; const float* v1b1 = (const float*)d_in[9];
    const float* v1W2 = (const float*)d_in[10]; const float* v1b2 = (const float*)d_in[11];
    const float* v2W1 = (const float*)d_in[12]; const float* v2b1 = (const float*)d_in[13];
    const float* v2W2 = (const float*)d_in[14]; const float* v2b2 = (const float*)d_in[15];
    float* out = (float*)d_out;

    cudaFuncSetAttribute(ol_precompute_kernel,
                         cudaFuncAttributeMaxDynamicSharedMemorySize, PRE_SMEM);
    cudaFuncSetAttribute(ol_edge_kernel,
                         cudaFuncAttributeMaxDynamicSharedMemorySize, EDGE_SMEM);

    ol_detect_kernel<<<1, 32>>>((const int*)ei);
    ol_convert_kernel<<<(NEDGES + 255) / 256, 256>>>(ei);
    ol_zero_kernel<<<(NNODES * 3 + 255) / 256, 256>>>();
    ol_precompute_kernel<<<(NNODES + 63) / 64, 256, PRE_SMEM>>>(h, eW1);
    ol_edge_kernel<<<148, 256, EDGE_SMEM>>>(x, edge_attr,
                                            eW1, eb1, eW2, eb2,
                                            v1W1, v1b1, v1W2, v1b2,
                                            v2W1, v2b1, v2W2, v2b2);
    ol_finalize_kernel<<<(NNODES + 255) / 256, 256>>>(out);
}

// round 17
// speedup vs baseline: 5.7382x; 1.2245x over previous
#include <cuda_runtime.h>
#include <cuda_fp16.h>
#include <math.h>

#define NNODES 50000
#define NEDGES 800000
#define HID    128
#define FE     16

typedef unsigned long long u64;
typedef unsigned int u32;

// ---------------- scratch ----------------
__device__ float g_Ha[NNODES * HID];
__device__ float g_Hb[NNODES * HID];
__device__ float g_vec1[NNODES * 3];
__device__ float g_vec2[NNODES * 3];
__device__ int   g_rows[NEDGES];
__device__ int   g_cols[NEDGES];
__device__ int   g_is64;

// ---------------- helpers ----------------
__device__ __forceinline__ u64 dup2(float s) {
    u64 r; asm("mov.b64 %0, {%1, %1};" : "=l"(r) : "f"(s)); return r;
}
__device__ __forceinline__ void fma2(u64& c, u64 a, u64 b) {
    asm("fma.rn.f32x2 %0, %1, %2, %3;" : "=l"(c) : "l"(a), "l"(b), "l"(c));
}
// silu via single-MUFU tanh: silu(x) = 0.5x(1 + tanh(x/2))
__device__ __forceinline__ float siluf(float v) {
    float hx = 0.5f * v, th;
    asm("tanh.approx.f32 %0, %1;" : "=f"(th) : "f"(hx));
    return fmaf(hx, th, hx);
}
__device__ __forceinline__ void cpf4(float* dst, const float* src, int nfloats,
                                     int tid, int nthreads) {
    const float4* s = reinterpret_cast<const float4*>(src);
    float4* d = reinterpret_cast<float4*>(dst);
    for (int i = tid; i < nfloats / 4; i += nthreads) d[i] = s[i];
}

// fp16x2 pack: even in low half
__device__ __forceinline__ u32 packh(float ev, float od) {
    u32 r; asm("cvt.rn.f16x2.f32 %0, %1, %2;" : "=r"(r) : "f"(od), "f"(ev)); return r;
}
__device__ __forceinline__ float hres(float v) {
    return v - __half2float(__float2half_rn(v));
}
__device__ __forceinline__ void packsplit(float ev, float od, u32& hi, u32& lo) {
    hi = packh(ev, od);
    lo = packh(hres(ev), hres(od));
}

// fp16 warp MMA: D(16x8,f32) += A(16x16) * B(16x8)
__device__ __forceinline__ void mma_f16(float* c, const u32* a, u32 b0, u32 b1) {
    asm volatile(
        "mma.sync.aligned.m16n8k16.row.col.f32.f16.f16.f32 "
        "{%0,%1,%2,%3}, {%4,%5,%6,%7}, {%8,%9}, {%0,%1,%2,%3};"
        : "+f"(c[0]), "+f"(c[1]), "+f"(c[2]), "+f"(c[3])
        : "r"(a[0]), "r"(a[1]), "r"(a[2]), "r"(a[3]), "r"(b0), "r"(b1));
}

// ---------------- dtype detection + index canonicalization ------------------
__global__ void ol_detect_kernel(const int* __restrict__ ei32) {
    if (threadIdx.x == 0 && blockIdx.x == 0) {
        int any = 0;
#pragma unroll
        for (int i = 0; i < 64; i++) any |= ei32[2 * i + 1];
        g_is64 = (any == 0) ? 1 : 0;
    }
}
__global__ void ol_convert_kernel(const void* __restrict__ eiv) {
    int i = blockIdx.x * blockDim.x + threadIdx.x;
    if (i >= NEDGES) return;
    if (g_is64) {
        const long long* e = (const long long*)eiv;
        g_rows[i] = (int)e[i];
        g_cols[i] = (int)e[NEDGES + i];
    } else {
        const int* e = (const int*)eiv;
        g_rows[i] = e[i];
        g_cols[i] = e[NEDGES + i];
    }
}
__global__ void ol_zero_kernel() {
    int i = blockIdx.x * blockDim.x + threadIdx.x;
    if (i < NNODES * 3) { g_vec1[i] = 0.0f; g_vec2[i] = 0.0f; }
}

// ---------------- node precompute (R4 version, known-good ~96us, no spill) --
#define PRE_SMEM ((256 * 128 + 8 * 8 * 128) * 4)
__global__ void __launch_bounds__(256, 1)
ol_precompute_kernel(const float* __restrict__ h, const float* __restrict__ eW1) {
    extern __shared__ float smem[];
    float* Wab = smem;
    float* act = smem + 256 * 128;

    cpf4(Wab, eW1, 256 * 128, threadIdx.x, 256);
    __syncthreads();

    const int warp = threadIdx.x >> 5, lane = threadIdx.x & 31;
    float* myAct = act + warp * (8 * 128);
    float4* myAct4 = reinterpret_cast<float4*>(myAct);
    const int n0 = (blockIdx.x * 8 + warp) * 8;

#pragma unroll
    for (int e = 0; e < 8; e++) {
        int n = n0 + e;
        float4 v = make_float4(0.f, 0.f, 0.f, 0.f);
        if (n < NNODES) v = reinterpret_cast<const float4*>(h)[n * 32 + lane];
        myAct4[e * 32 + lane] = v;
    }
    __syncwarp();

    u64 accA0[8], accA1[8], accB0[8], accB1[8];
#pragma unroll
    for (int e = 0; e < 8; e++) {
        accA0[e] = 0ull; accA1[e] = 0ull; accB0[e] = 0ull; accB1[e] = 0ull;
    }
    const ulonglong2* Wab2 = reinterpret_cast<const ulonglong2*>(Wab);
    for (int kb = 0; kb < 32; kb++) {
        ulonglong2 wa0 = Wab2[(4 * kb + 0) * 32 + lane];
        ulonglong2 wa1 = Wab2[(4 * kb + 1) * 32 + lane];
        ulonglong2 wa2 = Wab2[(4 * kb + 2) * 32 + lane];
        ulonglong2 wa3 = Wab2[(4 * kb + 3) * 32 + lane];
        ulonglong2 wb0 = Wab2[(128 + 4 * kb + 0) * 32 + lane];
        ulonglong2 wb1 = Wab2[(128 + 4 * kb + 1) * 32 + lane];
        ulonglong2 wb2 = Wab2[(128 + 4 * kb + 2) * 32 + lane];
        ulonglong2 wb3 = Wab2[(128 + 4 * kb + 3) * 32 + lane];
#pragma unroll
        for (int e = 0; e < 8; e++) {
            float4 a = myAct4[e * 32 + kb];
            u64 dx = dup2(a.x), dy = dup2(a.y), dz = dup2(a.z), dw = dup2(a.w);
            fma2(accA0[e], dx, wa0.x); fma2(accA1[e], dx, wa0.y);
            fma2(accA0[e], dy, wa1.x); fma2(accA1[e], dy, wa1.y);
            fma2(accA0[e], dz, wa2.x); fma2(accA1[e], dz, wa2.y);
            fma2(accA0[e], dw, wa3.x); fma2(accA1[e], dw, wa3.y);
            fma2(accB0[e], dx, wb0.x); fma2(accB1[e], dx, wb0.y);
            fma2(accB0[e], dy, wb1.x); fma2(accB1[e], dy, wb1.y);
            fma2(accB0[e], dz, wb2.x); fma2(accB1[e], dz, wb2.y);
            fma2(accB0[e], dw, wb3.x); fma2(accB1[e], dw, wb3.y);
        }
    }
#pragma unroll
    for (int e = 0; e < 8; e++) {
        int n = n0 + e;
        if (n < NNODES) {
            reinterpret_cast<ulonglong2*>(g_Ha)[n * 32 + lane] =
                make_ulonglong2(accA0[e], accA1[e]);
            reinterpret_cast<ulonglong2*>(g_Hb)[n * 32 + lane] =
                make_ulonglong2(accB0[e], accB1[e]);
        }
    }
}

// ---------------- fragment prepack (fp16 hi only) ----------------
__device__ void pack_wfrag(u32* Bh, const float* __restrict__ W,
                           int tid, int nthreads) {
    for (int idx = tid; idx < 4096; idx += nthreads) {
        int kt = idx >> 9, nt = (idx >> 5) & 15, l = idx & 31;
        int n = nt * 8 + (l >> 2), k0 = kt * 16 + (l & 3) * 2;
        Bh[idx * 2]     = packh(W[k0 * 128 + n],       W[(k0 + 1) * 128 + n]);
        Bh[idx * 2 + 1] = packh(W[(k0 + 8) * 128 + n], W[(k0 + 9) * 128 + n]);
    }
}
__device__ void pack_w1c(u32* Bh, const float* __restrict__ W,
                         int tid, int nthreads) {
    for (int idx = tid; idx < 512; idx += nthreads) {
        int nt = idx >> 5, l = idx & 31;
        int n = nt * 8 + (l >> 2), k0 = (l & 3) * 2;
        Bh[idx * 2]     = packh(W[k0 * 128 + n],       W[(k0 + 1) * 128 + n]);
        Bh[idx * 2 + 1] = packh(W[(k0 + 8) * 128 + n], W[(k0 + 9) * 128 + n]);
    }
}

// ---------------- edge kernel: warp-independent, register-resident acts -----
// Each warp owns 16 edges end-to-end; no act smem, no mainloop barriers.
// smem u32: sb1 0 |sb2 128 |sv1b1 256 |sv2b1 384 |sv1w2 512 |sv2w2 640 |
//           W1cH 768(1024) |W2h 1792(8192) |V1h 9984(8192) |V2h 18176(8192)
//           end 26368
#define EDGE_SMEM (26368 * 4)
#define NWTILES (NEDGES / 16)

__global__ void __launch_bounds__(256, 1)
ol_edge_kernel(const float* __restrict__ x,
               const float* __restrict__ edge_attr,
               const float* __restrict__ eW1, const float* __restrict__ eb1,
               const float* __restrict__ eW2, const float* __restrict__ eb2,
               const float* __restrict__ v1W1, const float* __restrict__ v1b1,
               const float* __restrict__ v1W2, const float* __restrict__ v1b2,
               const float* __restrict__ v2W1, const float* __restrict__ v2b1,
               const float* __restrict__ v2W2, const float* __restrict__ v2b2) {
    extern __shared__ float smem[];
    u32* su = (u32*)smem;

    float* sb1   = smem + 0;
    float* sb2   = smem + 128;
    float* sv1b1 = smem + 256;
    float* sv2b1 = smem + 384;
    float* sv1w2 = smem + 512;
    float* sv2w2 = smem + 640;
    u32* W1cH = su + 768;
    u32* W2h  = su + 1792;
    u32* V1h  = su + 9984;
    u32* V2h  = su + 18176;

    const int tid = threadIdx.x;
    const int w = tid >> 5, lane = tid & 31;

    cpf4(sb1, eb1, 128, tid, 256);
    cpf4(sb2, eb2, 128, tid, 256);
    cpf4(sv1b1, v1b1, 128, tid, 256);
    cpf4(sv2b1, v2b1, 128, tid, 256);
    cpf4(sv1w2, v1W2, 128, tid, 256);
    cpf4(sv2w2, v2W2, 128, tid, 256);
    pack_w1c(W1cH, eW1 + 256 * 128, tid, 256);
    pack_wfrag(W2h, eW2, tid, 256);
    pack_wfrag(V1h, v1W1, tid, 256);
    pack_wfrag(V2h, v2W1, tid, 256);
    __syncthreads();

    const float c1 = __ldg(v1b2);
    const float c2 = __ldg(v2b2);

    const int k0 = (lane & 3) * 2;
    const int gw = blockIdx.x * 8 + w;      // global warp id (0..1183)

    for (int t = gw; t < NWTILES; t += 1184) {
        const int tbase = t * 16;
        const int e0 = tbase + (lane >> 2), e1 = e0 + 8;
        const int rA = g_rows[e0], cA = g_cols[e0];
        const int rB = g_rows[e1], cB = g_cols[e1];

        // ---- A1 fragments from edge_attr (in registers) ----
        u32 AH1[4], AL1[4];
        {
            const float* epA = edge_attr + (size_t)e0 * 16;
            const float* epB = edge_attr + (size_t)e1 * 16;
            float2 q0 = *(const float2*)(epA + k0);
            float2 q1 = *(const float2*)(epB + k0);
            float2 q2 = *(const float2*)(epA + k0 + 8);
            float2 q3 = *(const float2*)(epB + k0 + 8);
            packsplit(q0.x, q0.y, AH1[0], AL1[0]);
            packsplit(q1.x, q1.y, AH1[1], AL1[1]);
            packsplit(q2.x, q2.y, AH1[2], AL1[2]);
            packsplit(q3.x, q3.y, AH1[3], AL1[3]);
        }

        // ---- layer1: C init (gather) + W1c MMA ----
        float C[16][4];
#pragma unroll
        for (int nt = 0; nt < 16; nt++) {
            int n0 = nt * 8 + k0;
            float2 a0 = *(const float2*)(g_Ha + (size_t)rA * 128 + n0);
            float2 b0 = *(const float2*)(g_Hb + (size_t)cA * 128 + n0);
            float2 a1 = *(const float2*)(g_Ha + (size_t)rB * 128 + n0);
            float2 b1v = *(const float2*)(g_Hb + (size_t)cB * 128 + n0);
            float2 bb = *(const float2*)(sb1 + n0);
            C[nt][0] = a0.x + b0.x + bb.x;
            C[nt][1] = a0.y + b0.y + bb.y;
            C[nt][2] = a1.x + b1v.x + bb.x;
            C[nt][3] = a1.y + b1v.y + bb.y;
        }
#pragma unroll
        for (int nt = 0; nt < 16; nt++) {
            int fo = (nt * 32 + lane) * 2;
            u32 b0 = W1cH[fo], b1 = W1cH[fo + 1];
            mma_f16(C[nt], AH1, b0, b1);
            mma_f16(C[nt], AL1, b0, b1);
        }

        // ---- silu + in-register repack C -> A fragments ----
        u32 AH[8][4], AL[8][4];
#pragma unroll
        for (int kt = 0; kt < 8; kt++) {
            packsplit(siluf(C[2 * kt][0]),     siluf(C[2 * kt][1]),     AH[kt][0], AL[kt][0]);
            packsplit(siluf(C[2 * kt][2]),     siluf(C[2 * kt][3]),     AH[kt][1], AL[kt][1]);
            packsplit(siluf(C[2 * kt + 1][0]), siluf(C[2 * kt + 1][1]), AH[kt][2], AL[kt][2]);
            packsplit(siluf(C[2 * kt + 1][2]), siluf(C[2 * kt + 1][3]), AH[kt][3], AL[kt][3]);
        }

        // ---- layer2: ef = silu(y1 @ eW2 + b2) ----
#pragma unroll
        for (int nt = 0; nt < 16; nt++) {
            C[nt][0] = 0.f; C[nt][1] = 0.f; C[nt][2] = 0.f; C[nt][3] = 0.f;
        }
#pragma unroll
        for (int kt = 0; kt < 8; kt++)
#pragma unroll
            for (int nt = 0; nt < 16; nt++) {
                int fo = ((kt * 16 + nt) * 32 + lane) * 2;
                u32 b0 = W2h[fo], b1 = W2h[fo + 1];
                mma_f16(C[nt], AH[kt], b0, b1);
                mma_f16(C[nt], AL[kt], b0, b1);
            }
#pragma unroll
        for (int kt = 0; kt < 8; kt++) {
            int g0 = 2 * kt, g1 = 2 * kt + 1;
            float2 bb0 = *(const float2*)(sb2 + g0 * 8 + k0);
            float2 bb1 = *(const float2*)(sb2 + g1 * 8 + k0);
            packsplit(siluf(C[g0][0] + bb0.x), siluf(C[g0][1] + bb0.y), AH[kt][0], AL[kt][0]);
            packsplit(siluf(C[g0][2] + bb0.x), siluf(C[g0][3] + bb0.y), AH[kt][1], AL[kt][1]);
            packsplit(siluf(C[g1][0] + bb1.x), siluf(C[g1][1] + bb1.y), AH[kt][2], AL[kt][2]);
            packsplit(siluf(C[g1][2] + bb1.x), siluf(C[g1][3] + bb1.y), AH[kt][3], AL[kt][3]);
        }

        // ---- head 1 ----
        float s1e0, s1e1;
        {
#pragma unroll
            for (int nt = 0; nt < 16; nt++) {
                C[nt][0] = 0.f; C[nt][1] = 0.f; C[nt][2] = 0.f; C[nt][3] = 0.f;
            }
#pragma unroll
            for (int kt = 0; kt < 8; kt++)
#pragma unroll
                for (int nt = 0; nt < 16; nt++) {
                    int fo = ((kt * 16 + nt) * 32 + lane) * 2;
                    u32 b0 = V1h[fo], b1 = V1h[fo + 1];
                    mma_f16(C[nt], AH[kt], b0, b1);
                    mma_f16(C[nt], AL[kt], b0, b1);
                }
            float p0 = 0.f, p1 = 0.f;
#pragma unroll
            for (int nt = 0; nt < 16; nt++) {
                int n0 = nt * 8 + k0;
                float2 bb = *(const float2*)(sv1b1 + n0);
                float2 ww = *(const float2*)(sv1w2 + n0);
                p0 += siluf(C[nt][0] + bb.x) * ww.x + siluf(C[nt][1] + bb.y) * ww.y;
                p1 += siluf(C[nt][2] + bb.x) * ww.x + siluf(C[nt][3] + bb.y) * ww.y;
            }
            p0 += __shfl_xor_sync(0xffffffffu, p0, 1);
            p0 += __shfl_xor_sync(0xffffffffu, p0, 2);
            p1 += __shfl_xor_sync(0xffffffffu, p1, 1);
            p1 += __shfl_xor_sync(0xffffffffu, p1, 2);
            s1e0 = p0 + c1; s1e1 = p1 + c1;
        }
        // ---- head 2 ----
        float s2e0, s2e1;
        {
#pragma unroll
            for (int nt = 0; nt < 16; nt++) {
                C[nt][0] = 0.f; C[nt][1] = 0.f; C[nt][2] = 0.f; C[nt][3] = 0.f;
            }
#pragma unroll
            for (int kt = 0; kt < 8; kt++)
#pragma unroll
                for (int nt = 0; nt < 16; nt++) {
                    int fo = ((kt * 16 + nt) * 32 + lane) * 2;
                    u32 b0 = V2h[fo], b1 = V2h[fo + 1];
                    mma_f16(C[nt], AH[kt], b0, b1);
                    mma_f16(C[nt], AL[kt], b0, b1);
                }
            float p0 = 0.f, p1 = 0.f;
#pragma unroll
            for (int nt = 0; nt < 16; nt++) {
                int n0 = nt * 8 + k0;
                float2 bb = *(const float2*)(sv2b1 + n0);
                float2 ww = *(const float2*)(sv2w2 + n0);
                p0 += siluf(C[nt][0] + bb.x) * ww.x + siluf(C[nt][1] + bb.y) * ww.y;
                p1 += siluf(C[nt][2] + bb.x) * ww.x + siluf(C[nt][3] + bb.y) * ww.y;
            }
            p0 += __shfl_xor_sync(0xffffffffu, p0, 1);
            p0 += __shfl_xor_sync(0xffffffffu, p0, 2);
            p1 += __shfl_xor_sync(0xffffffffu, p1, 1);
            p1 += __shfl_xor_sync(0xffffffffu, p1, 2);
            s2e0 = p0 + c2; s2e1 = p1 + c2;
        }

        // ---- scatter: quad leaders own edges e0, e1 ----
        if ((lane & 3) == 0) {
#pragma unroll
            for (int d = 0; d < 3; d++) {
                float rp = x[cA * 3 + d] - x[rA * 3 + d];
                atomicAdd(&g_vec1[rA * 3 + d], rp * s1e0);
                atomicAdd(&g_vec2[rA * 3 + d], rp * s2e0);
            }
#pragma unroll
            for (int d = 0; d < 3; d++) {
                float rp = x[cB * 3 + d] - x[rB * 3 + d];
                atomicAdd(&g_vec1[rB * 3 + d], rp * s1e1);
                atomicAdd(&g_vec2[rB * 3 + d], rp * s2e1);
            }
        }
    }
}

// ---------------- finalize: Gram-Schmidt per node ----------------
__global__ void ol_finalize_kernel(float* __restrict__ out) {
    int n = blockIdx.x * blockDim.x + threadIdx.x;
    if (n >= NNODES) return;
    float v1x = g_vec1[n * 3 + 0], v1y = g_vec1[n * 3 + 1], v1z = g_vec1[n * 3 + 2];
    float v2x = g_vec2[n * 3 + 0], v2y = g_vec2[n * 3 + 1], v2z = g_vec2[n * 3 + 2];

    float n1 = fmaxf(sqrtf(v1x * v1x + v1y * v1y + v1z * v1z), 1e-12f);
    float e1x = v1x / n1, e1y = v1y / n1, e1z = v1z / n1;

    float dp = e1x * v2x + e1y * v2y + e1z * v2z;
    float px = v2x - dp * e1x, py = v2y - dp * e1y, pz = v2z - dp * e1z;
    float n2 = fmaxf(sqrtf(px * px + py * py + pz * pz), 1e-12f);
    float e2x = px / n2, e2y = py / n2, e2z = pz / n2;

    float e3x = e1y * e2z - e1z * e2y;
    float e3y = e1z * e2x - e1x * e2z;
    float e3z = e1x * e2y - e1y * e2x;

    float* o = out + n * 9;
    o[0] = e1x; o[1] = e2x; o[2] = e3x;
    o[3] = e1y; o[4] = e2y; o[5] = e3y;
    o[6] = e1z; o[7] = e2z; o[8] = e3z;
}

// ---------------- launch ----------------
extern "C" void kernel_launch(void* const* d_in, const int* in_sizes, int n_in,
                              void* d_out, int out_size) {
    const float* h         = (const float*)d_in[0];
    const float* x         = (const float*)d_in[1];
    const void*  ei        = d_in[2];
    const float* edge_attr = (const float*)d_in[3];
    const float* eW1 = (const float*)d_in[4];  const float* eb1 = (const float*)d_in[5];
    const float* eW2 = (const float*)d_in[6];  const float* eb2 = (const float*)d_in[7];
    const float* v1W1 = (const float*)d_in[8]; const float* v1b1 = (const float*)d_in[9];
    const float* v1W2 = (const float*)d_in[10]; const float* v1b2 = (const float*)d_in[11];
    const float* v2W1 = (const float*)d_in[12]; const float* v2b1 = (const float*)d_in[13];
    const float* v2W2 = (const float*)d_in[14]; const float* v2b2 = (const float*)d_in[15];
    float* out = (float*)d_out;

    cudaFuncSetAttribute(ol_precompute_kernel,
                         cudaFuncAttributeMaxDynamicSharedMemorySize, PRE_SMEM);
    cudaFuncSetAttribute(ol_edge_kernel,
                         cudaFuncAttributeMaxDynamicSharedMemorySize, EDGE_SMEM);

    ol_detect_kernel<<<1, 32>>>((const int*)ei);
    ol_convert_kernel<<<(NEDGES + 255) / 256, 256>>>(ei);
    ol_zero_kernel<<<(NNODES * 3 + 255) / 256, 256>>>();
    ol_precompute_kernel<<<(NNODES + 63) / 64, 256, PRE_SMEM>>>(h, eW1);
    ol_edge_kernel<<<148, 256, EDGE_SMEM>>>(x, edge_attr,
                                            eW1, eb1, eW2, eb2,
                                            v1W1, v1b1, v1W2, v1b2,
                                            v2W1, v2b1, v2W2, v2b2);
    ol_finalize_kernel<<<(NNODES + 255) / 256, 256>>>(out);
}